// round 3
// baseline (speedup 1.0000x reference)
#include <cuda_runtime.h>
#include <cstdint>

// Problem constants
#define BB   4
#define SS   2048
#define DD   1024
#define HH   16
#define DHH  64
#define MTOK (BB * SS)          // 8192 token rows
#define NQKV (3 * HH * DHH)     // 3072

// ---------------------------------------------------------------------------
// Scratch (static __device__ arrays per harness rules: no allocation allowed)
// ---------------------------------------------------------------------------
__device__ float g_qkv[(size_t)MTOK * NQKV];   // 96 MB
__device__ float g_attn[(size_t)MTOK * DD];    // 32 MB
__device__ float g_y[(size_t)MTOK * DD];       // 32 MB

// ---------------------------------------------------------------------------
// SGEMM: C[M,N] = A[M,K] * W[N,K]^T (+ bias[n]) (+ res[m,n])
// Both A and W are row-major with K contiguous (NT GEMM).
// 128x128 block tile, BK=16, 256 threads, 8x8 per-thread micro-tile,
// register prefetch of next K-slab.
// ---------------------------------------------------------------------------
template <bool ADD_BIAS, bool ADD_RES>
__global__ __launch_bounds__(256, 2)
void sgemm_nt(const float* __restrict__ A, const float* __restrict__ W,
              const float* __restrict__ bias, const float* __restrict__ res,
              float* __restrict__ C, int M, int N, int K)
{
    __shared__ __align__(16) float As[16 * 128];
    __shared__ __align__(16) float Bs[16 * 128];

    const int tid = threadIdx.x;
    const int tx = tid & 15;        // 0..15 -> N micro-tile
    const int ty = tid >> 4;        // 0..15 -> M micro-tile
    const int m0 = blockIdx.y << 7;
    const int n0 = blockIdx.x << 7;

    // Each thread loads 2 float4 per operand per tile:
    // rows row0 and row0+64, k-segment seg0 (4 floats).
    const int row0 = tid >> 2;      // 0..63
    const int seg0 = tid & 3;       // 0..3

    const float* aptr = A + (size_t)(m0 + row0) * K + seg0 * 4;
    const float* bptr = W + (size_t)(n0 + row0) * K + seg0 * 4;
    const size_t rowskip = (size_t)64 * K;

    float4 ra0 = *(const float4*)(aptr);
    float4 ra1 = *(const float4*)(aptr + rowskip);
    float4 rb0 = *(const float4*)(bptr);
    float4 rb1 = *(const float4*)(bptr + rowskip);

    float acc[8][8];
#pragma unroll
    for (int i = 0; i < 8; i++)
#pragma unroll
        for (int j = 0; j < 8; j++) acc[i][j] = 0.0f;

    const int nk = K >> 4;
    const int c4 = seg0 * 4;
    for (int kt = 0; kt < nk; kt++) {
        // Stage current regs into smem (transposed: As[k][m])
        As[(c4 + 0) * 128 + row0]      = ra0.x;
        As[(c4 + 1) * 128 + row0]      = ra0.y;
        As[(c4 + 2) * 128 + row0]      = ra0.z;
        As[(c4 + 3) * 128 + row0]      = ra0.w;
        As[(c4 + 0) * 128 + row0 + 64] = ra1.x;
        As[(c4 + 1) * 128 + row0 + 64] = ra1.y;
        As[(c4 + 2) * 128 + row0 + 64] = ra1.z;
        As[(c4 + 3) * 128 + row0 + 64] = ra1.w;
        Bs[(c4 + 0) * 128 + row0]      = rb0.x;
        Bs[(c4 + 1) * 128 + row0]      = rb0.y;
        Bs[(c4 + 2) * 128 + row0]      = rb0.z;
        Bs[(c4 + 3) * 128 + row0]      = rb0.w;
        Bs[(c4 + 0) * 128 + row0 + 64] = rb1.x;
        Bs[(c4 + 1) * 128 + row0 + 64] = rb1.y;
        Bs[(c4 + 2) * 128 + row0 + 64] = rb1.z;
        Bs[(c4 + 3) * 128 + row0 + 64] = rb1.w;
        __syncthreads();

        // Prefetch next slab while computing this one
        if (kt + 1 < nk) {
            const float* ap = aptr + (size_t)(kt + 1) * 16;
            const float* bp = bptr + (size_t)(kt + 1) * 16;
            ra0 = *(const float4*)(ap);
            ra1 = *(const float4*)(ap + rowskip);
            rb0 = *(const float4*)(bp);
            rb1 = *(const float4*)(bp + rowskip);
        }

#pragma unroll
        for (int kk = 0; kk < 16; kk++) {
            float4 a0 = *(const float4*)&As[kk * 128 + ty * 8];
            float4 a1 = *(const float4*)&As[kk * 128 + ty * 8 + 4];
            float4 b0 = *(const float4*)&Bs[kk * 128 + tx * 8];
            float4 b1 = *(const float4*)&Bs[kk * 128 + tx * 8 + 4];
            float av[8] = {a0.x, a0.y, a0.z, a0.w, a1.x, a1.y, a1.z, a1.w};
            float bv[8] = {b0.x, b0.y, b0.z, b0.w, b1.x, b1.y, b1.z, b1.w};
#pragma unroll
            for (int i = 0; i < 8; i++)
#pragma unroll
                for (int j = 0; j < 8; j++)
                    acc[i][j] = fmaf(av[i], bv[j], acc[i][j]);
        }
        __syncthreads();
    }

    // Epilogue
    const int cb = n0 + tx * 8;
    float4 bia0 = make_float4(0.f, 0.f, 0.f, 0.f);
    float4 bia1 = make_float4(0.f, 0.f, 0.f, 0.f);
    if (ADD_BIAS) {
        bia0 = *(const float4*)&bias[cb];
        bia1 = *(const float4*)&bias[cb + 4];
    }
#pragma unroll
    for (int i = 0; i < 8; i++) {
        const int r = m0 + ty * 8 + i;
        float4 c0, c1;
        c0.x = acc[i][0] + bia0.x; c0.y = acc[i][1] + bia0.y;
        c0.z = acc[i][2] + bia0.z; c0.w = acc[i][3] + bia0.w;
        c1.x = acc[i][4] + bia1.x; c1.y = acc[i][5] + bia1.y;
        c1.z = acc[i][6] + bia1.z; c1.w = acc[i][7] + bia1.w;
        if (ADD_RES) {
            float4 r0 = *(const float4*)&res[(size_t)r * N + cb];
            float4 r1 = *(const float4*)&res[(size_t)r * N + cb + 4];
            c0.x += r0.x; c0.y += r0.y; c0.z += r0.z; c0.w += r0.w;
            c1.x += r1.x; c1.y += r1.y; c1.z += r1.z; c1.w += r1.w;
        }
        *(float4*)&C[(size_t)r * N + cb]     = c0;
        *(float4*)&C[(size_t)r * N + cb + 4] = c1;
    }
}

// ---------------------------------------------------------------------------
// Flash attention, fp32. One block = one (b,h) x 64-query tile.
// 256 threads = 16x16 grid, each thread owns a 4(q) x 4(k / dv) micro-tile.
// Online softmax in registers; masked keys -> -1e30 (self-correcting).
// K is stored transposed+XOR-swizzled for conflict-free float4 reads.
// P tile reuses the K buffer -> exactly 48 KB static smem.
// ---------------------------------------------------------------------------
__device__ __forceinline__ int ksw(int d, int c) {
    return d * 64 + (c ^ ((d & 15) << 2));
}

__global__ __launch_bounds__(256)
void flash_attn(const float* __restrict__ qkv, const int* __restrict__ mask,
                float* __restrict__ attn)
{
    __shared__ __align__(16) float Qs[64 * 64];    // natural [q][d], pre-scaled
    __shared__ __align__(16) float KPs[64 * 64];   // K transposed+swizzled, later P [q][k]
    __shared__ __align__(16) float Vs[64 * 64];    // natural [k][dv]

    const int tid = threadIdx.x;
    const int tx = tid & 15;
    const int ty = tid >> 4;
    const int b = blockIdx.x >> 4;
    const int h = blockIdx.x & 15;
    const int q0 = blockIdx.y << 6;

    const float scale = 0.125f;   // 1/sqrt(64)

    const float* qbase = qkv + (size_t)(b * SS + q0) * NQKV + h * DHH;
    const float* kbase = qkv + (size_t)b * SS * NQKV + HH * DHH + h * DHH;
    const float* vbase = qkv + (size_t)b * SS * NQKV + 2 * HH * DHH + h * DHH;
    const int*   mrow  = mask + b * SS;

    // Load Q tile (coalesced), pre-scaled
#pragma unroll
    for (int i = 0; i < 16; i++) {
        int e = i * 256 + tid;
        int q = e >> 6, d = e & 63;
        Qs[q * 64 + d] = qbase[(size_t)q * NQKV + d] * scale;
    }

    float m_i[4], l_i[4], o[4][4];
#pragma unroll
    for (int i = 0; i < 4; i++) {
        m_i[i] = -1e30f; l_i[i] = 0.0f;
#pragma unroll
        for (int j = 0; j < 4; j++) o[i][j] = 0.0f;
    }

    for (int k0 = 0; k0 < SS; k0 += 64) {
        // Load K (transposed+swizzled) and V (natural) tiles
#pragma unroll
        for (int i = 0; i < 16; i++) {
            int e = i * 256 + tid;
            int kk = e >> 6, d = e & 63;
            KPs[ksw(d, kk)] = kbase[(size_t)(k0 + kk) * NQKV + d];
            Vs[kk * 64 + d] = vbase[(size_t)(k0 + kk) * NQKV + d];
        }
        int mj[4];
#pragma unroll
        for (int j = 0; j < 4; j++) mj[j] = mrow[k0 + tx * 4 + j];
        __syncthreads();

        // S = Q K^T for this thread's 4x4 tile
        float p[4][4];
#pragma unroll
        for (int i = 0; i < 4; i++)
#pragma unroll
            for (int j = 0; j < 4; j++) p[i][j] = 0.0f;

#pragma unroll 8
        for (int d = 0; d < 64; d++) {
            float4 k4 = *(const float4*)&KPs[ksw(d, tx * 4)];
            float a0 = Qs[(ty * 4 + 0) * 64 + d];
            float a1 = Qs[(ty * 4 + 1) * 64 + d];
            float a2 = Qs[(ty * 4 + 2) * 64 + d];
            float a3 = Qs[(ty * 4 + 3) * 64 + d];
            p[0][0] = fmaf(a0, k4.x, p[0][0]); p[0][1] = fmaf(a0, k4.y, p[0][1]);
            p[0][2] = fmaf(a0, k4.z, p[0][2]); p[0][3] = fmaf(a0, k4.w, p[0][3]);
            p[1][0] = fmaf(a1, k4.x, p[1][0]); p[1][1] = fmaf(a1, k4.y, p[1][1]);
            p[1][2] = fmaf(a1, k4.z, p[1][2]); p[1][3] = fmaf(a1, k4.w, p[1][3]);
            p[2][0] = fmaf(a2, k4.x, p[2][0]); p[2][1] = fmaf(a2, k4.y, p[2][1]);
            p[2][2] = fmaf(a2, k4.z, p[2][2]); p[2][3] = fmaf(a2, k4.w, p[2][3]);
            p[3][0] = fmaf(a3, k4.x, p[3][0]); p[3][1] = fmaf(a3, k4.y, p[3][1]);
            p[3][2] = fmaf(a3, k4.z, p[3][2]); p[3][3] = fmaf(a3, k4.w, p[3][3]);
        }

        // Key-padding mask: attn_mask==1 -> masked
#pragma unroll
        for (int j = 0; j < 4; j++)
            if (mj[j]) {
#pragma unroll
                for (int i = 0; i < 4; i++) p[i][j] = -1e30f;
            }

        // Online softmax (row groups = 16 consecutive lanes)
#pragma unroll
        for (int i = 0; i < 4; i++) {
            float mm = fmaxf(fmaxf(p[i][0], p[i][1]), fmaxf(p[i][2], p[i][3]));
#pragma unroll
            for (int off = 1; off < 16; off <<= 1)
                mm = fmaxf(mm, __shfl_xor_sync(0xffffffffu, mm, off));
            float mn = fmaxf(m_i[i], mm);
            float alpha = __expf(m_i[i] - mn);
            m_i[i] = mn;
            float ls = 0.0f;
#pragma unroll
            for (int j = 0; j < 4; j++) {
                p[i][j] = __expf(p[i][j] - mn);
                ls += p[i][j];
            }
#pragma unroll
            for (int off = 1; off < 16; off <<= 1)
                ls += __shfl_xor_sync(0xffffffffu, ls, off);
            l_i[i] = l_i[i] * alpha + ls;
#pragma unroll
            for (int j = 0; j < 4; j++) o[i][j] *= alpha;
        }

        __syncthreads();  // everyone done reading KPs as K
        // Stage P (natural [q][k]) into the K buffer
#pragma unroll
        for (int i = 0; i < 4; i++)
            *(float4*)&KPs[(ty * 4 + i) * 64 + tx * 4] =
                make_float4(p[i][0], p[i][1], p[i][2], p[i][3]);
        __syncthreads();

        // O += P V
#pragma unroll 8
        for (int j = 0; j < 64; j++) {
            float4 v4 = *(const float4*)&Vs[j * 64 + tx * 4];
            float a0 = KPs[(ty * 4 + 0) * 64 + j];
            float a1 = KPs[(ty * 4 + 1) * 64 + j];
            float a2 = KPs[(ty * 4 + 2) * 64 + j];
            float a3 = KPs[(ty * 4 + 3) * 64 + j];
            o[0][0] = fmaf(a0, v4.x, o[0][0]); o[0][1] = fmaf(a0, v4.y, o[0][1]);
            o[0][2] = fmaf(a0, v4.z, o[0][2]); o[0][3] = fmaf(a0, v4.w, o[0][3]);
            o[1][0] = fmaf(a1, v4.x, o[1][0]); o[1][1] = fmaf(a1, v4.y, o[1][1]);
            o[1][2] = fmaf(a1, v4.z, o[1][2]); o[1][3] = fmaf(a1, v4.w, o[1][3]);
            o[2][0] = fmaf(a2, v4.x, o[2][0]); o[2][1] = fmaf(a2, v4.y, o[2][1]);
            o[2][2] = fmaf(a2, v4.z, o[2][2]); o[2][3] = fmaf(a2, v4.w, o[2][3]);
            o[3][0] = fmaf(a3, v4.x, o[3][0]); o[3][1] = fmaf(a3, v4.y, o[3][1]);
            o[3][2] = fmaf(a3, v4.z, o[3][2]); o[3][3] = fmaf(a3, v4.w, o[3][3]);
        }
        __syncthreads();  // done reading KPs/Vs before next tile load
    }

    // Epilogue: O / l -> attn buffer [B,S,H*DH]
    float* obase = attn + (size_t)(b * SS + q0) * DD + h * DHH;
#pragma unroll
    for (int i = 0; i < 4; i++) {
        float inv = 1.0f / l_i[i];
        *(float4*)&obase[(size_t)(ty * 4 + i) * DD + tx * 4] =
            make_float4(o[i][0] * inv, o[i][1] * inv, o[i][2] * inv, o[i][3] * inv);
    }
}

// ---------------------------------------------------------------------------
// LayerNorm: one block per row of 1024, 256 threads x float4.
// ---------------------------------------------------------------------------
__global__ __launch_bounds__(256)
void ln_kernel(const float* __restrict__ y, const float* __restrict__ gamma,
               const float* __restrict__ beta, float* __restrict__ out)
{
    __shared__ float red[16];
    const int row = blockIdx.x;
    const int tid = threadIdx.x;
    const float* yr = y + (size_t)row * DD;

    float4 v = *(const float4*)&yr[tid * 4];
    float s  = v.x + v.y + v.z + v.w;
    float s2 = v.x * v.x + v.y * v.y + v.z * v.z + v.w * v.w;
#pragma unroll
    for (int off = 16; off; off >>= 1) {
        s  += __shfl_xor_sync(0xffffffffu, s,  off);
        s2 += __shfl_xor_sync(0xffffffffu, s2, off);
    }
    const int w = tid >> 5;
    if ((tid & 31) == 0) { red[w] = s; red[w + 8] = s2; }
    __syncthreads();
    s = 0.0f; s2 = 0.0f;
#pragma unroll
    for (int i = 0; i < 8; i++) { s += red[i]; s2 += red[i + 8]; }

    const float mean = s * (1.0f / DD);
    const float var  = s2 * (1.0f / DD) - mean * mean;
    const float inv  = rsqrtf(var + 1e-5f);

    float4 g  = *(const float4*)&gamma[tid * 4];
    float4 bt = *(const float4*)&beta[tid * 4];
    float4 r;
    r.x = (v.x - mean) * inv * g.x + bt.x;
    r.y = (v.y - mean) * inv * g.y + bt.y;
    r.z = (v.z - mean) * inv * g.z + bt.z;
    r.w = (v.w - mean) * inv * g.w + bt.w;
    *(float4*)&out[(size_t)row * DD + tid * 4] = r;
}

// ---------------------------------------------------------------------------
extern "C" void kernel_launch(void* const* d_in, const int* in_sizes, int n_in,
                              void* d_out, int out_size)
{
    (void)in_sizes; (void)n_in; (void)out_size;
    const float* inp   = (const float*)d_in[0];
    const int*   mask  = (const int*)d_in[1];
    const float* Wqkv  = (const float*)d_in[2];
    const float* bqkv  = (const float*)d_in[3];
    const float* Wo    = (const float*)d_in[4];
    const float* gamma = (const float*)d_in[5];
    const float* beta  = (const float*)d_in[6];
    float* out = (float*)d_out;

    float *qkv, *attn, *y;
    cudaGetSymbolAddress((void**)&qkv,  g_qkv);
    cudaGetSymbolAddress((void**)&attn, g_attn);
    cudaGetSymbolAddress((void**)&y,    g_y);

    // 1) QKV = inp @ Wqkv^T + bqkv        [8192, 3072]
    sgemm_nt<true, false><<<dim3(NQKV / 128, MTOK / 128), 256>>>(
        inp, Wqkv, bqkv, nullptr, qkv, MTOK, NQKV, DD);

    // 2) attention                        [8192, 1024]
    flash_attn<<<dim3(BB * HH, SS / 64), 256>>>(qkv, mask, attn);

    // 3) y = inp + attn @ Wo^T            [8192, 1024]
    sgemm_nt<false, true><<<dim3(DD / 128, MTOK / 128), 256>>>(
        attn, Wo, nullptr, inp, y, MTOK, DD, DD);

    // 4) out = LayerNorm(y)
    ln_kernel<<<MTOK, 256>>>(y, gamma, beta, out);
}

// round 5
// speedup vs baseline: 6.1796x; 6.1796x over previous
#include <cuda_runtime.h>
#include <cuda_bf16.h>
#include <cstdint>

#define BB   4
#define SS   2048
#define DD   1024
#define HH   16
#define DHH  64
#define MTOK (BB * SS)          // 8192
#define NQKV (3 * HH * DHH)     // 3072

typedef __nv_bfloat16  bf16;
typedef __nv_bfloat162 bf162;

// ---------------------------------------------------------------------------
// Scratch (static __device__ arrays; no allocation allowed)
// ---------------------------------------------------------------------------
__device__ bf16  g_inpb [(size_t)MTOK * DD];     // 16 MB
__device__ bf16  g_wqkvb[(size_t)NQKV * DD];     // 6 MB
__device__ bf16  g_wob  [(size_t)DD * DD];       // 2 MB
__device__ bf16  g_qkvb [(size_t)MTOK * NQKV];   // 48 MB
__device__ bf16  g_attnb[(size_t)MTOK * DD];     // 16 MB
__device__ float g_y    [(size_t)MTOK * DD];     // 32 MB

// ---------------------------------------------------------------------------
// MMA / ldmatrix helpers (sm_80-style HMMA path; valid on sm_100a)
// ---------------------------------------------------------------------------
__device__ __forceinline__ uint32_t su32(const void* p) {
    return (uint32_t)__cvta_generic_to_shared(p);
}
__device__ __forceinline__ void ldm4(uint32_t& r0, uint32_t& r1, uint32_t& r2,
                                     uint32_t& r3, uint32_t a) {
    asm volatile("ldmatrix.sync.aligned.m8n8.x4.shared.b16 {%0,%1,%2,%3},[%4];\n"
                 : "=r"(r0), "=r"(r1), "=r"(r2), "=r"(r3) : "r"(a));
}
__device__ __forceinline__ void ldm4t(uint32_t& r0, uint32_t& r1, uint32_t& r2,
                                      uint32_t& r3, uint32_t a) {
    asm volatile("ldmatrix.sync.aligned.m8n8.x4.trans.shared.b16 {%0,%1,%2,%3},[%4];\n"
                 : "=r"(r0), "=r"(r1), "=r"(r2), "=r"(r3) : "r"(a));
}
__device__ __forceinline__ void mmabf(float* c, const uint32_t* a,
                                      uint32_t b0, uint32_t b1) {
    asm volatile(
        "mma.sync.aligned.m16n8k16.row.col.f32.bf16.bf16.f32 "
        "{%0,%1,%2,%3},{%4,%5,%6,%7},{%8,%9},{%0,%1,%2,%3};\n"
        : "+f"(c[0]), "+f"(c[1]), "+f"(c[2]), "+f"(c[3])
        : "r"(a[0]), "r"(a[1]), "r"(a[2]), "r"(a[3]), "r"(b0), "r"(b1));
}
__device__ __forceinline__ uint32_t packbf(float x, float y) {
    bf162 t = __floats2bfloat162_rn(x, y);
    return *reinterpret_cast<uint32_t*>(&t);
}

// ---------------------------------------------------------------------------
// fp32 -> bf16 conversion
// ---------------------------------------------------------------------------
__global__ void f2bf(const float* __restrict__ in, bf16* __restrict__ out, int n) {
    int i = (blockIdx.x * blockDim.x + threadIdx.x) * 4;
    if (i >= n) return;
    float4 v = *(const float4*)(in + i);
    bf162* o = (bf162*)(out + i);
    o[0] = __floats2bfloat162_rn(v.x, v.y);
    o[1] = __floats2bfloat162_rn(v.z, v.w);
}

// ---------------------------------------------------------------------------
// bf16 HGEMM (NT): C[M,N] = A[M,K] * W[N,K]^T (+bias fp32) (+res fp32)
// 128x128x32 tiles, 8 warps, warp tile 64x32, m16n8k16 HMMA.
// smem rows padded to 40 bf16 (80 B): conflict-free ldmatrix, 16B-aligned.
// ---------------------------------------------------------------------------
#define LDT 40
template <bool BIAS, bool RES, bool OBF>
__global__ __launch_bounds__(256)
void hgemm_nt(const bf16* __restrict__ A, const bf16* __restrict__ W,
              const float* __restrict__ bias, const float* __restrict__ res,
              void* __restrict__ Cout, int M, int N, int K)
{
    __shared__ __align__(16) bf16 As[128 * LDT];
    __shared__ __align__(16) bf16 Bs[128 * LDT];

    const int tid  = threadIdx.x;
    const int wid  = tid >> 5, lane = tid & 31;
    const int m0   = blockIdx.y << 7, n0 = blockIdx.x << 7;
    const int wm   = (wid >> 2) << 6, wn = (wid & 3) << 5;
    const int row0 = tid >> 2, seg = tid & 3;

    const bf16* aP = A + (size_t)(m0 + row0) * K + seg * 8;
    const bf16* bP = W + (size_t)(n0 + row0) * K + seg * 8;
    const size_t rs = (size_t)64 * K;

    uint4 ra0 = *(const uint4*)aP, ra1 = *(const uint4*)(aP + rs);
    uint4 rb0 = *(const uint4*)bP, rb1 = *(const uint4*)(bP + rs);

    float acc[4][4][4];
#pragma unroll
    for (int i = 0; i < 4; i++)
#pragma unroll
        for (int j = 0; j < 4; j++)
#pragma unroll
            for (int e = 0; e < 4; e++) acc[i][j][e] = 0.0f;

    const int nk = K >> 5;
    for (int kt = 0; kt < nk; kt++) {
        *(uint4*)&As[row0 * LDT + seg * 8]        = ra0;
        *(uint4*)&As[(row0 + 64) * LDT + seg * 8] = ra1;
        *(uint4*)&Bs[row0 * LDT + seg * 8]        = rb0;
        *(uint4*)&Bs[(row0 + 64) * LDT + seg * 8] = rb1;
        __syncthreads();

        if (kt + 1 < nk) {
            const bf16* ap = aP + (size_t)(kt + 1) * 32;
            const bf16* bp = bP + (size_t)(kt + 1) * 32;
            ra0 = *(const uint4*)ap; ra1 = *(const uint4*)(ap + rs);
            rb0 = *(const uint4*)bp; rb1 = *(const uint4*)(bp + rs);
        }

#pragma unroll
        for (int ks = 0; ks < 2; ks++) {
            uint32_t af[4][4], bfr[4][2];
#pragma unroll
            for (int mf = 0; mf < 4; mf++) {
                uint32_t ad = su32(&As[(wm + mf * 16 + (lane & 15)) * LDT +
                                       ks * 16 + (lane >> 4) * 8]);
                ldm4(af[mf][0], af[mf][1], af[mf][2], af[mf][3], ad);
            }
#pragma unroll
            for (int p = 0; p < 2; p++) {
                uint32_t bd = su32(&Bs[(wn + p * 16 + (lane & 7) + ((lane >> 4) << 3)) * LDT +
                                       ks * 16 + ((lane >> 3) & 1) * 8]);
                ldm4(bfr[2 * p][0], bfr[2 * p][1], bfr[2 * p + 1][0], bfr[2 * p + 1][1], bd);
            }
#pragma unroll
            for (int mf = 0; mf < 4; mf++)
#pragma unroll
                for (int nf = 0; nf < 4; nf++)
                    mmabf(acc[mf][nf], af[mf], bfr[nf][0], bfr[nf][1]);
        }
        __syncthreads();
    }

    // Epilogue. acc c0,c1 -> (row r0, cols c,c+1); c2,c3 -> (row r0+8).
#pragma unroll
    for (int mf = 0; mf < 4; mf++) {
        const int r0 = m0 + wm + mf * 16 + (lane >> 2);
#pragma unroll
        for (int nf = 0; nf < 4; nf++) {
            const int c = n0 + wn + nf * 8 + (lane & 3) * 2;
            float v0 = acc[mf][nf][0], v1 = acc[mf][nf][1];
            float v2 = acc[mf][nf][2], v3 = acc[mf][nf][3];
            if (BIAS) {
                float b0v = bias[c], b1v = bias[c + 1];
                v0 += b0v; v1 += b1v; v2 += b0v; v3 += b1v;
            }
            if (RES) {
                float2 q0 = *(const float2*)&res[(size_t)r0 * N + c];
                float2 q1 = *(const float2*)&res[(size_t)(r0 + 8) * N + c];
                v0 += q0.x; v1 += q0.y; v2 += q1.x; v3 += q1.y;
            }
            if (OBF) {
                bf16* C = (bf16*)Cout;
                *(bf162*)&C[(size_t)r0 * N + c]       = __floats2bfloat162_rn(v0, v1);
                *(bf162*)&C[(size_t)(r0 + 8) * N + c] = __floats2bfloat162_rn(v2, v3);
            } else {
                float* C = (float*)Cout;
                *(float2*)&C[(size_t)r0 * N + c]       = make_float2(v0, v1);
                *(float2*)&C[(size_t)(r0 + 8) * N + c] = make_float2(v2, v3);
            }
        }
    }
}

// ---------------------------------------------------------------------------
// bf16 flash attention. Block = (b,h) x 64-query tile, 4 warps (16 q each).
// QK^T and PV on HMMA; softmax fp32 in registers; S-acc repacked in-register
// as the A operand of PV (no smem round-trip). V fragments via ldmatrix.trans.
// smem rows padded to 72 bf16 (144 B): conflict-free, 16B-aligned.
// ---------------------------------------------------------------------------
#define LQT 72
__global__ __launch_bounds__(128)
void flash_bf16(const bf16* __restrict__ qkv, const int* __restrict__ mask,
                bf16* __restrict__ attn)
{
    __shared__ __align__(16) bf16 Qs[64 * LQT];
    __shared__ __align__(16) bf16 Ks[64 * LQT];
    __shared__ __align__(16) bf16 Vs[64 * LQT];
    __shared__ int msks[64];

    const int tid = threadIdx.x, wid = tid >> 5, lane = tid & 31;
    const int b = blockIdx.x >> 4, h = blockIdx.x & 15;
    const int q0 = blockIdx.y << 6;

    const bf16* qb = qkv + (size_t)(b * SS + q0) * NQKV + h * DHH;
    const bf16* kb = qkv + (size_t)b * SS * NQKV + HH * DHH + h * DHH;
    const bf16* vb = qkv + (size_t)b * SS * NQKV + 2 * HH * DHH + h * DHH;
    const int*  mrow = mask + b * SS;

#pragma unroll
    for (int i = 0; i < 4; i++) {
        int e = i * 128 + tid, r = e >> 3, sg = e & 7;
        *(uint4*)&Qs[r * LQT + sg * 8] = *(const uint4*)&qb[(size_t)r * NQKV + sg * 8];
    }
    __syncthreads();

    // Q fragments, loaded once (constant across the key loop)
    uint32_t qf[4][4];
#pragma unroll
    for (int ks = 0; ks < 4; ks++) {
        uint32_t ad = su32(&Qs[(wid * 16 + (lane & 15)) * LQT + ks * 16 + (lane >> 4) * 8]);
        ldm4(qf[ks][0], qf[ks][1], qf[ks][2], qf[ks][3], ad);
    }

    float m0v = -1e30f, m1v = -1e30f, l0 = 0.0f, l1 = 0.0f;
    float o[8][4];
#pragma unroll
    for (int nf = 0; nf < 8; nf++)
#pragma unroll
        for (int e = 0; e < 4; e++) o[nf][e] = 0.0f;

    for (int kb0 = 0; kb0 < SS; kb0 += 64) {
        __syncthreads();
#pragma unroll
        for (int i = 0; i < 4; i++) {
            int e = i * 128 + tid, r = e >> 3, sg = e & 7;
            *(uint4*)&Ks[r * LQT + sg * 8] = *(const uint4*)&kb[(size_t)(kb0 + r) * NQKV + sg * 8];
            *(uint4*)&Vs[r * LQT + sg * 8] = *(const uint4*)&vb[(size_t)(kb0 + r) * NQKV + sg * 8];
        }
        if (tid < 64) msks[tid] = mrow[kb0 + tid];
        __syncthreads();

        // S = Q K^T  (per warp: 16q x 64k; 8 n-frags, 4 k-steps over dh)
        float sv[8][4];
#pragma unroll
        for (int nf = 0; nf < 8; nf++)
#pragma unroll
            for (int e = 0; e < 4; e++) sv[nf][e] = 0.0f;

#pragma unroll
        for (int ks = 0; ks < 4; ks++) {
            uint32_t kf[8][2];
#pragma unroll
            for (int p = 0; p < 4; p++) {
                uint32_t bd = su32(&Ks[(p * 16 + (lane & 7) + ((lane >> 4) << 3)) * LQT +
                                       ks * 16 + ((lane >> 3) & 1) * 8]);
                ldm4(kf[2 * p][0], kf[2 * p][1], kf[2 * p + 1][0], kf[2 * p + 1][1], bd);
            }
#pragma unroll
            for (int nf = 0; nf < 8; nf++)
                mmabf(sv[nf], qf[ks], kf[nf][0], kf[nf][1]);
        }

        // scale + key-padding mask (mask==1 -> masked)
        const int c2 = (lane & 3) * 2;
#pragma unroll
        for (int nf = 0; nf < 8; nf++) {
            int mk0 = msks[nf * 8 + c2], mk1 = msks[nf * 8 + c2 + 1];
            sv[nf][0] = mk0 ? -1e30f : sv[nf][0] * 0.125f;
            sv[nf][1] = mk1 ? -1e30f : sv[nf][1] * 0.125f;
            sv[nf][2] = mk0 ? -1e30f : sv[nf][2] * 0.125f;
            sv[nf][3] = mk1 ? -1e30f : sv[nf][3] * 0.125f;
        }

        // online softmax; rows r0 (c0,c1) and r0+8 (c2,c3); quad = lanes xor 1,2
        float mx0 = -1e30f, mx1 = -1e30f;
#pragma unroll
        for (int nf = 0; nf < 8; nf++) {
            mx0 = fmaxf(mx0, fmaxf(sv[nf][0], sv[nf][1]));
            mx1 = fmaxf(mx1, fmaxf(sv[nf][2], sv[nf][3]));
        }
        mx0 = fmaxf(mx0, __shfl_xor_sync(0xffffffffu, mx0, 1));
        mx0 = fmaxf(mx0, __shfl_xor_sync(0xffffffffu, mx0, 2));
        mx1 = fmaxf(mx1, __shfl_xor_sync(0xffffffffu, mx1, 1));
        mx1 = fmaxf(mx1, __shfl_xor_sync(0xffffffffu, mx1, 2));

        float mn0 = fmaxf(m0v, mx0), mn1 = fmaxf(m1v, mx1);
        float al0 = __expf(m0v - mn0), al1 = __expf(m1v - mn1);
        m0v = mn0; m1v = mn1;

        float sum0 = 0.0f, sum1 = 0.0f;
#pragma unroll
        for (int nf = 0; nf < 8; nf++) {
            sv[nf][0] = __expf(sv[nf][0] - mn0);
            sv[nf][1] = __expf(sv[nf][1] - mn0);
            sv[nf][2] = __expf(sv[nf][2] - mn1);
            sv[nf][3] = __expf(sv[nf][3] - mn1);
            sum0 += sv[nf][0] + sv[nf][1];
            sum1 += sv[nf][2] + sv[nf][3];
        }
        sum0 += __shfl_xor_sync(0xffffffffu, sum0, 1);
        sum0 += __shfl_xor_sync(0xffffffffu, sum0, 2);
        sum1 += __shfl_xor_sync(0xffffffffu, sum1, 1);
        sum1 += __shfl_xor_sync(0xffffffffu, sum1, 2);
        l0 = l0 * al0 + sum0;
        l1 = l1 * al1 + sum1;
#pragma unroll
        for (int nf = 0; nf < 8; nf++) {
            o[nf][0] *= al0; o[nf][1] *= al0;
            o[nf][2] *= al1; o[nf][3] *= al1;
        }

        // O += P V : P repacked in-register as A frags; V via ldmatrix.trans
#pragma unroll
        for (int ks = 0; ks < 4; ks++) {
            uint32_t pa[4];
            pa[0] = packbf(sv[2 * ks][0],     sv[2 * ks][1]);
            pa[1] = packbf(sv[2 * ks][2],     sv[2 * ks][3]);
            pa[2] = packbf(sv[2 * ks + 1][0], sv[2 * ks + 1][1]);
            pa[3] = packbf(sv[2 * ks + 1][2], sv[2 * ks + 1][3]);
#pragma unroll
            for (int p = 0; p < 4; p++) {
                uint32_t v0, v1, v2, v3;
                uint32_t vd = su32(&Vs[(ks * 16 + (lane & 7) + (((lane >> 3) & 1) << 3)) * LQT +
                                       p * 16 + ((lane >> 4) << 3)]);
                ldm4t(v0, v1, v2, v3, vd);
                mmabf(o[2 * p],     pa, v0, v1);
                mmabf(o[2 * p + 1], pa, v2, v3);
            }
        }
    }

    const float i0 = 1.0f / l0, i1 = 1.0f / l1;
    const int r0 = q0 + wid * 16 + (lane >> 2);
    bf16* ob = attn + (size_t)b * SS * DD + h * DHH;
#pragma unroll
    for (int nf = 0; nf < 8; nf++) {
        int c = nf * 8 + (lane & 3) * 2;
        *(bf162*)&ob[(size_t)r0 * DD + c] =
            __floats2bfloat162_rn(o[nf][0] * i0, o[nf][1] * i0);
        *(bf162*)&ob[(size_t)(r0 + 8) * DD + c] =
            __floats2bfloat162_rn(o[nf][2] * i1, o[nf][3] * i1);
    }
}

// ---------------------------------------------------------------------------
// LayerNorm: one block per row of 1024, 256 threads x float4. (unchanged)
// ---------------------------------------------------------------------------
__global__ __launch_bounds__(256)
void ln_kernel(const float* __restrict__ y, const float* __restrict__ gamma,
               const float* __restrict__ beta, float* __restrict__ out)
{
    __shared__ float red[16];
    const int row = blockIdx.x;
    const int tid = threadIdx.x;
    const float* yr = y + (size_t)row * DD;

    float4 v = *(const float4*)&yr[tid * 4];
    float s  = v.x + v.y + v.z + v.w;
    float s2 = v.x * v.x + v.y * v.y + v.z * v.z + v.w * v.w;
#pragma unroll
    for (int off = 16; off; off >>= 1) {
        s  += __shfl_xor_sync(0xffffffffu, s,  off);
        s2 += __shfl_xor_sync(0xffffffffu, s2, off);
    }
    const int w = tid >> 5;
    if ((tid & 31) == 0) { red[w] = s; red[w + 8] = s2; }
    __syncthreads();
    s = 0.0f; s2 = 0.0f;
#pragma unroll
    for (int i = 0; i < 8; i++) { s += red[i]; s2 += red[i + 8]; }

    const float mean = s * (1.0f / DD);
    const float var  = s2 * (1.0f / DD) - mean * mean;
    const float inv  = rsqrtf(var + 1e-5f);

    float4 g  = *(const float4*)&gamma[tid * 4];
    float4 bt = *(const float4*)&beta[tid * 4];
    float4 r;
    r.x = (v.x - mean) * inv * g.x + bt.x;
    r.y = (v.y - mean) * inv * g.y + bt.y;
    r.z = (v.z - mean) * inv * g.z + bt.z;
    r.w = (v.w - mean) * inv * g.w + bt.w;
    *(float4*)&out[(size_t)row * DD + tid * 4] = r;
}

// ---------------------------------------------------------------------------
extern "C" void kernel_launch(void* const* d_in, const int* in_sizes, int n_in,
                              void* d_out, int out_size)
{
    (void)in_sizes; (void)n_in; (void)out_size;
    const float* inp   = (const float*)d_in[0];
    const int*   mask  = (const int*)d_in[1];
    const float* Wqkv  = (const float*)d_in[2];
    const float* bqkv  = (const float*)d_in[3];
    const float* Wo    = (const float*)d_in[4];
    const float* gamma = (const float*)d_in[5];
    const float* beta  = (const float*)d_in[6];
    float* out = (float*)d_out;

    bf16 *inpb, *wqkvb, *wob, *qkvb, *attnb;
    float* y;
    cudaGetSymbolAddress((void**)&inpb,  g_inpb);
    cudaGetSymbolAddress((void**)&wqkvb, g_wqkvb);
    cudaGetSymbolAddress((void**)&wob,   g_wob);
    cudaGetSymbolAddress((void**)&qkvb,  g_qkvb);
    cudaGetSymbolAddress((void**)&attnb, g_attnb);
    cudaGetSymbolAddress((void**)&y,     g_y);

    // 0) fp32 -> bf16 conversions
    f2bf<<<(MTOK * DD) / 1024, 256>>>(inp,  inpb,  MTOK * DD);
    f2bf<<<(NQKV * DD) / 1024, 256>>>(Wqkv, wqkvb, NQKV * DD);
    f2bf<<<(DD * DD)   / 1024, 256>>>(Wo,   wob,   DD * DD);

    // 1) QKV = inp @ Wqkv^T + bqkv   -> bf16 [8192, 3072]
    hgemm_nt<true, false, true><<<dim3(NQKV / 128, MTOK / 128), 256>>>(
        inpb, wqkvb, bqkv, nullptr, qkvb, MTOK, NQKV, DD);

    // 2) attention -> bf16 [8192, 1024]
    flash_bf16<<<dim3(BB * HH, SS / 64), 128>>>(qkvb, mask, attnb);

    // 3) y = inp + attn @ Wo^T  -> fp32 [8192, 1024]
    hgemm_nt<false, true, false><<<dim3(DD / 128, MTOK / 128), 256>>>(
        attnb, wob, nullptr, inp, y, MTOK, DD, DD);

    // 4) out = LayerNorm(y)
    ln_kernel<<<MTOK, 256>>>(y, gamma, beta, out);
}

// round 7
// speedup vs baseline: 6.3724x; 1.0312x over previous
#include <cuda_runtime.h>
#include <cuda_bf16.h>
#include <cstdint>

#define BB   4
#define SS   2048
#define DD   1024
#define HH   16
#define DHH  64
#define MTOK (BB * SS)          // 8192
#define NQKV (3 * HH * DHH)     // 3072

typedef __nv_bfloat16  bf16;
typedef __nv_bfloat162 bf162;

// ---------------------------------------------------------------------------
// Scratch (static __device__ arrays; no allocation allowed)
// ---------------------------------------------------------------------------
__device__ bf16  g_inpb [(size_t)MTOK * DD];     // 16 MB
__device__ bf16  g_wqkvb[(size_t)NQKV * DD];     // 6 MB
__device__ bf16  g_wob  [(size_t)DD * DD];       // 2 MB
__device__ bf16  g_qkvb [(size_t)MTOK * NQKV];   // 48 MB
__device__ bf16  g_attnb[(size_t)MTOK * DD];     // 16 MB
__device__ float g_y    [(size_t)MTOK * DD];     // 32 MB

// ---------------------------------------------------------------------------
// Helpers: ldmatrix / mma.sync (sm_80 PTX — compiles at compute_100) + cp.async
// ---------------------------------------------------------------------------
__device__ __forceinline__ uint32_t su32(const void* p) {
    return (uint32_t)__cvta_generic_to_shared(p);
}
__device__ __forceinline__ void ldm4(uint32_t& r0, uint32_t& r1, uint32_t& r2,
                                     uint32_t& r3, uint32_t a) {
    asm volatile("ldmatrix.sync.aligned.m8n8.x4.shared.b16 {%0,%1,%2,%3},[%4];\n"
                 : "=r"(r0), "=r"(r1), "=r"(r2), "=r"(r3) : "r"(a));
}
__device__ __forceinline__ void ldm4t(uint32_t& r0, uint32_t& r1, uint32_t& r2,
                                      uint32_t& r3, uint32_t a) {
    asm volatile("ldmatrix.sync.aligned.m8n8.x4.trans.shared.b16 {%0,%1,%2,%3},[%4];\n"
                 : "=r"(r0), "=r"(r1), "=r"(r2), "=r"(r3) : "r"(a));
}
__device__ __forceinline__ void mmabf(float* c, const uint32_t* a,
                                      uint32_t b0, uint32_t b1) {
    asm volatile(
        "mma.sync.aligned.m16n8k16.row.col.f32.bf16.bf16.f32 "
        "{%0,%1,%2,%3},{%4,%5,%6,%7},{%8,%9},{%0,%1,%2,%3};\n"
        : "+f"(c[0]), "+f"(c[1]), "+f"(c[2]), "+f"(c[3])
        : "r"(a[0]), "r"(a[1]), "r"(a[2]), "r"(a[3]), "r"(b0), "r"(b1));
}
__device__ __forceinline__ uint32_t packbf(float x, float y) {
    bf162 t = __floats2bfloat162_rn(x, y);
    return *reinterpret_cast<uint32_t*>(&t);
}
__device__ __forceinline__ void cpa16(uint32_t dst, const void* src) {
    asm volatile("cp.async.cg.shared.global [%0], [%1], 16;\n" :: "r"(dst), "l"(src));
}
#define CPCOMMIT() asm volatile("cp.async.commit_group;\n" ::: "memory")
#define CPWAIT(n)  asm volatile("cp.async.wait_group %0;\n" :: "n"(n) : "memory")

// ---------------------------------------------------------------------------
// fp32 -> bf16 conversion
// ---------------------------------------------------------------------------
__global__ void f2bf(const float* __restrict__ in, bf16* __restrict__ out, int n) {
    int i = (blockIdx.x * blockDim.x + threadIdx.x) * 4;
    if (i >= n) return;
    float4 v = *(const float4*)(in + i);
    bf162* o = (bf162*)(out + i);
    o[0] = __floats2bfloat162_rn(v.x, v.y);
    o[1] = __floats2bfloat162_rn(v.z, v.w);
}

// ---------------------------------------------------------------------------
// bf16 HGEMM (NT): C[M,N] = A[M,K] * W[N,K]^T (+bias fp32) (+res fp32)
// 128x128x32 tiles, 8 warps, warp tile 64x32, m16n8k16 HMMA.
// cp.async 2-stage pipeline: global->smem async, ONE __syncthreads per
// K-chunk, compute(k) overlaps fetch(k+1).
// smem rows padded to 40 bf16 (80 B): conflict-free ldmatrix, 16B-aligned.
// ---------------------------------------------------------------------------
#define LDT 40
template <bool BIAS, bool RES, bool OBF>
__global__ __launch_bounds__(256)
void hgemm_nt(const bf16* __restrict__ A, const bf16* __restrict__ W,
              const float* __restrict__ bias, const float* __restrict__ res,
              void* __restrict__ Cout, int M, int N, int K)
{
    __shared__ __align__(16) bf16 As[2][128 * LDT];   // 2 x 10 KB
    __shared__ __align__(16) bf16 Bs[2][128 * LDT];   // 2 x 10 KB

    const int tid  = threadIdx.x;
    const int wid  = tid >> 5, lane = tid & 31;
    const int m0   = blockIdx.y << 7, n0 = blockIdx.x << 7;
    const int wm   = (wid >> 2) << 6, wn = (wid & 3) << 5;

    // cp.async mapping: 512 16B-chunks per operand tile / 256 thr = 2 each.
    // chunk c: row r = c>>2 (128 rows), 16B-seg sg = c&3 (row = 32 bf16 = 64B).
    const int r0c = tid >> 2, sg0 = (tid & 3);

    float acc[4][4][4];
#pragma unroll
    for (int i = 0; i < 4; i++)
#pragma unroll
        for (int j = 0; j < 4; j++)
#pragma unroll
            for (int e = 0; e < 4; e++) acc[i][j][e] = 0.0f;

    const int nk = K >> 5;

    // load_stage(kt, buf): issue 4 cp.async per thread + one commit group
    auto load_stage = [&](int kt, int buf) {
        const int kofs = kt * 32;
#pragma unroll
        for (int i = 0; i < 2; i++) {
            int r = r0c + i * 64;
            cpa16(su32(&As[buf][r * LDT + sg0 * 8]),
                  &A[(size_t)(m0 + r) * K + kofs + sg0 * 8]);
        }
#pragma unroll
        for (int i = 0; i < 2; i++) {
            int r = r0c + i * 64;
            cpa16(su32(&Bs[buf][r * LDT + sg0 * 8]),
                  &W[(size_t)(n0 + r) * K + kofs + sg0 * 8]);
        }
        CPCOMMIT();
    };

    load_stage(0, 0);

    for (int kt = 0; kt < nk; kt++) {
        const int buf = kt & 1;
        CPWAIT(0);            // all pending groups (incl. stage kt) complete
        __syncthreads();      // data visible to all; previous buf free

        if (kt + 1 < nk) load_stage(kt + 1, buf ^ 1);

#pragma unroll
        for (int ks = 0; ks < 2; ks++) {
            uint32_t af[4][4], bfr[4][2];
#pragma unroll
            for (int mf = 0; mf < 4; mf++) {
                uint32_t ad = su32(&As[buf][(wm + mf * 16 + (lane & 15)) * LDT +
                                            ks * 16 + (lane >> 4) * 8]);
                ldm4(af[mf][0], af[mf][1], af[mf][2], af[mf][3], ad);
            }
#pragma unroll
            for (int p = 0; p < 2; p++) {
                uint32_t bd = su32(&Bs[buf][(wn + p * 16 + (lane & 7) + ((lane >> 4) << 3)) * LDT +
                                            ks * 16 + ((lane >> 3) & 1) * 8]);
                ldm4(bfr[2 * p][0], bfr[2 * p][1], bfr[2 * p + 1][0], bfr[2 * p + 1][1], bd);
            }
#pragma unroll
            for (int mf = 0; mf < 4; mf++)
#pragma unroll
                for (int nf = 0; nf < 4; nf++)
                    mmabf(acc[mf][nf], af[mf], bfr[nf][0], bfr[nf][1]);
        }
        __syncthreads();      // done reading buf before next iter's load into it
    }

    // Epilogue. acc c0,c1 -> (row r, cols c,c+1); c2,c3 -> (row r+8).
#pragma unroll
    for (int mf = 0; mf < 4; mf++) {
        const int r = m0 + wm + mf * 16 + (lane >> 2);
#pragma unroll
        for (int nf = 0; nf < 4; nf++) {
            const int c = n0 + wn + nf * 8 + (lane & 3) * 2;
            float v0 = acc[mf][nf][0], v1 = acc[mf][nf][1];
            float v2 = acc[mf][nf][2], v3 = acc[mf][nf][3];
            if (BIAS) {
                float b0v = bias[c], b1v = bias[c + 1];
                v0 += b0v; v1 += b1v; v2 += b0v; v3 += b1v;
            }
            if (RES) {
                float2 q0 = *(const float2*)&res[(size_t)r * N + c];
                float2 q1 = *(const float2*)&res[(size_t)(r + 8) * N + c];
                v0 += q0.x; v1 += q0.y; v2 += q1.x; v3 += q1.y;
            }
            if (OBF) {
                bf16* C = (bf16*)Cout;
                *(bf162*)&C[(size_t)r * N + c]       = __floats2bfloat162_rn(v0, v1);
                *(bf162*)&C[(size_t)(r + 8) * N + c] = __floats2bfloat162_rn(v2, v3);
            } else {
                float* C = (float*)Cout;
                *(float2*)&C[(size_t)r * N + c]       = make_float2(v0, v1);
                *(float2*)&C[(size_t)(r + 8) * N + c] = make_float2(v2, v3);
            }
        }
    }
}

// ---------------------------------------------------------------------------
// bf16 flash attention (HMMA). Block = (b,h) x 128-query tile, 8 warps
// (16 q each). K/V tiles of 64 keys shared by all 8 warps (halves L2 traffic
// vs Qtile=64). Softmax fp32 in registers; P stays in registers as PV A-op.
// ---------------------------------------------------------------------------
#define LQT 72
__global__ __launch_bounds__(256)
void flash_bf16(const bf16* __restrict__ qkv, const int* __restrict__ mask,
                bf16* __restrict__ attn)
{
    __shared__ __align__(16) bf16 Qs[128 * LQT];   // 18 KB
    __shared__ __align__(16) bf16 Ks[64 * LQT];    // 9 KB
    __shared__ __align__(16) bf16 Vs[64 * LQT];    // 9 KB
    __shared__ int msks[64];

    const int tid = threadIdx.x, wid = tid >> 5, lane = tid & 31;
    const int b = blockIdx.x >> 4, h = blockIdx.x & 15;
    const int q0 = blockIdx.y << 7;

    const bf16* qb = qkv + (size_t)(b * SS + q0) * NQKV + h * DHH;
    const bf16* kb = qkv + (size_t)b * SS * NQKV + HH * DHH + h * DHH;
    const bf16* vb = qkv + (size_t)b * SS * NQKV + 2 * HH * DHH + h * DHH;
    const int*  mrow = mask + b * SS;

#pragma unroll
    for (int i = 0; i < 4; i++) {                 // 128 rows x 8 chunks
        int e = i * 256 + tid, r = e >> 3, sg = e & 7;
        *(uint4*)&Qs[r * LQT + sg * 8] = *(const uint4*)&qb[(size_t)r * NQKV + sg * 8];
    }
    __syncthreads();

    uint32_t qf[4][4];
#pragma unroll
    for (int ks = 0; ks < 4; ks++) {
        uint32_t ad = su32(&Qs[(wid * 16 + (lane & 15)) * LQT + ks * 16 + (lane >> 4) * 8]);
        ldm4(qf[ks][0], qf[ks][1], qf[ks][2], qf[ks][3], ad);
    }

    float m0v = -1e30f, m1v = -1e30f, l0 = 0.0f, l1 = 0.0f;
    float o[8][4];
#pragma unroll
    for (int nf = 0; nf < 8; nf++)
#pragma unroll
        for (int e = 0; e < 4; e++) o[nf][e] = 0.0f;

    for (int kb0 = 0; kb0 < SS; kb0 += 64) {
        __syncthreads();
#pragma unroll
        for (int i = 0; i < 2; i++) {             // 64 rows x 8 chunks
            int e = i * 256 + tid, r = e >> 3, sg = e & 7;
            *(uint4*)&Ks[r * LQT + sg * 8] = *(const uint4*)&kb[(size_t)(kb0 + r) * NQKV + sg * 8];
            *(uint4*)&Vs[r * LQT + sg * 8] = *(const uint4*)&vb[(size_t)(kb0 + r) * NQKV + sg * 8];
        }
        if (tid < 64) msks[tid] = mrow[kb0 + tid];
        __syncthreads();

        float sv[8][4];
#pragma unroll
        for (int nf = 0; nf < 8; nf++)
#pragma unroll
            for (int e = 0; e < 4; e++) sv[nf][e] = 0.0f;

#pragma unroll
        for (int ks = 0; ks < 4; ks++) {
            uint32_t kf[8][2];
#pragma unroll
            for (int p = 0; p < 4; p++) {
                uint32_t bd = su32(&Ks[(p * 16 + (lane & 7) + ((lane >> 4) << 3)) * LQT +
                                       ks * 16 + ((lane >> 3) & 1) * 8]);
                ldm4(kf[2 * p][0], kf[2 * p][1], kf[2 * p + 1][0], kf[2 * p + 1][1], bd);
            }
#pragma unroll
            for (int nf = 0; nf < 8; nf++)
                mmabf(sv[nf], qf[ks], kf[nf][0], kf[nf][1]);
        }

        const int c2 = (lane & 3) * 2;
#pragma unroll
        for (int nf = 0; nf < 8; nf++) {
            int mk0 = msks[nf * 8 + c2], mk1 = msks[nf * 8 + c2 + 1];
            sv[nf][0] = mk0 ? -1e30f : sv[nf][0] * 0.125f;
            sv[nf][1] = mk1 ? -1e30f : sv[nf][1] * 0.125f;
            sv[nf][2] = mk0 ? -1e30f : sv[nf][2] * 0.125f;
            sv[nf][3] = mk1 ? -1e30f : sv[nf][3] * 0.125f;
        }

        float mx0 = -1e30f, mx1 = -1e30f;
#pragma unroll
        for (int nf = 0; nf < 8; nf++) {
            mx0 = fmaxf(mx0, fmaxf(sv[nf][0], sv[nf][1]));
            mx1 = fmaxf(mx1, fmaxf(sv[nf][2], sv[nf][3]));
        }
        mx0 = fmaxf(mx0, __shfl_xor_sync(0xffffffffu, mx0, 1));
        mx0 = fmaxf(mx0, __shfl_xor_sync(0xffffffffu, mx0, 2));
        mx1 = fmaxf(mx1, __shfl_xor_sync(0xffffffffu, mx1, 1));
        mx1 = fmaxf(mx1, __shfl_xor_sync(0xffffffffu, mx1, 2));

        float mn0 = fmaxf(m0v, mx0), mn1 = fmaxf(m1v, mx1);
        float al0 = __expf(m0v - mn0), al1 = __expf(m1v - mn1);
        m0v = mn0; m1v = mn1;

        float sum0 = 0.0f, sum1 = 0.0f;
#pragma unroll
        for (int nf = 0; nf < 8; nf++) {
            sv[nf][0] = __expf(sv[nf][0] - mn0);
            sv[nf][1] = __expf(sv[nf][1] - mn0);
            sv[nf][2] = __expf(sv[nf][2] - mn1);
            sv[nf][3] = __expf(sv[nf][3] - mn1);
            sum0 += sv[nf][0] + sv[nf][1];
            sum1 += sv[nf][2] + sv[nf][3];
        }
        sum0 += __shfl_xor_sync(0xffffffffu, sum0, 1);
        sum0 += __shfl_xor_sync(0xffffffffu, sum0, 2);
        sum1 += __shfl_xor_sync(0xffffffffu, sum1, 1);
        sum1 += __shfl_xor_sync(0xffffffffu, sum1, 2);
        l0 = l0 * al0 + sum0;
        l1 = l1 * al1 + sum1;
#pragma unroll
        for (int nf = 0; nf < 8; nf++) {
            o[nf][0] *= al0; o[nf][1] *= al0;
            o[nf][2] *= al1; o[nf][3] *= al1;
        }

#pragma unroll
        for (int ks = 0; ks < 4; ks++) {
            uint32_t pa[4];
            pa[0] = packbf(sv[2 * ks][0],     sv[2 * ks][1]);
            pa[1] = packbf(sv[2 * ks][2],     sv[2 * ks][3]);
            pa[2] = packbf(sv[2 * ks + 1][0], sv[2 * ks + 1][1]);
            pa[3] = packbf(sv[2 * ks + 1][2], sv[2 * ks + 1][3]);
#pragma unroll
            for (int p = 0; p < 4; p++) {
                uint32_t v0, v1, v2, v3;
                uint32_t vd = su32(&Vs[(ks * 16 + (lane & 7) + (((lane >> 3) & 1) << 3)) * LQT +
                                       p * 16 + ((lane >> 4) << 3)]);
                ldm4t(v0, v1, v2, v3, vd);
                mmabf(o[2 * p],     pa, v0, v1);
                mmabf(o[2 * p + 1], pa, v2, v3);
            }
        }
    }

    const float i0 = 1.0f / l0, i1 = 1.0f / l1;
    const int r0 = q0 + wid * 16 + (lane >> 2);
    bf16* ob = attn + (size_t)b * SS * DD + h * DHH;
#pragma unroll
    for (int nf = 0; nf < 8; nf++) {
        int c = nf * 8 + (lane & 3) * 2;
        *(bf162*)&ob[(size_t)r0 * DD + c] =
            __floats2bfloat162_rn(o[nf][0] * i0, o[nf][1] * i0);
        *(bf162*)&ob[(size_t)(r0 + 8) * DD + c] =
            __floats2bfloat162_rn(o[nf][2] * i1, o[nf][3] * i1);
    }
}

// ---------------------------------------------------------------------------
// LayerNorm: one block per row of 1024, 256 threads x float4.
// ---------------------------------------------------------------------------
__global__ __launch_bounds__(256)
void ln_kernel(const float* __restrict__ y, const float* __restrict__ gamma,
               const float* __restrict__ beta, float* __restrict__ out)
{
    __shared__ float red[16];
    const int row = blockIdx.x;
    const int tid = threadIdx.x;
    const float* yr = y + (size_t)row * DD;

    float4 v = *(const float4*)&yr[tid * 4];
    float s  = v.x + v.y + v.z + v.w;
    float s2 = v.x * v.x + v.y * v.y + v.z * v.z + v.w * v.w;
#pragma unroll
    for (int off = 16; off; off >>= 1) {
        s  += __shfl_xor_sync(0xffffffffu, s,  off);
        s2 += __shfl_xor_sync(0xffffffffu, s2, off);
    }
    const int w = tid >> 5;
    if ((tid & 31) == 0) { red[w] = s; red[w + 8] = s2; }
    __syncthreads();
    s = 0.0f; s2 = 0.0f;
#pragma unroll
    for (int i = 0; i < 8; i++) { s += red[i]; s2 += red[i + 8]; }

    const float mean = s * (1.0f / DD);
    const float var  = s2 * (1.0f / DD) - mean * mean;
    const float inv  = rsqrtf(var + 1e-5f);

    float4 g  = *(const float4*)&gamma[tid * 4];
    float4 bt = *(const float4*)&beta[tid * 4];
    float4 r;
    r.x = (v.x - mean) * inv * g.x + bt.x;
    r.y = (v.y - mean) * inv * g.y + bt.y;
    r.z = (v.z - mean) * inv * g.z + bt.z;
    r.w = (v.w - mean) * inv * g.w + bt.w;
    *(float4*)&out[(size_t)row * DD + tid * 4] = r;
}

// ---------------------------------------------------------------------------
extern "C" void kernel_launch(void* const* d_in, const int* in_sizes, int n_in,
                              void* d_out, int out_size)
{
    (void)in_sizes; (void)n_in; (void)out_size;
    const float* inp   = (const float*)d_in[0];
    const int*   mask  = (const int*)d_in[1];
    const float* Wqkv  = (const float*)d_in[2];
    const float* bqkv  = (const float*)d_in[3];
    const float* Wo    = (const float*)d_in[4];
    const float* gamma = (const float*)d_in[5];
    const float* beta  = (const float*)d_in[6];
    float* out = (float*)d_out;

    bf16 *inpb, *wqkvb, *wob, *qkvb, *attnb;
    float* y;
    cudaGetSymbolAddress((void**)&inpb,  g_inpb);
    cudaGetSymbolAddress((void**)&wqkvb, g_wqkvb);
    cudaGetSymbolAddress((void**)&wob,   g_wob);
    cudaGetSymbolAddress((void**)&qkvb,  g_qkvb);
    cudaGetSymbolAddress((void**)&attnb, g_attnb);
    cudaGetSymbolAddress((void**)&y,     g_y);

    // 0) fp32 -> bf16 conversions
    f2bf<<<(MTOK * DD) / 1024, 256>>>(inp,  inpb,  MTOK * DD);
    f2bf<<<(NQKV * DD) / 1024, 256>>>(Wqkv, wqkvb, NQKV * DD);
    f2bf<<<(DD * DD)   / 1024, 256>>>(Wo,   wob,   DD * DD);

    // 1) QKV = inp @ Wqkv^T + bqkv   -> bf16 [8192, 3072]
    hgemm_nt<true, false, true><<<dim3(NQKV / 128, MTOK / 128), 256>>>(
        inpb, wqkvb, bqkv, nullptr, qkvb, MTOK, NQKV, DD);

    // 2) attention -> bf16 [8192, 1024]
    flash_bf16<<<dim3(BB * HH, SS / 128), 256>>>(qkvb, mask, attnb);

    // 3) y = inp + attn @ Wo^T  -> fp32 [8192, 1024]
    hgemm_nt<false, true, false><<<dim3(DD / 128, MTOK / 128), 256>>>(
        attnb, wob, nullptr, inp, y, MTOK, DD, DD);

    // 4) out = LayerNorm(y)
    ln_kernel<<<MTOK, 256>>>(y, gamma, beta, out);
}

// round 8
// speedup vs baseline: 6.4136x; 1.0065x over previous
#include <cuda_runtime.h>
#include <cuda_bf16.h>
#include <cstdint>

#define BB   4
#define SS   2048
#define DD   1024
#define HH   16
#define DHH  64
#define MTOK (BB * SS)          // 8192
#define NQKV (3 * HH * DHH)     // 3072

typedef __nv_bfloat16  bf16;
typedef __nv_bfloat162 bf162;

// ---------------------------------------------------------------------------
// Scratch (static __device__ arrays; no allocation allowed)
// ---------------------------------------------------------------------------
__device__ bf16  g_inpb [(size_t)MTOK * DD];     // 16 MB
__device__ bf16  g_wqkvb[(size_t)NQKV * DD];     // 6 MB
__device__ bf16  g_wob  [(size_t)DD * DD];       // 2 MB
__device__ bf16  g_qkvb [(size_t)MTOK * NQKV];   // 48 MB
__device__ bf16  g_attnb[(size_t)MTOK * DD];     // 16 MB
__device__ float g_y    [(size_t)MTOK * DD];     // 32 MB

// ---------------------------------------------------------------------------
// Helpers: ldmatrix / mma.sync (sm_80 PTX) + cp.async
// ---------------------------------------------------------------------------
__device__ __forceinline__ uint32_t su32(const void* p) {
    return (uint32_t)__cvta_generic_to_shared(p);
}
__device__ __forceinline__ void ldm4(uint32_t& r0, uint32_t& r1, uint32_t& r2,
                                     uint32_t& r3, uint32_t a) {
    asm volatile("ldmatrix.sync.aligned.m8n8.x4.shared.b16 {%0,%1,%2,%3},[%4];\n"
                 : "=r"(r0), "=r"(r1), "=r"(r2), "=r"(r3) : "r"(a));
}
__device__ __forceinline__ void ldm4t(uint32_t& r0, uint32_t& r1, uint32_t& r2,
                                      uint32_t& r3, uint32_t a) {
    asm volatile("ldmatrix.sync.aligned.m8n8.x4.trans.shared.b16 {%0,%1,%2,%3},[%4];\n"
                 : "=r"(r0), "=r"(r1), "=r"(r2), "=r"(r3) : "r"(a));
}
__device__ __forceinline__ void mmabf(float* c, const uint32_t* a,
                                      uint32_t b0, uint32_t b1) {
    asm volatile(
        "mma.sync.aligned.m16n8k16.row.col.f32.bf16.bf16.f32 "
        "{%0,%1,%2,%3},{%4,%5,%6,%7},{%8,%9},{%0,%1,%2,%3};\n"
        : "+f"(c[0]), "+f"(c[1]), "+f"(c[2]), "+f"(c[3])
        : "r"(a[0]), "r"(a[1]), "r"(a[2]), "r"(a[3]), "r"(b0), "r"(b1));
}
__device__ __forceinline__ uint32_t packbf(float x, float y) {
    bf162 t = __floats2bfloat162_rn(x, y);
    return *reinterpret_cast<uint32_t*>(&t);
}
__device__ __forceinline__ void cpa16(uint32_t dst, const void* src) {
    asm volatile("cp.async.cg.shared.global [%0], [%1], 16;\n" :: "r"(dst), "l"(src));
}
#define CPCOMMIT() asm volatile("cp.async.commit_group;\n" ::: "memory")
#define CPWAIT(n)  asm volatile("cp.async.wait_group %0;\n" :: "n"(n) : "memory")

// ---------------------------------------------------------------------------
// fp32 -> bf16 conversion
// ---------------------------------------------------------------------------
__global__ void f2bf(const float* __restrict__ in, bf16* __restrict__ out, int n) {
    int i = (blockIdx.x * blockDim.x + threadIdx.x) * 4;
    if (i >= n) return;
    float4 v = *(const float4*)(in + i);
    bf162* o = (bf162*)(out + i);
    o[0] = __floats2bfloat162_rn(v.x, v.y);
    o[1] = __floats2bfloat162_rn(v.z, v.w);
}

// ---------------------------------------------------------------------------
// bf16 HGEMM (NT): C[M,N] = A[M,K] * W[N,K]^T (+bias fp32) (+res fp32)
// CTA tile 128x256, 8 warps (2 M x 4 N), warp tile 64x64 (MMA:LDSM = 4:1).
// K-chunk 64, 3-stage cp.async ring in dynamic smem (162 KB), one
// __syncthreads per chunk, 2 load-groups in flight (wait_group 1).
// smem rows: 64 bf16 + 8 pad = 72 (144 B) -> conflict-free ldmatrix.
// ---------------------------------------------------------------------------
#define GLD    72
#define A_SZ   (128 * GLD)            // bf16 elems per A stage
#define B_SZ   (256 * GLD)
#define STAGE_ELEMS (A_SZ + B_SZ)
#define GSMEM_BYTES (3 * STAGE_ELEMS * 2)   // 165888

template <bool BIAS, bool RES, bool OBF>
__global__ __launch_bounds__(256, 1)
void hgemm_nt(const bf16* __restrict__ A, const bf16* __restrict__ W,
              const float* __restrict__ bias, const float* __restrict__ res,
              void* __restrict__ Cout, int M, int N, int K)
{
    extern __shared__ __align__(16) bf16 smem[];

    const int tid  = threadIdx.x;
    const int wid  = tid >> 5, lane = tid & 31;
    const int m0   = blockIdx.y << 7;           // 128-row tile
    const int n0   = blockIdx.x << 8;           // 256-col tile
    const int wm   = (wid >> 2) << 6;           // 0 / 64
    const int wn   = (wid & 3) << 6;            // 0 / 64 / 128 / 192

    // cp.async mapping (chunk = 16B = 8 bf16): c -> row r=c>>3, seg sg=c&7
    const int r8 = tid >> 3, sg = tid & 7;

    float acc[4][8][4];
#pragma unroll
    for (int i = 0; i < 4; i++)
#pragma unroll
        for (int j = 0; j < 8; j++)
#pragma unroll
            for (int e = 0; e < 4; e++) acc[i][j][e] = 0.0f;

    const int nk = K >> 6;                      // 64-wide chunks

    auto load_stage = [&](int kt) {
        bf16* As = smem + (kt % 3) * STAGE_ELEMS;
        bf16* Bs = As + A_SZ;
        const int kofs = kt << 6;
#pragma unroll
        for (int i = 0; i < 4; i++) {           // A: 1024 chunks / 256 thr
            int r = r8 + i * 32;
            cpa16(su32(&As[r * GLD + sg * 8]),
                  &A[(size_t)(m0 + r) * K + kofs + sg * 8]);
        }
#pragma unroll
        for (int i = 0; i < 8; i++) {           // B: 2048 chunks / 256 thr
            int r = r8 + i * 32;
            cpa16(su32(&Bs[r * GLD + sg * 8]),
                  &W[(size_t)(n0 + r) * K + kofs + sg * 8]);
        }
        CPCOMMIT();
    };

    load_stage(0);
    load_stage(1);

    for (int kt = 0; kt < nk; kt++) {
        CPWAIT(1);                 // oldest group (stage kt) complete
        __syncthreads();           // visible to all; buf (kt-1)%3 free

        if (kt + 2 < nk) load_stage(kt + 2); else CPCOMMIT();

        const bf16* As = smem + (kt % 3) * STAGE_ELEMS;
        const bf16* Bs = As + A_SZ;

#pragma unroll
        for (int ks = 0; ks < 4; ks++) {
            uint32_t af[4][4], bfr[8][2];
#pragma unroll
            for (int mf = 0; mf < 4; mf++) {
                uint32_t ad = su32(&As[(wm + mf * 16 + (lane & 15)) * GLD +
                                       ks * 16 + (lane >> 4) * 8]);
                ldm4(af[mf][0], af[mf][1], af[mf][2], af[mf][3], ad);
            }
#pragma unroll
            for (int p = 0; p < 4; p++) {
                uint32_t bd = su32(&Bs[(wn + p * 16 + (lane & 7) + ((lane >> 4) << 3)) * GLD +
                                       ks * 16 + ((lane >> 3) & 1) * 8]);
                ldm4(bfr[2 * p][0], bfr[2 * p][1], bfr[2 * p + 1][0], bfr[2 * p + 1][1], bd);
            }
#pragma unroll
            for (int mf = 0; mf < 4; mf++)
#pragma unroll
                for (int nf = 0; nf < 8; nf++)
                    mmabf(acc[mf][nf], af[mf], bfr[nf][0], bfr[nf][1]);
        }
        __syncthreads();           // done reading stage kt
    }

    // Epilogue. acc c0,c1 -> (row r, cols c,c+1); c2,c3 -> (row r+8).
#pragma unroll
    for (int mf = 0; mf < 4; mf++) {
        const int r = m0 + wm + mf * 16 + (lane >> 2);
#pragma unroll
        for (int nf = 0; nf < 8; nf++) {
            const int c = n0 + wn + nf * 8 + (lane & 3) * 2;
            float v0 = acc[mf][nf][0], v1 = acc[mf][nf][1];
            float v2 = acc[mf][nf][2], v3 = acc[mf][nf][3];
            if (BIAS) {
                float b0v = bias[c], b1v = bias[c + 1];
                v0 += b0v; v1 += b1v; v2 += b0v; v3 += b1v;
            }
            if (RES) {
                float2 q0 = *(const float2*)&res[(size_t)r * N + c];
                float2 q1 = *(const float2*)&res[(size_t)(r + 8) * N + c];
                v0 += q0.x; v1 += q0.y; v2 += q1.x; v3 += q1.y;
            }
            if (OBF) {
                bf16* C = (bf16*)Cout;
                *(bf162*)&C[(size_t)r * N + c]       = __floats2bfloat162_rn(v0, v1);
                *(bf162*)&C[(size_t)(r + 8) * N + c] = __floats2bfloat162_rn(v2, v3);
            } else {
                float* C = (float*)Cout;
                *(float2*)&C[(size_t)r * N + c]       = make_float2(v0, v1);
                *(float2*)&C[(size_t)(r + 8) * N + c] = make_float2(v2, v3);
            }
        }
    }
}

// ---------------------------------------------------------------------------
// bf16 flash attention (HMMA). Block = (b,h) x 128-query tile, 8 warps
// (16 q each). K/V tiles of 64 keys shared by all 8 warps. Softmax fp32 in
// registers; P stays in registers as PV A-op. (unchanged from R7)
// ---------------------------------------------------------------------------
#define LQT 72
__global__ __launch_bounds__(256)
void flash_bf16(const bf16* __restrict__ qkv, const int* __restrict__ mask,
                bf16* __restrict__ attn)
{
    __shared__ __align__(16) bf16 Qs[128 * LQT];   // 18 KB
    __shared__ __align__(16) bf16 Ks[64 * LQT];    // 9 KB
    __shared__ __align__(16) bf16 Vs[64 * LQT];    // 9 KB
    __shared__ int msks[64];

    const int tid = threadIdx.x, wid = tid >> 5, lane = tid & 31;
    const int b = blockIdx.x >> 4, h = blockIdx.x & 15;
    const int q0 = blockIdx.y << 7;

    const bf16* qb = qkv + (size_t)(b * SS + q0) * NQKV + h * DHH;
    const bf16* kb = qkv + (size_t)b * SS * NQKV + HH * DHH + h * DHH;
    const bf16* vb = qkv + (size_t)b * SS * NQKV + 2 * HH * DHH + h * DHH;
    const int*  mrow = mask + b * SS;

#pragma unroll
    for (int i = 0; i < 4; i++) {
        int e = i * 256 + tid, r = e >> 3, sgq = e & 7;
        *(uint4*)&Qs[r * LQT + sgq * 8] = *(const uint4*)&qb[(size_t)r * NQKV + sgq * 8];
    }
    __syncthreads();

    uint32_t qf[4][4];
#pragma unroll
    for (int ks = 0; ks < 4; ks++) {
        uint32_t ad = su32(&Qs[(wid * 16 + (lane & 15)) * LQT + ks * 16 + (lane >> 4) * 8]);
        ldm4(qf[ks][0], qf[ks][1], qf[ks][2], qf[ks][3], ad);
    }

    float m0v = -1e30f, m1v = -1e30f, l0 = 0.0f, l1 = 0.0f;
    float o[8][4];
#pragma unroll
    for (int nf = 0; nf < 8; nf++)
#pragma unroll
        for (int e = 0; e < 4; e++) o[nf][e] = 0.0f;

    for (int kb0 = 0; kb0 < SS; kb0 += 64) {
        __syncthreads();
#pragma unroll
        for (int i = 0; i < 2; i++) {
            int e = i * 256 + tid, r = e >> 3, sgq = e & 7;
            *(uint4*)&Ks[r * LQT + sgq * 8] = *(const uint4*)&kb[(size_t)(kb0 + r) * NQKV + sgq * 8];
            *(uint4*)&Vs[r * LQT + sgq * 8] = *(const uint4*)&vb[(size_t)(kb0 + r) * NQKV + sgq * 8];
        }
        if (tid < 64) msks[tid] = mrow[kb0 + tid];
        __syncthreads();

        float sv[8][4];
#pragma unroll
        for (int nf = 0; nf < 8; nf++)
#pragma unroll
            for (int e = 0; e < 4; e++) sv[nf][e] = 0.0f;

#pragma unroll
        for (int ks = 0; ks < 4; ks++) {
            uint32_t kf[8][2];
#pragma unroll
            for (int p = 0; p < 4; p++) {
                uint32_t bd = su32(&Ks[(p * 16 + (lane & 7) + ((lane >> 4) << 3)) * LQT +
                                       ks * 16 + ((lane >> 3) & 1) * 8]);
                ldm4(kf[2 * p][0], kf[2 * p][1], kf[2 * p + 1][0], kf[2 * p + 1][1], bd);
            }
#pragma unroll
            for (int nf = 0; nf < 8; nf++)
                mmabf(sv[nf], qf[ks], kf[nf][0], kf[nf][1]);
        }

        const int c2 = (lane & 3) * 2;
#pragma unroll
        for (int nf = 0; nf < 8; nf++) {
            int mk0 = msks[nf * 8 + c2], mk1 = msks[nf * 8 + c2 + 1];
            sv[nf][0] = mk0 ? -1e30f : sv[nf][0] * 0.125f;
            sv[nf][1] = mk1 ? -1e30f : sv[nf][1] * 0.125f;
            sv[nf][2] = mk0 ? -1e30f : sv[nf][2] * 0.125f;
            sv[nf][3] = mk1 ? -1e30f : sv[nf][3] * 0.125f;
        }

        float mx0 = -1e30f, mx1 = -1e30f;
#pragma unroll
        for (int nf = 0; nf < 8; nf++) {
            mx0 = fmaxf(mx0, fmaxf(sv[nf][0], sv[nf][1]));
            mx1 = fmaxf(mx1, fmaxf(sv[nf][2], sv[nf][3]));
        }
        mx0 = fmaxf(mx0, __shfl_xor_sync(0xffffffffu, mx0, 1));
        mx0 = fmaxf(mx0, __shfl_xor_sync(0xffffffffu, mx0, 2));
        mx1 = fmaxf(mx1, __shfl_xor_sync(0xffffffffu, mx1, 1));
        mx1 = fmaxf(mx1, __shfl_xor_sync(0xffffffffu, mx1, 2));

        float mn0 = fmaxf(m0v, mx0), mn1 = fmaxf(m1v, mx1);
        float al0 = __expf(m0v - mn0), al1 = __expf(m1v - mn1);
        m0v = mn0; m1v = mn1;

        float sum0 = 0.0f, sum1 = 0.0f;
#pragma unroll
        for (int nf = 0; nf < 8; nf++) {
            sv[nf][0] = __expf(sv[nf][0] - mn0);
            sv[nf][1] = __expf(sv[nf][1] - mn0);
            sv[nf][2] = __expf(sv[nf][2] - mn1);
            sv[nf][3] = __expf(sv[nf][3] - mn1);
            sum0 += sv[nf][0] + sv[nf][1];
            sum1 += sv[nf][2] + sv[nf][3];
        }
        sum0 += __shfl_xor_sync(0xffffffffu, sum0, 1);
        sum0 += __shfl_xor_sync(0xffffffffu, sum0, 2);
        sum1 += __shfl_xor_sync(0xffffffffu, sum1, 1);
        sum1 += __shfl_xor_sync(0xffffffffu, sum1, 2);
        l0 = l0 * al0 + sum0;
        l1 = l1 * al1 + sum1;
#pragma unroll
        for (int nf = 0; nf < 8; nf++) {
            o[nf][0] *= al0; o[nf][1] *= al0;
            o[nf][2] *= al1; o[nf][3] *= al1;
        }

#pragma unroll
        for (int ks = 0; ks < 4; ks++) {
            uint32_t pa[4];
            pa[0] = packbf(sv[2 * ks][0],     sv[2 * ks][1]);
            pa[1] = packbf(sv[2 * ks][2],     sv[2 * ks][3]);
            pa[2] = packbf(sv[2 * ks + 1][0], sv[2 * ks + 1][1]);
            pa[3] = packbf(sv[2 * ks + 1][2], sv[2 * ks + 1][3]);
#pragma unroll
            for (int p = 0; p < 4; p++) {
                uint32_t v0, v1, v2, v3;
                uint32_t vd = su32(&Vs[(ks * 16 + (lane & 7) + (((lane >> 3) & 1) << 3)) * LQT +
                                       p * 16 + ((lane >> 4) << 3)]);
                ldm4t(v0, v1, v2, v3, vd);
                mmabf(o[2 * p],     pa, v0, v1);
                mmabf(o[2 * p + 1], pa, v2, v3);
            }
        }
    }

    const float i0 = 1.0f / l0, i1 = 1.0f / l1;
    const int r0 = q0 + wid * 16 + (lane >> 2);
    bf16* ob = attn + (size_t)b * SS * DD + h * DHH;
#pragma unroll
    for (int nf = 0; nf < 8; nf++) {
        int c = nf * 8 + (lane & 3) * 2;
        *(bf162*)&ob[(size_t)r0 * DD + c] =
            __floats2bfloat162_rn(o[nf][0] * i0, o[nf][1] * i0);
        *(bf162*)&ob[(size_t)(r0 + 8) * DD + c] =
            __floats2bfloat162_rn(o[nf][2] * i1, o[nf][3] * i1);
    }
}

// ---------------------------------------------------------------------------
// LayerNorm
// ---------------------------------------------------------------------------
__global__ __launch_bounds__(256)
void ln_kernel(const float* __restrict__ y, const float* __restrict__ gamma,
               const float* __restrict__ beta, float* __restrict__ out)
{
    __shared__ float red[16];
    const int row = blockIdx.x;
    const int tid = threadIdx.x;
    const float* yr = y + (size_t)row * DD;

    float4 v = *(const float4*)&yr[tid * 4];
    float s  = v.x + v.y + v.z + v.w;
    float s2 = v.x * v.x + v.y * v.y + v.z * v.z + v.w * v.w;
#pragma unroll
    for (int off = 16; off; off >>= 1) {
        s  += __shfl_xor_sync(0xffffffffu, s,  off);
        s2 += __shfl_xor_sync(0xffffffffu, s2, off);
    }
    const int w = tid >> 5;
    if ((tid & 31) == 0) { red[w] = s; red[w + 8] = s2; }
    __syncthreads();
    s = 0.0f; s2 = 0.0f;
#pragma unroll
    for (int i = 0; i < 8; i++) { s += red[i]; s2 += red[i + 8]; }

    const float mean = s * (1.0f / DD);
    const float var  = s2 * (1.0f / DD) - mean * mean;
    const float inv  = rsqrtf(var + 1e-5f);

    float4 g  = *(const float4*)&gamma[tid * 4];
    float4 bt = *(const float4*)&beta[tid * 4];
    float4 r;
    r.x = (v.x - mean) * inv * g.x + bt.x;
    r.y = (v.y - mean) * inv * g.y + bt.y;
    r.z = (v.z - mean) * inv * g.z + bt.z;
    r.w = (v.w - mean) * inv * g.w + bt.w;
    *(float4*)&out[(size_t)row * DD + tid * 4] = r;
}

// ---------------------------------------------------------------------------
extern "C" void kernel_launch(void* const* d_in, const int* in_sizes, int n_in,
                              void* d_out, int out_size)
{
    (void)in_sizes; (void)n_in; (void)out_size;
    const float* inp   = (const float*)d_in[0];
    const int*   mask  = (const int*)d_in[1];
    const float* Wqkv  = (const float*)d_in[2];
    const float* bqkv  = (const float*)d_in[3];
    const float* Wo    = (const float*)d_in[4];
    const float* gamma = (const float*)d_in[5];
    const float* beta  = (const float*)d_in[6];
    float* out = (float*)d_out;

    bf16 *inpb, *wqkvb, *wob, *qkvb, *attnb;
    float* y;
    cudaGetSymbolAddress((void**)&inpb,  g_inpb);
    cudaGetSymbolAddress((void**)&wqkvb, g_wqkvb);
    cudaGetSymbolAddress((void**)&wob,   g_wob);
    cudaGetSymbolAddress((void**)&qkvb,  g_qkvb);
    cudaGetSymbolAddress((void**)&attnb, g_attnb);
    cudaGetSymbolAddress((void**)&y,     g_y);

    // Dynamic smem opt-in (idempotent host-side attribute set; not a stream
    // op, not an allocation — safe under graph capture)
    cudaFuncSetAttribute(hgemm_nt<true, false, true>,
                         cudaFuncAttributeMaxDynamicSharedMemorySize, GSMEM_BYTES);
    cudaFuncSetAttribute(hgemm_nt<false, true, false>,
                         cudaFuncAttributeMaxDynamicSharedMemorySize, GSMEM_BYTES);

    // 0) fp32 -> bf16 conversions
    f2bf<<<(MTOK * DD) / 1024, 256>>>(inp,  inpb,  MTOK * DD);
    f2bf<<<(NQKV * DD) / 1024, 256>>>(Wqkv, wqkvb, NQKV * DD);
    f2bf<<<(DD * DD)   / 1024, 256>>>(Wo,   wob,   DD * DD);

    // 1) QKV = inp @ Wqkv^T + bqkv   -> bf16 [8192, 3072]
    hgemm_nt<true, false, true><<<dim3(NQKV / 256, MTOK / 128), 256, GSMEM_BYTES>>>(
        inpb, wqkvb, bqkv, nullptr, qkvb, MTOK, NQKV, DD);

    // 2) attention -> bf16 [8192, 1024]
    flash_bf16<<<dim3(BB * HH, SS / 128), 256>>>(qkvb, mask, attnb);

    // 3) y = inp + attn @ Wo^T  -> fp32 [8192, 1024]
    hgemm_nt<false, true, false><<<dim3(DD / 256, MTOK / 128), 256, GSMEM_BYTES>>>(
        attnb, wob, nullptr, inp, y, MTOK, DD, DD);

    // 4) out = LayerNorm(y)
    ln_kernel<<<MTOK, 256>>>(y, gamma, beta, out);
}

// round 9
// speedup vs baseline: 7.9333x; 1.2369x over previous
#include <cuda_runtime.h>
#include <cuda_bf16.h>
#include <cstdint>

#define BB   4
#define SS   2048
#define DD   1024
#define HH   16
#define DHH  64
#define MTOK (BB * SS)          // 8192
#define NQKV (3 * HH * DHH)     // 3072

typedef __nv_bfloat16  bf16;
typedef __nv_bfloat162 bf162;

// ---------------------------------------------------------------------------
// Scratch (static __device__ arrays; no allocation allowed)
// ---------------------------------------------------------------------------
__device__ bf16  g_inpb [(size_t)MTOK * DD];     // 16 MB
__device__ bf16  g_wqkvb[(size_t)NQKV * DD];     // 6 MB
__device__ bf16  g_wob  [(size_t)DD * DD];       // 2 MB
__device__ bf16  g_qkvb [(size_t)MTOK * NQKV];   // 48 MB
__device__ bf16  g_kc   [(size_t)MTOK * DD];     // 16 MB compact K
__device__ bf16  g_vc   [(size_t)MTOK * DD];     // 16 MB compact V
__device__ bf16  g_attnb[(size_t)MTOK * DD];     // 16 MB
__device__ float g_y    [(size_t)MTOK * DD];     // 32 MB
__device__ int   g_idx  [BB * SS];
__device__ int   g_cnt  [BB];

// ---------------------------------------------------------------------------
// Helpers: ldmatrix / mma.sync (sm_80 PTX) + cp.async
// ---------------------------------------------------------------------------
__device__ __forceinline__ uint32_t su32(const void* p) {
    return (uint32_t)__cvta_generic_to_shared(p);
}
__device__ __forceinline__ void ldm4(uint32_t& r0, uint32_t& r1, uint32_t& r2,
                                     uint32_t& r3, uint32_t a) {
    asm volatile("ldmatrix.sync.aligned.m8n8.x4.shared.b16 {%0,%1,%2,%3},[%4];\n"
                 : "=r"(r0), "=r"(r1), "=r"(r2), "=r"(r3) : "r"(a));
}
__device__ __forceinline__ void ldm4t(uint32_t& r0, uint32_t& r1, uint32_t& r2,
                                      uint32_t& r3, uint32_t a) {
    asm volatile("ldmatrix.sync.aligned.m8n8.x4.trans.shared.b16 {%0,%1,%2,%3},[%4];\n"
                 : "=r"(r0), "=r"(r1), "=r"(r2), "=r"(r3) : "r"(a));
}
__device__ __forceinline__ void mmabf(float* c, const uint32_t* a,
                                      uint32_t b0, uint32_t b1) {
    asm volatile(
        "mma.sync.aligned.m16n8k16.row.col.f32.bf16.bf16.f32 "
        "{%0,%1,%2,%3},{%4,%5,%6,%7},{%8,%9},{%0,%1,%2,%3};\n"
        : "+f"(c[0]), "+f"(c[1]), "+f"(c[2]), "+f"(c[3])
        : "r"(a[0]), "r"(a[1]), "r"(a[2]), "r"(a[3]), "r"(b0), "r"(b1));
}
__device__ __forceinline__ uint32_t packbf(float x, float y) {
    bf162 t = __floats2bfloat162_rn(x, y);
    return *reinterpret_cast<uint32_t*>(&t);
}
__device__ __forceinline__ void cpa16(uint32_t dst, const void* src) {
    asm volatile("cp.async.cg.shared.global [%0], [%1], 16;\n" :: "r"(dst), "l"(src));
}
#define CPCOMMIT() asm volatile("cp.async.commit_group;\n" ::: "memory")
#define CPWAIT(n)  asm volatile("cp.async.wait_group %0;\n" :: "n"(n) : "memory")

// ---------------------------------------------------------------------------
// fp32 -> bf16 conversion
// ---------------------------------------------------------------------------
__global__ void f2bf(const float* __restrict__ in, bf16* __restrict__ out, int n) {
    int i = (blockIdx.x * blockDim.x + threadIdx.x) * 4;
    if (i >= n) return;
    float4 v = *(const float4*)(in + i);
    bf162* o = (bf162*)(out + i);
    o[0] = __floats2bfloat162_rn(v.x, v.y);
    o[1] = __floats2bfloat162_rn(v.z, v.w);
}

// ---------------------------------------------------------------------------
// Key compaction: per batch, ordered list of unmasked key indices + count.
// One block (256 thr x 8 elems) per batch; deterministic prefix scan.
// ---------------------------------------------------------------------------
__global__ void compact_k(const int* __restrict__ mask, int* __restrict__ idx,
                          int* __restrict__ cnt)
{
    const int b = blockIdx.x, tid = threadIdx.x;
    const int lane = tid & 31, wid = tid >> 5;
    const int* mrow = mask + b * SS;
    __shared__ int ws[8];

    int lm[8], local = 0;
#pragma unroll
    for (int i = 0; i < 8; i++) { lm[i] = (mrow[tid * 8 + i] == 0); local += lm[i]; }

    int inc = local;
#pragma unroll
    for (int off = 1; off < 32; off <<= 1) {
        int n = __shfl_up_sync(0xffffffffu, inc, off);
        if (lane >= off) inc += n;
    }
    if (lane == 31) ws[wid] = inc;
    __syncthreads();
    if (tid == 0) {
        int run = 0;
#pragma unroll
        for (int w = 0; w < 8; w++) { int t = ws[w]; ws[w] = run; run += t; }
        cnt[b] = run;
    }
    __syncthreads();

    int pos = ws[wid] + inc - local;
#pragma unroll
    for (int i = 0; i < 8; i++)
        if (lm[i]) { idx[b * SS + pos] = tid * 8 + i; pos++; }
}

// ---------------------------------------------------------------------------
// Gather compact K/V rows (all heads, 1024 bf16/row) from qkv; zero-pad to
// the next 64-multiple. Grid (BB, SS/64), 256 threads.
// ---------------------------------------------------------------------------
__global__ void gather_kv(const bf16* __restrict__ qkv, const int* __restrict__ idx,
                          const int* __restrict__ cnt, bf16* __restrict__ kc,
                          bf16* __restrict__ vc)
{
    const int b = blockIdx.x, j0 = blockIdx.y << 6, tid = threadIdx.x;
    const int c_ = cnt[b];
    const int padded = (c_ + 63) & ~63;
    if (j0 >= padded) return;

#pragma unroll
    for (int i = 0; i < 32; i++) {          // 64 rows x 128 16B-chunks
        int e = i * 256 + tid;
        int r = e >> 7, cc = e & 127;
        int j = j0 + r;
        uint4 kv = make_uint4(0, 0, 0, 0), vv = make_uint4(0, 0, 0, 0);
        if (j < c_) {
            int s = idx[b * SS + j];
            const bf16* base = qkv + (size_t)(b * SS + s) * NQKV;
            kv = *(const uint4*)(base + DD + cc * 8);
            vv = *(const uint4*)(base + 2 * DD + cc * 8);
        }
        *(uint4*)&kc[(size_t)(b * SS + j) * DD + cc * 8] = kv;
        *(uint4*)&vc[(size_t)(b * SS + j) * DD + cc * 8] = vv;
    }
}

// ---------------------------------------------------------------------------
// bf16 HGEMM (NT): C[M,N] = A[M,K] * W[N,K]^T (+bias fp32) (+res fp32)
// CTA tile 128x256, 8 warps (2 M x 4 N), warp tile 64x64.
// K-chunk 64, 3-stage cp.async ring (162 KB dynamic smem). (R8 state)
// ---------------------------------------------------------------------------
#define GLD    72
#define A_SZ   (128 * GLD)
#define B_SZ   (256 * GLD)
#define STAGE_ELEMS (A_SZ + B_SZ)
#define GSMEM_BYTES (3 * STAGE_ELEMS * 2)   // 165888

template <bool BIAS, bool RES, bool OBF>
__global__ __launch_bounds__(256, 1)
void hgemm_nt(const bf16* __restrict__ A, const bf16* __restrict__ W,
              const float* __restrict__ bias, const float* __restrict__ res,
              void* __restrict__ Cout, int M, int N, int K)
{
    extern __shared__ __align__(16) bf16 smem[];

    const int tid  = threadIdx.x;
    const int wid  = tid >> 5, lane = tid & 31;
    const int m0   = blockIdx.y << 7;
    const int n0   = blockIdx.x << 8;
    const int wm   = (wid >> 2) << 6;
    const int wn   = (wid & 3) << 6;
    const int r8 = tid >> 3, sg = tid & 7;

    float acc[4][8][4];
#pragma unroll
    for (int i = 0; i < 4; i++)
#pragma unroll
        for (int j = 0; j < 8; j++)
#pragma unroll
            for (int e = 0; e < 4; e++) acc[i][j][e] = 0.0f;

    const int nk = K >> 6;

    auto load_stage = [&](int kt) {
        bf16* As = smem + (kt % 3) * STAGE_ELEMS;
        bf16* Bs = As + A_SZ;
        const int kofs = kt << 6;
#pragma unroll
        for (int i = 0; i < 4; i++) {
            int r = r8 + i * 32;
            cpa16(su32(&As[r * GLD + sg * 8]),
                  &A[(size_t)(m0 + r) * K + kofs + sg * 8]);
        }
#pragma unroll
        for (int i = 0; i < 8; i++) {
            int r = r8 + i * 32;
            cpa16(su32(&Bs[r * GLD + sg * 8]),
                  &W[(size_t)(n0 + r) * K + kofs + sg * 8]);
        }
        CPCOMMIT();
    };

    load_stage(0);
    load_stage(1);

    for (int kt = 0; kt < nk; kt++) {
        CPWAIT(1);
        __syncthreads();

        if (kt + 2 < nk) load_stage(kt + 2); else CPCOMMIT();

        const bf16* As = smem + (kt % 3) * STAGE_ELEMS;
        const bf16* Bs = As + A_SZ;

#pragma unroll
        for (int ks = 0; ks < 4; ks++) {
            uint32_t af[4][4], bfr[8][2];
#pragma unroll
            for (int mf = 0; mf < 4; mf++) {
                uint32_t ad = su32(&As[(wm + mf * 16 + (lane & 15)) * GLD +
                                       ks * 16 + (lane >> 4) * 8]);
                ldm4(af[mf][0], af[mf][1], af[mf][2], af[mf][3], ad);
            }
#pragma unroll
            for (int p = 0; p < 4; p++) {
                uint32_t bd = su32(&Bs[(wn + p * 16 + (lane & 7) + ((lane >> 4) << 3)) * GLD +
                                       ks * 16 + ((lane >> 3) & 1) * 8]);
                ldm4(bfr[2 * p][0], bfr[2 * p][1], bfr[2 * p + 1][0], bfr[2 * p + 1][1], bd);
            }
#pragma unroll
            for (int mf = 0; mf < 4; mf++)
#pragma unroll
                for (int nf = 0; nf < 8; nf++)
                    mmabf(acc[mf][nf], af[mf], bfr[nf][0], bfr[nf][1]);
        }
        __syncthreads();
    }

#pragma unroll
    for (int mf = 0; mf < 4; mf++) {
        const int r = m0 + wm + mf * 16 + (lane >> 2);
#pragma unroll
        for (int nf = 0; nf < 8; nf++) {
            const int c = n0 + wn + nf * 8 + (lane & 3) * 2;
            float v0 = acc[mf][nf][0], v1 = acc[mf][nf][1];
            float v2 = acc[mf][nf][2], v3 = acc[mf][nf][3];
            if (BIAS) {
                float b0v = bias[c], b1v = bias[c + 1];
                v0 += b0v; v1 += b1v; v2 += b0v; v3 += b1v;
            }
            if (RES) {
                float2 q0 = *(const float2*)&res[(size_t)r * N + c];
                float2 q1 = *(const float2*)&res[(size_t)(r + 8) * N + c];
                v0 += q0.x; v1 += q0.y; v2 += q1.x; v3 += q1.y;
            }
            if (OBF) {
                bf16* C = (bf16*)Cout;
                *(bf162*)&C[(size_t)r * N + c]       = __floats2bfloat162_rn(v0, v1);
                *(bf162*)&C[(size_t)(r + 8) * N + c] = __floats2bfloat162_rn(v2, v3);
            } else {
                float* C = (float*)Cout;
                *(float2*)&C[(size_t)r * N + c]       = make_float2(v0, v1);
                *(float2*)&C[(size_t)(r + 8) * N + c] = make_float2(v2, v3);
            }
        }
    }
}

// ---------------------------------------------------------------------------
// bf16 flash attention over COMPACTED keys. Block = (b,h) x 128-query tile,
// 8 warps. Loops ceil(cnt/64) key tiles (~half of S); tail masked by
// kidx >= cnt compare (no mask array reads).
// ---------------------------------------------------------------------------
#define LQT 72
__global__ __launch_bounds__(256)
void flash_bf16(const bf16* __restrict__ qkv, const bf16* __restrict__ kc,
                const bf16* __restrict__ vc, const int* __restrict__ cnt,
                bf16* __restrict__ attn)
{
    __shared__ __align__(16) bf16 Qs[128 * LQT];   // 18 KB
    __shared__ __align__(16) bf16 Ks[64 * LQT];    // 9 KB
    __shared__ __align__(16) bf16 Vs[64 * LQT];    // 9 KB

    const int tid = threadIdx.x, wid = tid >> 5, lane = tid & 31;
    const int b = blockIdx.x >> 4, h = blockIdx.x & 15;
    const int q0 = blockIdx.y << 7;

    const int c_ = cnt[b];
    const int padded = (c_ + 63) & ~63;

    const bf16* qb  = qkv + (size_t)(b * SS + q0) * NQKV + h * DHH;
    const bf16* kcb = kc + (size_t)b * SS * DD + h * DHH;
    const bf16* vcb = vc + (size_t)b * SS * DD + h * DHH;

#pragma unroll
    for (int i = 0; i < 4; i++) {
        int e = i * 256 + tid, r = e >> 3, sgq = e & 7;
        *(uint4*)&Qs[r * LQT + sgq * 8] = *(const uint4*)&qb[(size_t)r * NQKV + sgq * 8];
    }
    __syncthreads();

    uint32_t qf[4][4];
#pragma unroll
    for (int ks = 0; ks < 4; ks++) {
        uint32_t ad = su32(&Qs[(wid * 16 + (lane & 15)) * LQT + ks * 16 + (lane >> 4) * 8]);
        ldm4(qf[ks][0], qf[ks][1], qf[ks][2], qf[ks][3], ad);
    }

    float m0v = -1e30f, m1v = -1e30f, l0 = 0.0f, l1 = 0.0f;
    float o[8][4];
#pragma unroll
    for (int nf = 0; nf < 8; nf++)
#pragma unroll
        for (int e = 0; e < 4; e++) o[nf][e] = 0.0f;

    for (int kb0 = 0; kb0 < padded; kb0 += 64) {
        __syncthreads();
#pragma unroll
        for (int i = 0; i < 2; i++) {
            int e = i * 256 + tid, r = e >> 3, sgq = e & 7;
            *(uint4*)&Ks[r * LQT + sgq * 8] = *(const uint4*)&kcb[(size_t)(kb0 + r) * DD + sgq * 8];
            *(uint4*)&Vs[r * LQT + sgq * 8] = *(const uint4*)&vcb[(size_t)(kb0 + r) * DD + sgq * 8];
        }
        __syncthreads();

        float sv[8][4];
#pragma unroll
        for (int nf = 0; nf < 8; nf++)
#pragma unroll
            for (int e = 0; e < 4; e++) sv[nf][e] = 0.0f;

#pragma unroll
        for (int ks = 0; ks < 4; ks++) {
            uint32_t kf[8][2];
#pragma unroll
            for (int p = 0; p < 4; p++) {
                uint32_t bd = su32(&Ks[(p * 16 + (lane & 7) + ((lane >> 4) << 3)) * LQT +
                                       ks * 16 + ((lane >> 3) & 1) * 8]);
                ldm4(kf[2 * p][0], kf[2 * p][1], kf[2 * p + 1][0], kf[2 * p + 1][1], bd);
            }
#pragma unroll
            for (int nf = 0; nf < 8; nf++)
                mmabf(sv[nf], qf[ks], kf[nf][0], kf[nf][1]);
        }

        // scale + tail-tile validity (key slot >= cnt -> -1e30)
        const int c2 = (lane & 3) * 2;
#pragma unroll
        for (int nf = 0; nf < 8; nf++) {
            int kidx = kb0 + nf * 8 + c2;
            bool v0 = kidx < c_, v1 = (kidx + 1) < c_;
            sv[nf][0] = v0 ? sv[nf][0] * 0.125f : -1e30f;
            sv[nf][1] = v1 ? sv[nf][1] * 0.125f : -1e30f;
            sv[nf][2] = v0 ? sv[nf][2] * 0.125f : -1e30f;
            sv[nf][3] = v1 ? sv[nf][3] * 0.125f : -1e30f;
        }

        float mx0 = -1e30f, mx1 = -1e30f;
#pragma unroll
        for (int nf = 0; nf < 8; nf++) {
            mx0 = fmaxf(mx0, fmaxf(sv[nf][0], sv[nf][1]));
            mx1 = fmaxf(mx1, fmaxf(sv[nf][2], sv[nf][3]));
        }
        mx0 = fmaxf(mx0, __shfl_xor_sync(0xffffffffu, mx0, 1));
        mx0 = fmaxf(mx0, __shfl_xor_sync(0xffffffffu, mx0, 2));
        mx1 = fmaxf(mx1, __shfl_xor_sync(0xffffffffu, mx1, 1));
        mx1 = fmaxf(mx1, __shfl_xor_sync(0xffffffffu, mx1, 2));

        float mn0 = fmaxf(m0v, mx0), mn1 = fmaxf(m1v, mx1);
        float al0 = __expf(m0v - mn0), al1 = __expf(m1v - mn1);
        m0v = mn0; m1v = mn1;

        float sum0 = 0.0f, sum1 = 0.0f;
#pragma unroll
        for (int nf = 0; nf < 8; nf++) {
            sv[nf][0] = __expf(sv[nf][0] - mn0);
            sv[nf][1] = __expf(sv[nf][1] - mn0);
            sv[nf][2] = __expf(sv[nf][2] - mn1);
            sv[nf][3] = __expf(sv[nf][3] - mn1);
            sum0 += sv[nf][0] + sv[nf][1];
            sum1 += sv[nf][2] + sv[nf][3];
        }
        sum0 += __shfl_xor_sync(0xffffffffu, sum0, 1);
        sum0 += __shfl_xor_sync(0xffffffffu, sum0, 2);
        sum1 += __shfl_xor_sync(0xffffffffu, sum1, 1);
        sum1 += __shfl_xor_sync(0xffffffffu, sum1, 2);
        l0 = l0 * al0 + sum0;
        l1 = l1 * al1 + sum1;
#pragma unroll
        for (int nf = 0; nf < 8; nf++) {
            o[nf][0] *= al0; o[nf][1] *= al0;
            o[nf][2] *= al1; o[nf][3] *= al1;
        }

#pragma unroll
        for (int ks = 0; ks < 4; ks++) {
            uint32_t pa[4];
            pa[0] = packbf(sv[2 * ks][0],     sv[2 * ks][1]);
            pa[1] = packbf(sv[2 * ks][2],     sv[2 * ks][3]);
            pa[2] = packbf(sv[2 * ks + 1][0], sv[2 * ks + 1][1]);
            pa[3] = packbf(sv[2 * ks + 1][2], sv[2 * ks + 1][3]);
#pragma unroll
            for (int p = 0; p < 4; p++) {
                uint32_t v0, v1, v2, v3;
                uint32_t vd = su32(&Vs[(ks * 16 + (lane & 7) + (((lane >> 3) & 1) << 3)) * LQT +
                                       p * 16 + ((lane >> 4) << 3)]);
                ldm4t(v0, v1, v2, v3, vd);
                mmabf(o[2 * p],     pa, v0, v1);
                mmabf(o[2 * p + 1], pa, v2, v3);
            }
        }
    }

    const float i0 = 1.0f / l0, i1 = 1.0f / l1;
    const int r0 = q0 + wid * 16 + (lane >> 2);
    bf16* ob = attn + (size_t)b * SS * DD + h * DHH;
#pragma unroll
    for (int nf = 0; nf < 8; nf++) {
        int c = nf * 8 + (lane & 3) * 2;
        *(bf162*)&ob[(size_t)r0 * DD + c] =
            __floats2bfloat162_rn(o[nf][0] * i0, o[nf][1] * i0);
        *(bf162*)&ob[(size_t)(r0 + 8) * DD + c] =
            __floats2bfloat162_rn(o[nf][2] * i1, o[nf][3] * i1);
    }
}

// ---------------------------------------------------------------------------
// LayerNorm
// ---------------------------------------------------------------------------
__global__ __launch_bounds__(256)
void ln_kernel(const float* __restrict__ y, const float* __restrict__ gamma,
               const float* __restrict__ beta, float* __restrict__ out)
{
    __shared__ float red[16];
    const int row = blockIdx.x;
    const int tid = threadIdx.x;
    const float* yr = y + (size_t)row * DD;

    float4 v = *(const float4*)&yr[tid * 4];
    float s  = v.x + v.y + v.z + v.w;
    float s2 = v.x * v.x + v.y * v.y + v.z * v.z + v.w * v.w;
#pragma unroll
    for (int off = 16; off; off >>= 1) {
        s  += __shfl_xor_sync(0xffffffffu, s,  off);
        s2 += __shfl_xor_sync(0xffffffffu, s2, off);
    }
    const int w = tid >> 5;
    if ((tid & 31) == 0) { red[w] = s; red[w + 8] = s2; }
    __syncthreads();
    s = 0.0f; s2 = 0.0f;
#pragma unroll
    for (int i = 0; i < 8; i++) { s += red[i]; s2 += red[i + 8]; }

    const float mean = s * (1.0f / DD);
    const float var  = s2 * (1.0f / DD) - mean * mean;
    const float inv  = rsqrtf(var + 1e-5f);

    float4 g  = *(const float4*)&gamma[tid * 4];
    float4 bt = *(const float4*)&beta[tid * 4];
    float4 r;
    r.x = (v.x - mean) * inv * g.x + bt.x;
    r.y = (v.y - mean) * inv * g.y + bt.y;
    r.z = (v.z - mean) * inv * g.z + bt.z;
    r.w = (v.w - mean) * inv * g.w + bt.w;
    *(float4*)&out[(size_t)row * DD + tid * 4] = r;
}

// ---------------------------------------------------------------------------
extern "C" void kernel_launch(void* const* d_in, const int* in_sizes, int n_in,
                              void* d_out, int out_size)
{
    (void)in_sizes; (void)n_in; (void)out_size;
    const float* inp   = (const float*)d_in[0];
    const int*   mask  = (const int*)d_in[1];
    const float* Wqkv  = (const float*)d_in[2];
    const float* bqkv  = (const float*)d_in[3];
    const float* Wo    = (const float*)d_in[4];
    const float* gamma = (const float*)d_in[5];
    const float* beta  = (const float*)d_in[6];
    float* out = (float*)d_out;

    bf16 *inpb, *wqkvb, *wob, *qkvb, *kc, *vc, *attnb;
    float* y;
    int *idx, *cnt;
    cudaGetSymbolAddress((void**)&inpb,  g_inpb);
    cudaGetSymbolAddress((void**)&wqkvb, g_wqkvb);
    cudaGetSymbolAddress((void**)&wob,   g_wob);
    cudaGetSymbolAddress((void**)&qkvb,  g_qkvb);
    cudaGetSymbolAddress((void**)&kc,    g_kc);
    cudaGetSymbolAddress((void**)&vc,    g_vc);
    cudaGetSymbolAddress((void**)&attnb, g_attnb);
    cudaGetSymbolAddress((void**)&y,     g_y);
    cudaGetSymbolAddress((void**)&idx,   g_idx);
    cudaGetSymbolAddress((void**)&cnt,   g_cnt);

    cudaFuncSetAttribute(hgemm_nt<true, false, true>,
                         cudaFuncAttributeMaxDynamicSharedMemorySize, GSMEM_BYTES);
    cudaFuncSetAttribute(hgemm_nt<false, true, false>,
                         cudaFuncAttributeMaxDynamicSharedMemorySize, GSMEM_BYTES);

    // 0) conversions + key compaction index
    f2bf<<<(MTOK * DD) / 1024, 256>>>(inp,  inpb,  MTOK * DD);
    f2bf<<<(NQKV * DD) / 1024, 256>>>(Wqkv, wqkvb, NQKV * DD);
    f2bf<<<(DD * DD)   / 1024, 256>>>(Wo,   wob,   DD * DD);
    compact_k<<<BB, 256>>>(mask, idx, cnt);

    // 1) QKV = inp @ Wqkv^T + bqkv   -> bf16 [8192, 3072]
    hgemm_nt<true, false, true><<<dim3(NQKV / 256, MTOK / 128), 256, GSMEM_BYTES>>>(
        inpb, wqkvb, bqkv, nullptr, qkvb, MTOK, NQKV, DD);

    // 2) gather compacted K/V, then attention over ~cnt keys
    gather_kv<<<dim3(BB, SS / 64), 256>>>(qkvb, idx, cnt, kc, vc);
    flash_bf16<<<dim3(BB * HH, SS / 128), 256>>>(qkvb, kc, vc, cnt, attnb);

    // 3) y = inp + attn @ Wo^T  -> fp32 [8192, 1024]
    hgemm_nt<false, true, false><<<dim3(DD / 256, MTOK / 128), 256, GSMEM_BYTES>>>(
        attnb, wob, nullptr, inp, y, MTOK, DD, DD);

    // 4) out = LayerNorm(y)
    ln_kernel<<<MTOK, 256>>>(y, gamma, beta, out);
}

// round 10
// speedup vs baseline: 9.4293x; 1.1886x over previous
#include <cuda_runtime.h>
#include <cuda_bf16.h>
#include <cstdint>

#define BB   4
#define SS   2048
#define DD   1024
#define HH   16
#define DHH  64
#define MTOK (BB * SS)          // 8192
#define NQKV (3 * HH * DHH)     // 3072

typedef __nv_bfloat16  bf16;
typedef __nv_bfloat162 bf162;

// ---------------------------------------------------------------------------
// Scratch (static __device__ arrays; no allocation allowed)
// ---------------------------------------------------------------------------
__device__ bf16  g_inpb [(size_t)MTOK * DD];     // 16 MB
__device__ bf16  g_wqkvb[(size_t)NQKV * DD];     // 6 MB
__device__ bf16  g_wob  [(size_t)DD * DD];       // 2 MB
__device__ bf16  g_qb   [(size_t)MTOK * DD];     // 16 MB  Q projections
__device__ bf16  g_kc   [(size_t)MTOK * DD];     // 16 MB  compact K
__device__ bf16  g_vc   [(size_t)MTOK * DD];     // 16 MB  compact V
__device__ bf16  g_attnb[(size_t)MTOK * DD];     // 16 MB
__device__ float g_y    [(size_t)MTOK * DD];     // 32 MB
__device__ int   g_idx  [BB * SS];
__device__ int   g_cnt  [BB];

// ---------------------------------------------------------------------------
// Helpers: ldmatrix / mma.sync (sm_80 PTX) + cp.async
// ---------------------------------------------------------------------------
__device__ __forceinline__ uint32_t su32(const void* p) {
    return (uint32_t)__cvta_generic_to_shared(p);
}
__device__ __forceinline__ void ldm4(uint32_t& r0, uint32_t& r1, uint32_t& r2,
                                     uint32_t& r3, uint32_t a) {
    asm volatile("ldmatrix.sync.aligned.m8n8.x4.shared.b16 {%0,%1,%2,%3},[%4];\n"
                 : "=r"(r0), "=r"(r1), "=r"(r2), "=r"(r3) : "r"(a));
}
__device__ __forceinline__ void ldm4t(uint32_t& r0, uint32_t& r1, uint32_t& r2,
                                      uint32_t& r3, uint32_t a) {
    asm volatile("ldmatrix.sync.aligned.m8n8.x4.trans.shared.b16 {%0,%1,%2,%3},[%4];\n"
                 : "=r"(r0), "=r"(r1), "=r"(r2), "=r"(r3) : "r"(a));
}
__device__ __forceinline__ void mmabf(float* c, const uint32_t* a,
                                      uint32_t b0, uint32_t b1) {
    asm volatile(
        "mma.sync.aligned.m16n8k16.row.col.f32.bf16.bf16.f32 "
        "{%0,%1,%2,%3},{%4,%5,%6,%7},{%8,%9},{%0,%1,%2,%3};\n"
        : "+f"(c[0]), "+f"(c[1]), "+f"(c[2]), "+f"(c[3])
        : "r"(a[0]), "r"(a[1]), "r"(a[2]), "r"(a[3]), "r"(b0), "r"(b1));
}
__device__ __forceinline__ uint32_t packbf(float x, float y) {
    bf162 t = __floats2bfloat162_rn(x, y);
    return *reinterpret_cast<uint32_t*>(&t);
}
__device__ __forceinline__ void cpa16(uint32_t dst, const void* src) {
    asm volatile("cp.async.cg.shared.global [%0], [%1], 16;\n" :: "r"(dst), "l"(src));
}
#define CPCOMMIT() asm volatile("cp.async.commit_group;\n" ::: "memory")
#define CPWAIT(n)  asm volatile("cp.async.wait_group %0;\n" :: "n"(n) : "memory")

// ---------------------------------------------------------------------------
// fp32 -> bf16 conversion
// ---------------------------------------------------------------------------
__global__ void f2bf(const float* __restrict__ in, bf16* __restrict__ out, int n) {
    int i = (blockIdx.x * blockDim.x + threadIdx.x) * 4;
    if (i >= n) return;
    float4 v = *(const float4*)(in + i);
    bf162* o = (bf162*)(out + i);
    o[0] = __floats2bfloat162_rn(v.x, v.y);
    o[1] = __floats2bfloat162_rn(v.z, v.w);
}

// ---------------------------------------------------------------------------
// Key compaction: per batch, ordered list of unmasked key indices + count.
// ---------------------------------------------------------------------------
__global__ void compact_k(const int* __restrict__ mask, int* __restrict__ idx,
                          int* __restrict__ cnt)
{
    const int b = blockIdx.x, tid = threadIdx.x;
    const int lane = tid & 31, wid = tid >> 5;
    const int* mrow = mask + b * SS;
    __shared__ int ws[8];

    int lm[8], local = 0;
#pragma unroll
    for (int i = 0; i < 8; i++) { lm[i] = (mrow[tid * 8 + i] == 0); local += lm[i]; }

    int inc = local;
#pragma unroll
    for (int off = 1; off < 32; off <<= 1) {
        int n = __shfl_up_sync(0xffffffffu, inc, off);
        if (lane >= off) inc += n;
    }
    if (lane == 31) ws[wid] = inc;
    __syncthreads();
    if (tid == 0) {
        int run = 0;
#pragma unroll
        for (int w = 0; w < 8; w++) { int t = ws[w]; ws[w] = run; run += t; }
        cnt[b] = run;
    }
    __syncthreads();

    int pos = ws[wid] + inc - local;
#pragma unroll
    for (int i = 0; i < 8; i++)
        if (lm[i]) { idx[b * SS + pos] = tid * 8 + i; pos++; }
}

// ---------------------------------------------------------------------------
// GEMM tiling constants (shared by hgemm_nt and kv_gemm)
// CTA tile 128x256, 8 warps (2 M x 4 N), warp tile 64x64, K-chunk 64,
// 3-stage cp.async ring in dynamic smem.
// ---------------------------------------------------------------------------
#define GLD    72
#define A_SZ   (128 * GLD)
#define B_SZ   (256 * GLD)
#define STAGE_ELEMS (A_SZ + B_SZ)
#define GSMEM_BYTES (3 * STAGE_ELEMS * 2)   // 165888

// ---------------------------------------------------------------------------
// bf16 HGEMM (NT): C[M,N] = A[M,K] * W[N,K]^T (+bias fp32) (+res fp32)
// ---------------------------------------------------------------------------
template <bool BIAS, bool RES, bool OBF>
__global__ __launch_bounds__(256, 1)
void hgemm_nt(const bf16* __restrict__ A, const bf16* __restrict__ W,
              const float* __restrict__ bias, const float* __restrict__ res,
              void* __restrict__ Cout, int M, int N, int K)
{
    extern __shared__ __align__(16) bf16 smem[];

    const int tid  = threadIdx.x;
    const int wid  = tid >> 5, lane = tid & 31;
    const int m0   = blockIdx.y << 7;
    const int n0   = blockIdx.x << 8;
    const int wm   = (wid >> 2) << 6;
    const int wn   = (wid & 3) << 6;
    const int r8 = tid >> 3, sg = tid & 7;

    float acc[4][8][4];
#pragma unroll
    for (int i = 0; i < 4; i++)
#pragma unroll
        for (int j = 0; j < 8; j++)
#pragma unroll
            for (int e = 0; e < 4; e++) acc[i][j][e] = 0.0f;

    const int nk = K >> 6;

    auto load_stage = [&](int kt) {
        bf16* As = smem + (kt % 3) * STAGE_ELEMS;
        bf16* Bs = As + A_SZ;
        const int kofs = kt << 6;
#pragma unroll
        for (int i = 0; i < 4; i++) {
            int r = r8 + i * 32;
            cpa16(su32(&As[r * GLD + sg * 8]),
                  &A[(size_t)(m0 + r) * K + kofs + sg * 8]);
        }
#pragma unroll
        for (int i = 0; i < 8; i++) {
            int r = r8 + i * 32;
            cpa16(su32(&Bs[r * GLD + sg * 8]),
                  &W[(size_t)(n0 + r) * K + kofs + sg * 8]);
        }
        CPCOMMIT();
    };

    load_stage(0);
    load_stage(1);

    for (int kt = 0; kt < nk; kt++) {
        CPWAIT(1);
        __syncthreads();

        if (kt + 2 < nk) load_stage(kt + 2); else CPCOMMIT();

        const bf16* As = smem + (kt % 3) * STAGE_ELEMS;
        const bf16* Bs = As + A_SZ;

#pragma unroll
        for (int ks = 0; ks < 4; ks++) {
            uint32_t af[4][4], bfr[8][2];
#pragma unroll
            for (int mf = 0; mf < 4; mf++) {
                uint32_t ad = su32(&As[(wm + mf * 16 + (lane & 15)) * GLD +
                                       ks * 16 + (lane >> 4) * 8]);
                ldm4(af[mf][0], af[mf][1], af[mf][2], af[mf][3], ad);
            }
#pragma unroll
            for (int p = 0; p < 4; p++) {
                uint32_t bd = su32(&Bs[(wn + p * 16 + (lane & 7) + ((lane >> 4) << 3)) * GLD +
                                       ks * 16 + ((lane >> 3) & 1) * 8]);
                ldm4(bfr[2 * p][0], bfr[2 * p][1], bfr[2 * p + 1][0], bfr[2 * p + 1][1], bd);
            }
#pragma unroll
            for (int mf = 0; mf < 4; mf++)
#pragma unroll
                for (int nf = 0; nf < 8; nf++)
                    mmabf(acc[mf][nf], af[mf], bfr[nf][0], bfr[nf][1]);
        }
        __syncthreads();
    }

#pragma unroll
    for (int mf = 0; mf < 4; mf++) {
        const int r = m0 + wm + mf * 16 + (lane >> 2);
#pragma unroll
        for (int nf = 0; nf < 8; nf++) {
            const int c = n0 + wn + nf * 8 + (lane & 3) * 2;
            float v0 = acc[mf][nf][0], v1 = acc[mf][nf][1];
            float v2 = acc[mf][nf][2], v3 = acc[mf][nf][3];
            if (BIAS) {
                float b0v = bias[c], b1v = bias[c + 1];
                v0 += b0v; v1 += b1v; v2 += b0v; v3 += b1v;
            }
            if (RES) {
                float2 q0 = *(const float2*)&res[(size_t)r * N + c];
                float2 q1 = *(const float2*)&res[(size_t)(r + 8) * N + c];
                v0 += q0.x; v1 += q0.y; v2 += q1.x; v3 += q1.y;
            }
            if (OBF) {
                bf16* C = (bf16*)Cout;
                *(bf162*)&C[(size_t)r * N + c]       = __floats2bfloat162_rn(v0, v1);
                *(bf162*)&C[(size_t)(r + 8) * N + c] = __floats2bfloat162_rn(v2, v3);
            } else {
                float* C = (float*)Cout;
                *(float2*)&C[(size_t)r * N + c]       = make_float2(v0, v1);
                *(float2*)&C[(size_t)(r + 8) * N + c] = make_float2(v2, v3);
            }
        }
    }
}

// ---------------------------------------------------------------------------
// KV GEMM with fused row gather: for batch b, rows j < cnt[b]:
//   KV[j, 0:2048] = inpb[b*SS + idx[j]] @ Wkv^T + bkv
// cols 0..1023 -> kc, 1024..2047 -> vc (compact, zero-padded to ceil128(cnt)).
// Grid (2048/256, SS/128, BB); CTAs beyond ceil128(cnt) exit early.
// ---------------------------------------------------------------------------
__global__ __launch_bounds__(256, 1)
void kv_gemm(const bf16* __restrict__ Ain, const bf16* __restrict__ Wkv,
             const float* __restrict__ bkv, const int* __restrict__ idx,
             const int* __restrict__ cnt, bf16* __restrict__ kc,
             bf16* __restrict__ vc)
{
    extern __shared__ __align__(16) bf16 smem[];
    __shared__ int sidx[128];

    const int b   = blockIdx.z;
    const int m0  = blockIdx.y << 7;
    const int n0  = blockIdx.x << 8;
    const int c_  = cnt[b];
    if (m0 >= ((c_ + 127) & ~127)) return;

    const int tid  = threadIdx.x;
    const int wid  = tid >> 5, lane = tid & 31;
    const int wm   = (wid >> 2) << 6;
    const int wn   = (wid & 3) << 6;
    const int r8 = tid >> 3, sg = tid & 7;

    if (tid < 128) {
        int j = m0 + tid;
        sidx[tid] = (j < c_) ? idx[b * SS + j] : 0;
    }
    __syncthreads();

    const bf16* A = Ain + (size_t)b * SS * DD;

    float acc[4][8][4];
#pragma unroll
    for (int i = 0; i < 4; i++)
#pragma unroll
        for (int j = 0; j < 8; j++)
#pragma unroll
            for (int e = 0; e < 4; e++) acc[i][j][e] = 0.0f;

    const int nk = DD >> 6;     // K = 1024

    auto load_stage = [&](int kt) {
        bf16* As = smem + (kt % 3) * STAGE_ELEMS;
        bf16* Bs = As + A_SZ;
        const int kofs = kt << 6;
#pragma unroll
        for (int i = 0; i < 4; i++) {
            int r = r8 + i * 32;
            cpa16(su32(&As[r * GLD + sg * 8]),
                  &A[(size_t)sidx[r] * DD + kofs + sg * 8]);
        }
#pragma unroll
        for (int i = 0; i < 8; i++) {
            int r = r8 + i * 32;
            cpa16(su32(&Bs[r * GLD + sg * 8]),
                  &Wkv[(size_t)(n0 + r) * DD + kofs + sg * 8]);
        }
        CPCOMMIT();
    };

    load_stage(0);
    load_stage(1);

    for (int kt = 0; kt < nk; kt++) {
        CPWAIT(1);
        __syncthreads();

        if (kt + 2 < nk) load_stage(kt + 2); else CPCOMMIT();

        const bf16* As = smem + (kt % 3) * STAGE_ELEMS;
        const bf16* Bs = As + A_SZ;

#pragma unroll
        for (int ks = 0; ks < 4; ks++) {
            uint32_t af[4][4], bfr[8][2];
#pragma unroll
            for (int mf = 0; mf < 4; mf++) {
                uint32_t ad = su32(&As[(wm + mf * 16 + (lane & 15)) * GLD +
                                       ks * 16 + (lane >> 4) * 8]);
                ldm4(af[mf][0], af[mf][1], af[mf][2], af[mf][3], ad);
            }
#pragma unroll
            for (int p = 0; p < 4; p++) {
                uint32_t bd = su32(&Bs[(wn + p * 16 + (lane & 7) + ((lane >> 4) << 3)) * GLD +
                                       ks * 16 + ((lane >> 3) & 1) * 8]);
                ldm4(bfr[2 * p][0], bfr[2 * p][1], bfr[2 * p + 1][0], bfr[2 * p + 1][1], bd);
            }
#pragma unroll
            for (int mf = 0; mf < 4; mf++)
#pragma unroll
                for (int nf = 0; nf < 8; nf++)
                    mmabf(acc[mf][nf], af[mf], bfr[nf][0], bfr[nf][1]);
        }
        __syncthreads();
    }

    // Epilogue: bias add; route col<1024 -> kc, else vc; zero rows j >= cnt.
#pragma unroll
    for (int mf = 0; mf < 4; mf++) {
        const int j = m0 + wm + mf * 16 + (lane >> 2);   // local row in batch
#pragma unroll
        for (int nf = 0; nf < 8; nf++) {
            const int c = n0 + wn + nf * 8 + (lane & 3) * 2;   // 0..2047
            float b0v = bkv[c], b1v = bkv[c + 1];
            float v0 = acc[mf][nf][0] + b0v, v1 = acc[mf][nf][1] + b1v;
            float v2 = acc[mf][nf][2] + b0v, v3 = acc[mf][nf][3] + b1v;
            if (j >= c_)     { v0 = 0.0f; v1 = 0.0f; }
            if (j + 8 >= c_) { v2 = 0.0f; v3 = 0.0f; }
            bf16* dst = (c < DD) ? kc : vc;
            const int cc = (c < DD) ? c : c - DD;
            *(bf162*)&dst[(size_t)(b * SS + j) * DD + cc]     = __floats2bfloat162_rn(v0, v1);
            *(bf162*)&dst[(size_t)(b * SS + j + 8) * DD + cc] = __floats2bfloat162_rn(v2, v3);
        }
    }
}

// ---------------------------------------------------------------------------
// bf16 flash attention over COMPACTED keys. Block = (b,h) x 128-query tile,
// 8 warps. Q from g_qb [MTOK, DD]. Tail masked by kidx >= cnt.
// ---------------------------------------------------------------------------
#define LQT 72
__global__ __launch_bounds__(256)
void flash_bf16(const bf16* __restrict__ qp, const bf16* __restrict__ kc,
                const bf16* __restrict__ vc, const int* __restrict__ cnt,
                bf16* __restrict__ attn)
{
    __shared__ __align__(16) bf16 Qs[128 * LQT];   // 18 KB
    __shared__ __align__(16) bf16 Ks[64 * LQT];    // 9 KB
    __shared__ __align__(16) bf16 Vs[64 * LQT];    // 9 KB

    const int tid = threadIdx.x, wid = tid >> 5, lane = tid & 31;
    const int b = blockIdx.x >> 4, h = blockIdx.x & 15;
    const int q0 = blockIdx.y << 7;

    const int c_ = cnt[b];
    const int padded = (c_ + 63) & ~63;

    const bf16* qb  = qp + (size_t)(b * SS + q0) * DD + h * DHH;
    const bf16* kcb = kc + (size_t)b * SS * DD + h * DHH;
    const bf16* vcb = vc + (size_t)b * SS * DD + h * DHH;

#pragma unroll
    for (int i = 0; i < 4; i++) {
        int e = i * 256 + tid, r = e >> 3, sgq = e & 7;
        *(uint4*)&Qs[r * LQT + sgq * 8] = *(const uint4*)&qb[(size_t)r * DD + sgq * 8];
    }
    __syncthreads();

    uint32_t qf[4][4];
#pragma unroll
    for (int ks = 0; ks < 4; ks++) {
        uint32_t ad = su32(&Qs[(wid * 16 + (lane & 15)) * LQT + ks * 16 + (lane >> 4) * 8]);
        ldm4(qf[ks][0], qf[ks][1], qf[ks][2], qf[ks][3], ad);
    }

    float m0v = -1e30f, m1v = -1e30f, l0 = 0.0f, l1 = 0.0f;
    float o[8][4];
#pragma unroll
    for (int nf = 0; nf < 8; nf++)
#pragma unroll
        for (int e = 0; e < 4; e++) o[nf][e] = 0.0f;

    for (int kb0 = 0; kb0 < padded; kb0 += 64) {
        __syncthreads();
#pragma unroll
        for (int i = 0; i < 2; i++) {
            int e = i * 256 + tid, r = e >> 3, sgq = e & 7;
            *(uint4*)&Ks[r * LQT + sgq * 8] = *(const uint4*)&kcb[(size_t)(kb0 + r) * DD + sgq * 8];
            *(uint4*)&Vs[r * LQT + sgq * 8] = *(const uint4*)&vcb[(size_t)(kb0 + r) * DD + sgq * 8];
        }
        __syncthreads();

        float sv[8][4];
#pragma unroll
        for (int nf = 0; nf < 8; nf++)
#pragma unroll
            for (int e = 0; e < 4; e++) sv[nf][e] = 0.0f;

#pragma unroll
        for (int ks = 0; ks < 4; ks++) {
            uint32_t kf[8][2];
#pragma unroll
            for (int p = 0; p < 4; p++) {
                uint32_t bd = su32(&Ks[(p * 16 + (lane & 7) + ((lane >> 4) << 3)) * LQT +
                                       ks * 16 + ((lane >> 3) & 1) * 8]);
                ldm4(kf[2 * p][0], kf[2 * p][1], kf[2 * p + 1][0], kf[2 * p + 1][1], bd);
            }
#pragma unroll
            for (int nf = 0; nf < 8; nf++)
                mmabf(sv[nf], qf[ks], kf[nf][0], kf[nf][1]);
        }

        const int c2 = (lane & 3) * 2;
#pragma unroll
        for (int nf = 0; nf < 8; nf++) {
            int kidx = kb0 + nf * 8 + c2;
            bool v0 = kidx < c_, v1 = (kidx + 1) < c_;
            sv[nf][0] = v0 ? sv[nf][0] * 0.125f : -1e30f;
            sv[nf][1] = v1 ? sv[nf][1] * 0.125f : -1e30f;
            sv[nf][2] = v0 ? sv[nf][2] * 0.125f : -1e30f;
            sv[nf][3] = v1 ? sv[nf][3] * 0.125f : -1e30f;
        }

        float mx0 = -1e30f, mx1 = -1e30f;
#pragma unroll
        for (int nf = 0; nf < 8; nf++) {
            mx0 = fmaxf(mx0, fmaxf(sv[nf][0], sv[nf][1]));
            mx1 = fmaxf(mx1, fmaxf(sv[nf][2], sv[nf][3]));
        }
        mx0 = fmaxf(mx0, __shfl_xor_sync(0xffffffffu, mx0, 1));
        mx0 = fmaxf(mx0, __shfl_xor_sync(0xffffffffu, mx0, 2));
        mx1 = fmaxf(mx1, __shfl_xor_sync(0xffffffffu, mx1, 1));
        mx1 = fmaxf(mx1, __shfl_xor_sync(0xffffffffu, mx1, 2));

        float mn0 = fmaxf(m0v, mx0), mn1 = fmaxf(m1v, mx1);
        float al0 = __expf(m0v - mn0), al1 = __expf(m1v - mn1);
        m0v = mn0; m1v = mn1;

        float sum0 = 0.0f, sum1 = 0.0f;
#pragma unroll
        for (int nf = 0; nf < 8; nf++) {
            sv[nf][0] = __expf(sv[nf][0] - mn0);
            sv[nf][1] = __expf(sv[nf][1] - mn0);
            sv[nf][2] = __expf(sv[nf][2] - mn1);
            sv[nf][3] = __expf(sv[nf][3] - mn1);
            sum0 += sv[nf][0] + sv[nf][1];
            sum1 += sv[nf][2] + sv[nf][3];
        }
        sum0 += __shfl_xor_sync(0xffffffffu, sum0, 1);
        sum0 += __shfl_xor_sync(0xffffffffu, sum0, 2);
        sum1 += __shfl_xor_sync(0xffffffffu, sum1, 1);
        sum1 += __shfl_xor_sync(0xffffffffu, sum1, 2);
        l0 = l0 * al0 + sum0;
        l1 = l1 * al1 + sum1;
#pragma unroll
        for (int nf = 0; nf < 8; nf++) {
            o[nf][0] *= al0; o[nf][1] *= al0;
            o[nf][2] *= al1; o[nf][3] *= al1;
        }

#pragma unroll
        for (int ks = 0; ks < 4; ks++) {
            uint32_t pa[4];
            pa[0] = packbf(sv[2 * ks][0],     sv[2 * ks][1]);
            pa[1] = packbf(sv[2 * ks][2],     sv[2 * ks][3]);
            pa[2] = packbf(sv[2 * ks + 1][0], sv[2 * ks + 1][1]);
            pa[3] = packbf(sv[2 * ks + 1][2], sv[2 * ks + 1][3]);
#pragma unroll
            for (int p = 0; p < 4; p++) {
                uint32_t v0, v1, v2, v3;
                uint32_t vd = su32(&Vs[(ks * 16 + (lane & 7) + (((lane >> 3) & 1) << 3)) * LQT +
                                       p * 16 + ((lane >> 4) << 3)]);
                ldm4t(v0, v1, v2, v3, vd);
                mmabf(o[2 * p],     pa, v0, v1);
                mmabf(o[2 * p + 1], pa, v2, v3);
            }
        }
    }

    const float i0 = 1.0f / l0, i1 = 1.0f / l1;
    const int r0 = q0 + wid * 16 + (lane >> 2);
    bf16* ob = attn + (size_t)b * SS * DD + h * DHH;
#pragma unroll
    for (int nf = 0; nf < 8; nf++) {
        int c = nf * 8 + (lane & 3) * 2;
        *(bf162*)&ob[(size_t)r0 * DD + c] =
            __floats2bfloat162_rn(o[nf][0] * i0, o[nf][1] * i0);
        *(bf162*)&ob[(size_t)(r0 + 8) * DD + c] =
            __floats2bfloat162_rn(o[nf][2] * i1, o[nf][3] * i1);
    }
}

// ---------------------------------------------------------------------------
// LayerNorm
// ---------------------------------------------------------------------------
__global__ __launch_bounds__(256)
void ln_kernel(const float* __restrict__ y, const float* __restrict__ gamma,
               const float* __restrict__ beta, float* __restrict__ out)
{
    __shared__ float red[16];
    const int row = blockIdx.x;
    const int tid = threadIdx.x;
    const float* yr = y + (size_t)row * DD;

    float4 v = *(const float4*)&yr[tid * 4];
    float s  = v.x + v.y + v.z + v.w;
    float s2 = v.x * v.x + v.y * v.y + v.z * v.z + v.w * v.w;
#pragma unroll
    for (int off = 16; off; off >>= 1) {
        s  += __shfl_xor_sync(0xffffffffu, s,  off);
        s2 += __shfl_xor_sync(0xffffffffu, s2, off);
    }
    const int w = tid >> 5;
    if ((tid & 31) == 0) { red[w] = s; red[w + 8] = s2; }
    __syncthreads();
    s = 0.0f; s2 = 0.0f;
#pragma unroll
    for (int i = 0; i < 8; i++) { s += red[i]; s2 += red[i + 8]; }

    const float mean = s * (1.0f / DD);
    const float var  = s2 * (1.0f / DD) - mean * mean;
    const float inv  = rsqrtf(var + 1e-5f);

    float4 g  = *(const float4*)&gamma[tid * 4];
    float4 bt = *(const float4*)&beta[tid * 4];
    float4 r;
    r.x = (v.x - mean) * inv * g.x + bt.x;
    r.y = (v.y - mean) * inv * g.y + bt.y;
    r.z = (v.z - mean) * inv * g.z + bt.z;
    r.w = (v.w - mean) * inv * g.w + bt.w;
    *(float4*)&out[(size_t)row * DD + tid * 4] = r;
}

// ---------------------------------------------------------------------------
extern "C" void kernel_launch(void* const* d_in, const int* in_sizes, int n_in,
                              void* d_out, int out_size)
{
    (void)in_sizes; (void)n_in; (void)out_size;
    const float* inp   = (const float*)d_in[0];
    const int*   mask  = (const int*)d_in[1];
    const float* Wqkv  = (const float*)d_in[2];
    const float* bqkv  = (const float*)d_in[3];
    const float* Wo    = (const float*)d_in[4];
    const float* gamma = (const float*)d_in[5];
    const float* beta  = (const float*)d_in[6];
    float* out = (float*)d_out;

    bf16 *inpb, *wqkvb, *wob, *qb, *kc, *vc, *attnb;
    float* y;
    int *idx, *cnt;
    cudaGetSymbolAddress((void**)&inpb,  g_inpb);
    cudaGetSymbolAddress((void**)&wqkvb, g_wqkvb);
    cudaGetSymbolAddress((void**)&wob,   g_wob);
    cudaGetSymbolAddress((void**)&qb,    g_qb);
    cudaGetSymbolAddress((void**)&kc,    g_kc);
    cudaGetSymbolAddress((void**)&vc,    g_vc);
    cudaGetSymbolAddress((void**)&attnb, g_attnb);
    cudaGetSymbolAddress((void**)&y,     g_y);
    cudaGetSymbolAddress((void**)&idx,   g_idx);
    cudaGetSymbolAddress((void**)&cnt,   g_cnt);

    cudaFuncSetAttribute(hgemm_nt<true, false, true>,
                         cudaFuncAttributeMaxDynamicSharedMemorySize, GSMEM_BYTES);
    cudaFuncSetAttribute(hgemm_nt<false, true, false>,
                         cudaFuncAttributeMaxDynamicSharedMemorySize, GSMEM_BYTES);
    cudaFuncSetAttribute(kv_gemm,
                         cudaFuncAttributeMaxDynamicSharedMemorySize, GSMEM_BYTES);

    // 0) conversions + key compaction index
    f2bf<<<(MTOK * DD) / 1024, 256>>>(inp,  inpb,  MTOK * DD);
    f2bf<<<(NQKV * DD) / 1024, 256>>>(Wqkv, wqkvb, NQKV * DD);
    f2bf<<<(DD * DD)   / 1024, 256>>>(Wo,   wob,   DD * DD);
    compact_k<<<BB, 256>>>(mask, idx, cnt);

    // 1a) Q = inp @ Wq^T + bq          -> bf16 [8192, 1024]
    hgemm_nt<true, false, true><<<dim3(DD / 256, MTOK / 128), 256, GSMEM_BYTES>>>(
        inpb, wqkvb, bqkv, nullptr, qb, MTOK, DD, DD);

    // 1b) compact K/V = inp[idx] @ Wkv^T + bkv  -> kc/vc (gather fused)
    kv_gemm<<<dim3(2 * DD / 256, SS / 128, BB), 256, GSMEM_BYTES>>>(
        inpb, wqkvb + (size_t)DD * DD, bqkv + DD, idx, cnt, kc, vc);

    // 2) attention over ~cnt keys -> bf16 [8192, 1024]
    flash_bf16<<<dim3(BB * HH, SS / 128), 256>>>(qb, kc, vc, cnt, attnb);

    // 3) y = inp + attn @ Wo^T  -> fp32 [8192, 1024]
    hgemm_nt<false, true, false><<<dim3(DD / 256, MTOK / 128), 256, GSMEM_BYTES>>>(
        attnb, wob, nullptr, inp, y, MTOK, DD, DD);

    // 4) out = LayerNorm(y)
    ln_kernel<<<MTOK, 256>>>(y, gamma, beta, out);
}

// round 11
// speedup vs baseline: 9.6422x; 1.0226x over previous
#include <cuda_runtime.h>
#include <cuda_bf16.h>
#include <cstdint>

#define BB   4
#define SS   2048
#define DD   1024
#define HH   16
#define DHH  64
#define MTOK (BB * SS)          // 8192
#define NQKV (3 * HH * DHH)     // 3072

typedef __nv_bfloat16  bf16;
typedef __nv_bfloat162 bf162;

// ---------------------------------------------------------------------------
// Scratch (static __device__ arrays; no allocation allowed)
// ---------------------------------------------------------------------------
__device__ bf16  g_inpb [(size_t)MTOK * DD];     // 16 MB
__device__ bf16  g_wqkvb[(size_t)NQKV * DD];     // 6 MB
__device__ bf16  g_wob  [(size_t)DD * DD];       // 2 MB
__device__ bf16  g_qb   [(size_t)MTOK * DD];     // 16 MB  Q projections
__device__ bf16  g_kc   [(size_t)MTOK * DD];     // 16 MB  compact K
__device__ bf16  g_vc   [(size_t)MTOK * DD];     // 16 MB  compact V
__device__ bf16  g_attnb[(size_t)MTOK * DD];     // 16 MB
__device__ float g_y    [(size_t)MTOK * DD];     // 32 MB
__device__ int   g_idx  [BB * SS];
__device__ int   g_cnt  [BB];

// ---------------------------------------------------------------------------
// Helpers: ldmatrix / mma.sync (sm_80 PTX) + cp.async
// ---------------------------------------------------------------------------
__device__ __forceinline__ uint32_t su32(const void* p) {
    return (uint32_t)__cvta_generic_to_shared(p);
}
__device__ __forceinline__ void ldm4(uint32_t& r0, uint32_t& r1, uint32_t& r2,
                                     uint32_t& r3, uint32_t a) {
    asm volatile("ldmatrix.sync.aligned.m8n8.x4.shared.b16 {%0,%1,%2,%3},[%4];\n"
                 : "=r"(r0), "=r"(r1), "=r"(r2), "=r"(r3) : "r"(a));
}
__device__ __forceinline__ void ldm4t(uint32_t& r0, uint32_t& r1, uint32_t& r2,
                                      uint32_t& r3, uint32_t a) {
    asm volatile("ldmatrix.sync.aligned.m8n8.x4.trans.shared.b16 {%0,%1,%2,%3},[%4];\n"
                 : "=r"(r0), "=r"(r1), "=r"(r2), "=r"(r3) : "r"(a));
}
__device__ __forceinline__ void mmabf(float* c, const uint32_t* a,
                                      uint32_t b0, uint32_t b1) {
    asm volatile(
        "mma.sync.aligned.m16n8k16.row.col.f32.bf16.bf16.f32 "
        "{%0,%1,%2,%3},{%4,%5,%6,%7},{%8,%9},{%0,%1,%2,%3};\n"
        : "+f"(c[0]), "+f"(c[1]), "+f"(c[2]), "+f"(c[3])
        : "r"(a[0]), "r"(a[1]), "r"(a[2]), "r"(a[3]), "r"(b0), "r"(b1));
}
__device__ __forceinline__ uint32_t packbf(float x, float y) {
    bf162 t = __floats2bfloat162_rn(x, y);
    return *reinterpret_cast<uint32_t*>(&t);
}
__device__ __forceinline__ void cpa16(uint32_t dst, const void* src) {
    asm volatile("cp.async.cg.shared.global [%0], [%1], 16;\n" :: "r"(dst), "l"(src));
}
#define CPCOMMIT() asm volatile("cp.async.commit_group;\n" ::: "memory")
#define CPWAIT(n)  asm volatile("cp.async.wait_group %0;\n" :: "n"(n) : "memory")

// ---------------------------------------------------------------------------
// fp32 -> bf16 conversion
// ---------------------------------------------------------------------------
__global__ void f2bf(const float* __restrict__ in, bf16* __restrict__ out, int n) {
    int i = (blockIdx.x * blockDim.x + threadIdx.x) * 4;
    if (i >= n) return;
    float4 v = *(const float4*)(in + i);
    bf162* o = (bf162*)(out + i);
    o[0] = __floats2bfloat162_rn(v.x, v.y);
    o[1] = __floats2bfloat162_rn(v.z, v.w);
}

// ---------------------------------------------------------------------------
// Key compaction: per batch, ordered list of unmasked key indices + count.
// ---------------------------------------------------------------------------
__global__ void compact_k(const int* __restrict__ mask, int* __restrict__ idx,
                          int* __restrict__ cnt)
{
    const int b = blockIdx.x, tid = threadIdx.x;
    const int lane = tid & 31, wid = tid >> 5;
    const int* mrow = mask + b * SS;
    __shared__ int ws[8];

    int lm[8], local = 0;
#pragma unroll
    for (int i = 0; i < 8; i++) { lm[i] = (mrow[tid * 8 + i] == 0); local += lm[i]; }

    int inc = local;
#pragma unroll
    for (int off = 1; off < 32; off <<= 1) {
        int n = __shfl_up_sync(0xffffffffu, inc, off);
        if (lane >= off) inc += n;
    }
    if (lane == 31) ws[wid] = inc;
    __syncthreads();
    if (tid == 0) {
        int run = 0;
#pragma unroll
        for (int w = 0; w < 8; w++) { int t = ws[w]; ws[w] = run; run += t; }
        cnt[b] = run;
    }
    __syncthreads();

    int pos = ws[wid] + inc - local;
#pragma unroll
    for (int i = 0; i < 8; i++)
        if (lm[i]) { idx[b * SS + pos] = tid * 8 + i; pos++; }
}

// ---------------------------------------------------------------------------
// GEMM tiling constants: CTA 128x256, 8 warps (2Mx4N), warp tile 64x64,
// K-chunk 64, 3-stage cp.async ring in dynamic smem.
// ---------------------------------------------------------------------------
#define GLD    72
#define A_SZ   (128 * GLD)
#define B_SZ   (256 * GLD)
#define STAGE_ELEMS (A_SZ + B_SZ)
#define GSMEM_BYTES (3 * STAGE_ELEMS * 2)   // 165888

// ---------------------------------------------------------------------------
// bf16 HGEMM (NT): C[M,N] = A[M,K] * W[N,K]^T (+bias fp32) (+res fp32)
// ---------------------------------------------------------------------------
template <bool BIAS, bool RES, bool OBF>
__global__ __launch_bounds__(256, 1)
void hgemm_nt(const bf16* __restrict__ A, const bf16* __restrict__ W,
              const float* __restrict__ bias, const float* __restrict__ res,
              void* __restrict__ Cout, int M, int N, int K)
{
    extern __shared__ __align__(16) bf16 smem[];

    const int tid  = threadIdx.x;
    const int wid  = tid >> 5, lane = tid & 31;
    const int m0   = blockIdx.y << 7;
    const int n0   = blockIdx.x << 8;
    const int wm   = (wid >> 2) << 6;
    const int wn   = (wid & 3) << 6;
    const int r8 = tid >> 3, sg = tid & 7;

    float acc[4][8][4];
#pragma unroll
    for (int i = 0; i < 4; i++)
#pragma unroll
        for (int j = 0; j < 8; j++)
#pragma unroll
            for (int e = 0; e < 4; e++) acc[i][j][e] = 0.0f;

    const int nk = K >> 6;

    auto load_stage = [&](int kt) {
        bf16* As = smem + (kt % 3) * STAGE_ELEMS;
        bf16* Bs = As + A_SZ;
        const int kofs = kt << 6;
#pragma unroll
        for (int i = 0; i < 4; i++) {
            int r = r8 + i * 32;
            cpa16(su32(&As[r * GLD + sg * 8]),
                  &A[(size_t)(m0 + r) * K + kofs + sg * 8]);
        }
#pragma unroll
        for (int i = 0; i < 8; i++) {
            int r = r8 + i * 32;
            cpa16(su32(&Bs[r * GLD + sg * 8]),
                  &W[(size_t)(n0 + r) * K + kofs + sg * 8]);
        }
        CPCOMMIT();
    };

    load_stage(0);
    load_stage(1);

    for (int kt = 0; kt < nk; kt++) {
        CPWAIT(1);
        __syncthreads();        // orders compute(kt-1) before load(kt+2) below

        if (kt + 2 < nk) load_stage(kt + 2); else CPCOMMIT();

        const bf16* As = smem + (kt % 3) * STAGE_ELEMS;
        const bf16* Bs = As + A_SZ;

#pragma unroll
        for (int ks = 0; ks < 4; ks++) {
            uint32_t af[4][4], bfr[8][2];
#pragma unroll
            for (int mf = 0; mf < 4; mf++) {
                uint32_t ad = su32(&As[(wm + mf * 16 + (lane & 15)) * GLD +
                                       ks * 16 + (lane >> 4) * 8]);
                ldm4(af[mf][0], af[mf][1], af[mf][2], af[mf][3], ad);
            }
#pragma unroll
            for (int p = 0; p < 4; p++) {
                uint32_t bd = su32(&Bs[(wn + p * 16 + (lane & 7) + ((lane >> 4) << 3)) * GLD +
                                       ks * 16 + ((lane >> 3) & 1) * 8]);
                ldm4(bfr[2 * p][0], bfr[2 * p][1], bfr[2 * p + 1][0], bfr[2 * p + 1][1], bd);
            }
#pragma unroll
            for (int mf = 0; mf < 4; mf++)
#pragma unroll
                for (int nf = 0; nf < 8; nf++)
                    mmabf(acc[mf][nf], af[mf], bfr[nf][0], bfr[nf][1]);
        }
    }

#pragma unroll
    for (int mf = 0; mf < 4; mf++) {
        const int r = m0 + wm + mf * 16 + (lane >> 2);
#pragma unroll
        for (int nf = 0; nf < 8; nf++) {
            const int c = n0 + wn + nf * 8 + (lane & 3) * 2;
            float v0 = acc[mf][nf][0], v1 = acc[mf][nf][1];
            float v2 = acc[mf][nf][2], v3 = acc[mf][nf][3];
            if (BIAS) {
                float b0v = bias[c], b1v = bias[c + 1];
                v0 += b0v; v1 += b1v; v2 += b0v; v3 += b1v;
            }
            if (RES) {
                float2 q0 = *(const float2*)&res[(size_t)r * N + c];
                float2 q1 = *(const float2*)&res[(size_t)(r + 8) * N + c];
                v0 += q0.x; v1 += q0.y; v2 += q1.x; v3 += q1.y;
            }
            if (OBF) {
                bf16* C = (bf16*)Cout;
                *(bf162*)&C[(size_t)r * N + c]       = __floats2bfloat162_rn(v0, v1);
                *(bf162*)&C[(size_t)(r + 8) * N + c] = __floats2bfloat162_rn(v2, v3);
            } else {
                float* C = (float*)Cout;
                *(float2*)&C[(size_t)r * N + c]       = make_float2(v0, v1);
                *(float2*)&C[(size_t)(r + 8) * N + c] = make_float2(v2, v3);
            }
        }
    }
}

// ---------------------------------------------------------------------------
// KV GEMM with fused row gather: for batch b, rows j < cnt[b]:
//   KV[j, 0:2048] = inpb[b*SS + idx[j]] @ Wkv^T + bkv
// cols 0..1023 -> kc, 1024..2047 -> vc (zero-padded to ceil128(cnt)).
// ---------------------------------------------------------------------------
__global__ __launch_bounds__(256, 1)
void kv_gemm(const bf16* __restrict__ Ain, const bf16* __restrict__ Wkv,
             const float* __restrict__ bkv, const int* __restrict__ idx,
             const int* __restrict__ cnt, bf16* __restrict__ kc,
             bf16* __restrict__ vc)
{
    extern __shared__ __align__(16) bf16 smem[];
    __shared__ int sidx[128];

    const int b   = blockIdx.z;
    const int m0  = blockIdx.y << 7;
    const int n0  = blockIdx.x << 8;
    const int c_  = cnt[b];
    if (m0 >= ((c_ + 127) & ~127)) return;

    const int tid  = threadIdx.x;
    const int wid  = tid >> 5, lane = tid & 31;
    const int wm   = (wid >> 2) << 6;
    const int wn   = (wid & 3) << 6;
    const int r8 = tid >> 3, sg = tid & 7;

    if (tid < 128) {
        int j = m0 + tid;
        sidx[tid] = (j < c_) ? idx[b * SS + j] : 0;
    }
    __syncthreads();

    const bf16* A = Ain + (size_t)b * SS * DD;

    float acc[4][8][4];
#pragma unroll
    for (int i = 0; i < 4; i++)
#pragma unroll
        for (int j = 0; j < 8; j++)
#pragma unroll
            for (int e = 0; e < 4; e++) acc[i][j][e] = 0.0f;

    const int nk = DD >> 6;     // K = 1024

    auto load_stage = [&](int kt) {
        bf16* As = smem + (kt % 3) * STAGE_ELEMS;
        bf16* Bs = As + A_SZ;
        const int kofs = kt << 6;
#pragma unroll
        for (int i = 0; i < 4; i++) {
            int r = r8 + i * 32;
            cpa16(su32(&As[r * GLD + sg * 8]),
                  &A[(size_t)sidx[r] * DD + kofs + sg * 8]);
        }
#pragma unroll
        for (int i = 0; i < 8; i++) {
            int r = r8 + i * 32;
            cpa16(su32(&Bs[r * GLD + sg * 8]),
                  &Wkv[(size_t)(n0 + r) * DD + kofs + sg * 8]);
        }
        CPCOMMIT();
    };

    load_stage(0);
    load_stage(1);

    for (int kt = 0; kt < nk; kt++) {
        CPWAIT(1);
        __syncthreads();

        if (kt + 2 < nk) load_stage(kt + 2); else CPCOMMIT();

        const bf16* As = smem + (kt % 3) * STAGE_ELEMS;
        const bf16* Bs = As + A_SZ;

#pragma unroll
        for (int ks = 0; ks < 4; ks++) {
            uint32_t af[4][4], bfr[8][2];
#pragma unroll
            for (int mf = 0; mf < 4; mf++) {
                uint32_t ad = su32(&As[(wm + mf * 16 + (lane & 15)) * GLD +
                                       ks * 16 + (lane >> 4) * 8]);
                ldm4(af[mf][0], af[mf][1], af[mf][2], af[mf][3], ad);
            }
#pragma unroll
            for (int p = 0; p < 4; p++) {
                uint32_t bd = su32(&Bs[(wn + p * 16 + (lane & 7) + ((lane >> 4) << 3)) * GLD +
                                       ks * 16 + ((lane >> 3) & 1) * 8]);
                ldm4(bfr[2 * p][0], bfr[2 * p][1], bfr[2 * p + 1][0], bfr[2 * p + 1][1], bd);
            }
#pragma unroll
            for (int mf = 0; mf < 4; mf++)
#pragma unroll
                for (int nf = 0; nf < 8; nf++)
                    mmabf(acc[mf][nf], af[mf], bfr[nf][0], bfr[nf][1]);
        }
    }

#pragma unroll
    for (int mf = 0; mf < 4; mf++) {
        const int j = m0 + wm + mf * 16 + (lane >> 2);
#pragma unroll
        for (int nf = 0; nf < 8; nf++) {
            const int c = n0 + wn + nf * 8 + (lane & 3) * 2;
            float b0v = bkv[c], b1v = bkv[c + 1];
            float v0 = acc[mf][nf][0] + b0v, v1 = acc[mf][nf][1] + b1v;
            float v2 = acc[mf][nf][2] + b0v, v3 = acc[mf][nf][3] + b1v;
            if (j >= c_)     { v0 = 0.0f; v1 = 0.0f; }
            if (j + 8 >= c_) { v2 = 0.0f; v3 = 0.0f; }
            bf16* dst = (c < DD) ? kc : vc;
            const int cc = (c < DD) ? c : c - DD;
            *(bf162*)&dst[(size_t)(b * SS + j) * DD + cc]     = __floats2bfloat162_rn(v0, v1);
            *(bf162*)&dst[(size_t)(b * SS + j + 8) * DD + cc] = __floats2bfloat162_rn(v2, v3);
        }
    }
}

// ---------------------------------------------------------------------------
// bf16 flash attention over COMPACTED keys. Block = (b,h) x 128-query tile,
// 8 warps. 3-stage cp.async ring for K/V (overlap loads with QK/softmax/PV),
// ONE __syncthreads per key tile. Dynamic smem 72 KB.
// ---------------------------------------------------------------------------
#define LQT 72
#define FQ_ELEMS  (128 * LQT)
#define FKV_STAGE (2 * 64 * LQT)
#define FSMEM_BYTES ((FQ_ELEMS + 3 * FKV_STAGE) * 2)   // 73728

__global__ __launch_bounds__(256)
void flash_bf16(const bf16* __restrict__ qp, const bf16* __restrict__ kc,
                const bf16* __restrict__ vc, const int* __restrict__ cnt,
                bf16* __restrict__ attn)
{
    extern __shared__ __align__(16) bf16 fsm[];
    bf16* Qs = fsm;

    const int tid = threadIdx.x, wid = tid >> 5, lane = tid & 31;
    const int b = blockIdx.x >> 4, h = blockIdx.x & 15;
    const int q0 = blockIdx.y << 7;

    const int c_ = cnt[b];
    const int T = ((c_ + 63) & ~63) >> 6;       // number of 64-key tiles

    const bf16* qb  = qp + (size_t)(b * SS + q0) * DD + h * DHH;
    const bf16* kcb = kc + (size_t)b * SS * DD + h * DHH;
    const bf16* vcb = vc + (size_t)b * SS * DD + h * DHH;

    auto load_kv = [&](int t) {
        bf16* Ks = fsm + FQ_ELEMS + (t % 3) * FKV_STAGE;
        bf16* Vs = Ks + 64 * LQT;
        const int kb0 = t << 6;
#pragma unroll
        for (int i = 0; i < 2; i++) {
            int e = i * 256 + tid, r = e >> 3, sgq = e & 7;
            cpa16(su32(&Ks[r * LQT + sgq * 8]), &kcb[(size_t)(kb0 + r) * DD + sgq * 8]);
            cpa16(su32(&Vs[r * LQT + sgq * 8]), &vcb[(size_t)(kb0 + r) * DD + sgq * 8]);
        }
        CPCOMMIT();
    };

    // Prefetch first two K/V tiles; overlap with Q staging.
    load_kv(0);
    if (T > 1) load_kv(1); else CPCOMMIT();

#pragma unroll
    for (int i = 0; i < 4; i++) {
        int e = i * 256 + tid, r = e >> 3, sgq = e & 7;
        *(uint4*)&Qs[r * LQT + sgq * 8] = *(const uint4*)&qb[(size_t)r * DD + sgq * 8];
    }
    __syncthreads();

    uint32_t qf[4][4];
#pragma unroll
    for (int ks = 0; ks < 4; ks++) {
        uint32_t ad = su32(&Qs[(wid * 16 + (lane & 15)) * LQT + ks * 16 + (lane >> 4) * 8]);
        ldm4(qf[ks][0], qf[ks][1], qf[ks][2], qf[ks][3], ad);
    }

    float m0v = -1e30f, m1v = -1e30f, l0 = 0.0f, l1 = 0.0f;
    float o[8][4];
#pragma unroll
    for (int nf = 0; nf < 8; nf++)
#pragma unroll
        for (int e = 0; e < 4; e++) o[nf][e] = 0.0f;

    for (int t = 0; t < T; t++) {
        CPWAIT(1);
        __syncthreads();        // stage t ready; orders compute(t-1) before load(t+2)
        if (t + 2 < T) load_kv(t + 2); else CPCOMMIT();

        const bf16* Ks = fsm + FQ_ELEMS + (t % 3) * FKV_STAGE;
        const bf16* Vs = Ks + 64 * LQT;
        const int kb0 = t << 6;

        float sv[8][4];
#pragma unroll
        for (int nf = 0; nf < 8; nf++)
#pragma unroll
            for (int e = 0; e < 4; e++) sv[nf][e] = 0.0f;

#pragma unroll
        for (int ks = 0; ks < 4; ks++) {
            uint32_t kf[8][2];
#pragma unroll
            for (int p = 0; p < 4; p++) {
                uint32_t bd = su32(&Ks[(p * 16 + (lane & 7) + ((lane >> 4) << 3)) * LQT +
                                       ks * 16 + ((lane >> 3) & 1) * 8]);
                ldm4(kf[2 * p][0], kf[2 * p][1], kf[2 * p + 1][0], kf[2 * p + 1][1], bd);
            }
#pragma unroll
            for (int nf = 0; nf < 8; nf++)
                mmabf(sv[nf], qf[ks], kf[nf][0], kf[nf][1]);
        }

        const int c2 = (lane & 3) * 2;
#pragma unroll
        for (int nf = 0; nf < 8; nf++) {
            int kidx = kb0 + nf * 8 + c2;
            bool v0 = kidx < c_, v1 = (kidx + 1) < c_;
            sv[nf][0] = v0 ? sv[nf][0] * 0.125f : -1e30f;
            sv[nf][1] = v1 ? sv[nf][1] * 0.125f : -1e30f;
            sv[nf][2] = v0 ? sv[nf][2] * 0.125f : -1e30f;
            sv[nf][3] = v1 ? sv[nf][3] * 0.125f : -1e30f;
        }

        float mx0 = -1e30f, mx1 = -1e30f;
#pragma unroll
        for (int nf = 0; nf < 8; nf++) {
            mx0 = fmaxf(mx0, fmaxf(sv[nf][0], sv[nf][1]));
            mx1 = fmaxf(mx1, fmaxf(sv[nf][2], sv[nf][3]));
        }
        mx0 = fmaxf(mx0, __shfl_xor_sync(0xffffffffu, mx0, 1));
        mx0 = fmaxf(mx0, __shfl_xor_sync(0xffffffffu, mx0, 2));
        mx1 = fmaxf(mx1, __shfl_xor_sync(0xffffffffu, mx1, 1));
        mx1 = fmaxf(mx1, __shfl_xor_sync(0xffffffffu, mx1, 2));

        float mn0 = fmaxf(m0v, mx0), mn1 = fmaxf(m1v, mx1);
        float al0 = __expf(m0v - mn0), al1 = __expf(m1v - mn1);
        m0v = mn0; m1v = mn1;

        float sum0 = 0.0f, sum1 = 0.0f;
#pragma unroll
        for (int nf = 0; nf < 8; nf++) {
            sv[nf][0] = __expf(sv[nf][0] - mn0);
            sv[nf][1] = __expf(sv[nf][1] - mn0);
            sv[nf][2] = __expf(sv[nf][2] - mn1);
            sv[nf][3] = __expf(sv[nf][3] - mn1);
            sum0 += sv[nf][0] + sv[nf][1];
            sum1 += sv[nf][2] + sv[nf][3];
        }
        sum0 += __shfl_xor_sync(0xffffffffu, sum0, 1);
        sum0 += __shfl_xor_sync(0xffffffffu, sum0, 2);
        sum1 += __shfl_xor_sync(0xffffffffu, sum1, 1);
        sum1 += __shfl_xor_sync(0xffffffffu, sum1, 2);
        l0 = l0 * al0 + sum0;
        l1 = l1 * al1 + sum1;
#pragma unroll
        for (int nf = 0; nf < 8; nf++) {
            o[nf][0] *= al0; o[nf][1] *= al0;
            o[nf][2] *= al1; o[nf][3] *= al1;
        }

#pragma unroll
        for (int ks = 0; ks < 4; ks++) {
            uint32_t pa[4];
            pa[0] = packbf(sv[2 * ks][0],     sv[2 * ks][1]);
            pa[1] = packbf(sv[2 * ks][2],     sv[2 * ks][3]);
            pa[2] = packbf(sv[2 * ks + 1][0], sv[2 * ks + 1][1]);
            pa[3] = packbf(sv[2 * ks + 1][2], sv[2 * ks + 1][3]);
#pragma unroll
            for (int p = 0; p < 4; p++) {
                uint32_t v0, v1, v2, v3;
                uint32_t vd = su32(&Vs[(ks * 16 + (lane & 7) + (((lane >> 3) & 1) << 3)) * LQT +
                                       p * 16 + ((lane >> 4) << 3)]);
                ldm4t(v0, v1, v2, v3, vd);
                mmabf(o[2 * p],     pa, v0, v1);
                mmabf(o[2 * p + 1], pa, v2, v3);
            }
        }
    }

    const float i0 = 1.0f / l0, i1 = 1.0f / l1;
    const int r0 = q0 + wid * 16 + (lane >> 2);
    bf16* ob = attn + (size_t)b * SS * DD + h * DHH;
#pragma unroll
    for (int nf = 0; nf < 8; nf++) {
        int c = nf * 8 + (lane & 3) * 2;
        *(bf162*)&ob[(size_t)r0 * DD + c] =
            __floats2bfloat162_rn(o[nf][0] * i0, o[nf][1] * i0);
        *(bf162*)&ob[(size_t)(r0 + 8) * DD + c] =
            __floats2bfloat162_rn(o[nf][2] * i1, o[nf][3] * i1);
    }
}

// ---------------------------------------------------------------------------
// LayerNorm
// ---------------------------------------------------------------------------
__global__ __launch_bounds__(256)
void ln_kernel(const float* __restrict__ y, const float* __restrict__ gamma,
               const float* __restrict__ beta, float* __restrict__ out)
{
    __shared__ float red[16];
    const int row = blockIdx.x;
    const int tid = threadIdx.x;
    const float* yr = y + (size_t)row * DD;

    float4 v = *(const float4*)&yr[tid * 4];
    float s  = v.x + v.y + v.z + v.w;
    float s2 = v.x * v.x + v.y * v.y + v.z * v.z + v.w * v.w;
#pragma unroll
    for (int off = 16; off; off >>= 1) {
        s  += __shfl_xor_sync(0xffffffffu, s,  off);
        s2 += __shfl_xor_sync(0xffffffffu, s2, off);
    }
    const int w = tid >> 5;
    if ((tid & 31) == 0) { red[w] = s; red[w + 8] = s2; }
    __syncthreads();
    s = 0.0f; s2 = 0.0f;
#pragma unroll
    for (int i = 0; i < 8; i++) { s += red[i]; s2 += red[i + 8]; }

    const float mean = s * (1.0f / DD);
    const float var  = s2 * (1.0f / DD) - mean * mean;
    const float inv  = rsqrtf(var + 1e-5f);

    float4 g  = *(const float4*)&gamma[tid * 4];
    float4 bt = *(const float4*)&beta[tid * 4];
    float4 r;
    r.x = (v.x - mean) * inv * g.x + bt.x;
    r.y = (v.y - mean) * inv * g.y + bt.y;
    r.z = (v.z - mean) * inv * g.z + bt.z;
    r.w = (v.w - mean) * inv * g.w + bt.w;
    *(float4*)&out[(size_t)row * DD + tid * 4] = r;
}

// ---------------------------------------------------------------------------
extern "C" void kernel_launch(void* const* d_in, const int* in_sizes, int n_in,
                              void* d_out, int out_size)
{
    (void)in_sizes; (void)n_in; (void)out_size;
    const float* inp   = (const float*)d_in[0];
    const int*   mask  = (const int*)d_in[1];
    const float* Wqkv  = (const float*)d_in[2];
    const float* bqkv  = (const float*)d_in[3];
    const float* Wo    = (const float*)d_in[4];
    const float* gamma = (const float*)d_in[5];
    const float* beta  = (const float*)d_in[6];
    float* out = (float*)d_out;

    bf16 *inpb, *wqkvb, *wob, *qb, *kc, *vc, *attnb;
    float* y;
    int *idx, *cnt;
    cudaGetSymbolAddress((void**)&inpb,  g_inpb);
    cudaGetSymbolAddress((void**)&wqkvb, g_wqkvb);
    cudaGetSymbolAddress((void**)&wob,   g_wob);
    cudaGetSymbolAddress((void**)&qb,    g_qb);
    cudaGetSymbolAddress((void**)&kc,    g_kc);
    cudaGetSymbolAddress((void**)&vc,    g_vc);
    cudaGetSymbolAddress((void**)&attnb, g_attnb);
    cudaGetSymbolAddress((void**)&y,     g_y);
    cudaGetSymbolAddress((void**)&idx,   g_idx);
    cudaGetSymbolAddress((void**)&cnt,   g_cnt);

    cudaFuncSetAttribute(hgemm_nt<true, false, true>,
                         cudaFuncAttributeMaxDynamicSharedMemorySize, GSMEM_BYTES);
    cudaFuncSetAttribute(hgemm_nt<false, true, false>,
                         cudaFuncAttributeMaxDynamicSharedMemorySize, GSMEM_BYTES);
    cudaFuncSetAttribute(kv_gemm,
                         cudaFuncAttributeMaxDynamicSharedMemorySize, GSMEM_BYTES);
    cudaFuncSetAttribute(flash_bf16,
                         cudaFuncAttributeMaxDynamicSharedMemorySize, FSMEM_BYTES);

    // 0) conversions + key compaction index
    f2bf<<<(MTOK * DD) / 1024, 256>>>(inp,  inpb,  MTOK * DD);
    f2bf<<<(NQKV * DD) / 1024, 256>>>(Wqkv, wqkvb, NQKV * DD);
    f2bf<<<(DD * DD)   / 1024, 256>>>(Wo,   wob,   DD * DD);
    compact_k<<<BB, 256>>>(mask, idx, cnt);

    // 1a) Q = inp @ Wq^T + bq          -> bf16 [8192, 1024]
    hgemm_nt<true, false, true><<<dim3(DD / 256, MTOK / 128), 256, GSMEM_BYTES>>>(
        inpb, wqkvb, bqkv, nullptr, qb, MTOK, DD, DD);

    // 1b) compact K/V = inp[idx] @ Wkv^T + bkv  -> kc/vc (gather fused)
    kv_gemm<<<dim3(2 * DD / 256, SS / 128, BB), 256, GSMEM_BYTES>>>(
        inpb, wqkvb + (size_t)DD * DD, bqkv + DD, idx, cnt, kc, vc);

    // 2) attention over ~cnt keys -> bf16 [8192, 1024]
    flash_bf16<<<dim3(BB * HH, SS / 128), 256, FSMEM_BYTES>>>(qb, kc, vc, cnt, attnb);

    // 3) y = inp + attn @ Wo^T  -> fp32 [8192, 1024]
    hgemm_nt<false, true, false><<<dim3(DD / 256, MTOK / 128), 256, GSMEM_BYTES>>>(
        attnb, wob, nullptr, inp, y, MTOK, DD, DD);

    // 4) out = LayerNorm(y)
    ln_kernel<<<MTOK, 256>>>(y, gamma, beta, out);
}

// round 13
// speedup vs baseline: 9.9938x; 1.0365x over previous
#include <cuda_runtime.h>
#include <cuda_bf16.h>
#include <cstdint>

#define BB   4
#define SS   2048
#define DD   1024
#define HH   16
#define DHH  64
#define MTOK (BB * SS)          // 8192
#define NQKV (3 * HH * DHH)     // 3072

typedef __nv_bfloat16  bf16;
typedef __nv_bfloat162 bf162;

// ---------------------------------------------------------------------------
// Scratch (static __device__ arrays; no allocation allowed)
// ---------------------------------------------------------------------------
__device__ bf16  g_inpb [(size_t)MTOK * DD];     // 16 MB
__device__ bf16  g_wqkvb[(size_t)NQKV * DD];     // 6 MB
__device__ bf16  g_wob  [(size_t)DD * DD];       // 2 MB
__device__ bf16  g_qb   [(size_t)MTOK * DD];     // 16 MB  Q projections
__device__ bf16  g_kc   [(size_t)MTOK * DD];     // 16 MB  compact K
__device__ bf16  g_vc   [(size_t)MTOK * DD];     // 16 MB  compact V
__device__ bf16  g_attnb[(size_t)MTOK * DD];     // 16 MB
__device__ float g_y    [(size_t)MTOK * DD];     // 32 MB
__device__ int   g_idx  [BB * SS];
__device__ int   g_cnt  [BB];

// ---------------------------------------------------------------------------
// Helpers: ldmatrix / mma.sync (sm_80 PTX) + cp.async
// ---------------------------------------------------------------------------
__device__ __forceinline__ uint32_t su32(const void* p) {
    return (uint32_t)__cvta_generic_to_shared(p);
}
__device__ __forceinline__ void ldm4(uint32_t& r0, uint32_t& r1, uint32_t& r2,
                                     uint32_t& r3, uint32_t a) {
    asm volatile("ldmatrix.sync.aligned.m8n8.x4.shared.b16 {%0,%1,%2,%3},[%4];\n"
                 : "=r"(r0), "=r"(r1), "=r"(r2), "=r"(r3) : "r"(a));
}
__device__ __forceinline__ void ldm4t(uint32_t& r0, uint32_t& r1, uint32_t& r2,
                                      uint32_t& r3, uint32_t a) {
    asm volatile("ldmatrix.sync.aligned.m8n8.x4.trans.shared.b16 {%0,%1,%2,%3},[%4];\n"
                 : "=r"(r0), "=r"(r1), "=r"(r2), "=r"(r3) : "r"(a));
}
__device__ __forceinline__ void mmabf(float* c, const uint32_t* a,
                                      uint32_t b0, uint32_t b1) {
    asm volatile(
        "mma.sync.aligned.m16n8k16.row.col.f32.bf16.bf16.f32 "
        "{%0,%1,%2,%3},{%4,%5,%6,%7},{%8,%9},{%0,%1,%2,%3};\n"
        : "+f"(c[0]), "+f"(c[1]), "+f"(c[2]), "+f"(c[3])
        : "r"(a[0]), "r"(a[1]), "r"(a[2]), "r"(a[3]), "r"(b0), "r"(b1));
}
__device__ __forceinline__ uint32_t packbf(float x, float y) {
    bf162 t = __floats2bfloat162_rn(x, y);
    return *reinterpret_cast<uint32_t*>(&t);
}
__device__ __forceinline__ void cpa16(uint32_t dst, const void* src) {
    asm volatile("cp.async.cg.shared.global [%0], [%1], 16;\n" :: "r"(dst), "l"(src));
}
#define CPCOMMIT() asm volatile("cp.async.commit_group;\n" ::: "memory")
#define CPWAIT(n)  asm volatile("cp.async.wait_group %0;\n" :: "n"(n) : "memory")

// ---------------------------------------------------------------------------
// Fused preprocessing: 3x f2bf + key compaction, one launch.
// Blocks [0,8192): inp->inpb ; [8192,11264): Wqkv->wqkvb ;
// [11264,12288): Wo->wob ; [12288,12292): compact_k per batch.
// ---------------------------------------------------------------------------
#define PRE_INP  (MTOK * DD / 1024)            // 8192
#define PRE_WQKV (NQKV * DD / 1024)            // 3072
#define PRE_WO   (DD * DD / 1024)              // 1024
#define PRE_TOTAL (PRE_INP + PRE_WQKV + PRE_WO + BB)

__global__ __launch_bounds__(256)
void preproc(const float* __restrict__ inp, const float* __restrict__ Wqkv,
             const float* __restrict__ Wo, const int* __restrict__ mask,
             bf16* __restrict__ inpb, bf16* __restrict__ wqkvb,
             bf16* __restrict__ wob, int* __restrict__ idx, int* __restrict__ cnt)
{
    const int bid = blockIdx.x, tid = threadIdx.x;
    if (bid < PRE_INP + PRE_WQKV + PRE_WO) {
        const float* src; bf16* dst; int blk;
        if (bid < PRE_INP)                 { src = inp;  dst = inpb;  blk = bid; }
        else if (bid < PRE_INP + PRE_WQKV) { src = Wqkv; dst = wqkvb; blk = bid - PRE_INP; }
        else                               { src = Wo;   dst = wob;   blk = bid - PRE_INP - PRE_WQKV; }
        int i = blk * 1024 + tid * 4;
        float4 v = *(const float4*)(src + i);
        bf162* o = (bf162*)(dst + i);
        o[0] = __floats2bfloat162_rn(v.x, v.y);
        o[1] = __floats2bfloat162_rn(v.z, v.w);
        return;
    }
    // --- key compaction for batch b ---
    const int b = bid - (PRE_INP + PRE_WQKV + PRE_WO);
    const int lane = tid & 31, wid = tid >> 5;
    const int* mrow = mask + b * SS;
    __shared__ int ws[8];

    int lm[8], local = 0;
#pragma unroll
    for (int i = 0; i < 8; i++) { lm[i] = (mrow[tid * 8 + i] == 0); local += lm[i]; }

    int inc = local;
#pragma unroll
    for (int off = 1; off < 32; off <<= 1) {
        int n = __shfl_up_sync(0xffffffffu, inc, off);
        if (lane >= off) inc += n;
    }
    if (lane == 31) ws[wid] = inc;
    __syncthreads();
    if (tid == 0) {
        int run = 0;
#pragma unroll
        for (int w = 0; w < 8; w++) { int t = ws[w]; ws[w] = run; run += t; }
        cnt[b] = run;
    }
    __syncthreads();

    int pos = ws[wid] + inc - local;
#pragma unroll
    for (int i = 0; i < 8; i++)
        if (lm[i]) { idx[b * SS + pos] = tid * 8 + i; pos++; }
}

// ---------------------------------------------------------------------------
// GEMM tiling constants: CTA 128x256, 8 warps (2Mx4N), warp tile 64x64,
// K-chunk 64, 3-stage cp.async ring in dynamic smem.
// ---------------------------------------------------------------------------
#define GLD    72
#define A_SZ   (128 * GLD)
#define B_SZ   (256 * GLD)
#define STAGE_ELEMS (A_SZ + B_SZ)
#define GSMEM_BYTES (3 * STAGE_ELEMS * 2)   // 165888

// ---------------------------------------------------------------------------
// Unified QKV GEMM, one launch (back-fills wave tails):
//  blocks [0,256): Q tile:  qb[m0:,n0:] = inpb @ Wq^T + bq        (m over MTOK)
//  blocks [256,768): KV tile (batch b): gathered rows idx[j] @ Wkv^T + bkv
//                    cols<1024 -> kc, else -> vc; zero-pad to cnt ceil.
// Both paths share the identical pipeline via sidx (identity for Q).
// ---------------------------------------------------------------------------
__global__ __launch_bounds__(256, 1)
void qkv_gemm(const bf16* __restrict__ inpb, const bf16* __restrict__ wqkvb,
              const float* __restrict__ bqkv, const int* __restrict__ idx,
              const int* __restrict__ cnt, bf16* __restrict__ qb,
              bf16* __restrict__ kc, bf16* __restrict__ vc)
{
    extern __shared__ __align__(16) bf16 smem[];
    __shared__ int sidx[128];

    const int bid = blockIdx.x;
    const bool isQ = bid < 256;
    const int tid  = threadIdx.x;
    const int wid  = tid >> 5, lane = tid & 31;
    const int wm   = (wid >> 2) << 6;
    const int wn   = (wid & 3) << 6;
    const int r8 = tid >> 3, sg = tid & 7;

    int m0, n0, b = 0, c_ = 0;
    if (isQ) {
        n0 = (bid & 3) << 8;           // 4 n-tiles over 1024
        m0 = (bid >> 2) << 7;          // 64 m-tiles over 8192
    } else {
        const int t = bid - 256;
        b  = t >> 7;                   // 128 tiles per batch
        const int r = t & 127;
        n0 = (r & 7) << 8;             // 8 n-tiles over 2048
        m0 = (r >> 3) << 7;            // 16 m-tiles over 2048
        c_ = cnt[b];
        if (m0 >= ((c_ + 127) & ~127)) return;
    }

    if (tid < 128) {
        int j = m0 + tid;
        sidx[tid] = isQ ? j : ((j < c_) ? idx[b * SS + j] : 0);
    }
    __syncthreads();

    const bf16* A = inpb + (isQ ? 0 : (size_t)b * SS * DD);
    const bf16* W = wqkvb + (isQ ? 0 : (size_t)DD * DD);
    const float* bias = bqkv + (isQ ? 0 : DD);

    float acc[4][8][4];
#pragma unroll
    for (int i = 0; i < 4; i++)
#pragma unroll
        for (int j = 0; j < 8; j++)
#pragma unroll
            for (int e = 0; e < 4; e++) acc[i][j][e] = 0.0f;

    const int nk = DD >> 6;     // K = 1024

    auto load_stage = [&](int kt) {
        bf16* As = smem + (kt % 3) * STAGE_ELEMS;
        bf16* Bs = As + A_SZ;
        const int kofs = kt << 6;
#pragma unroll
        for (int i = 0; i < 4; i++) {
            int r = r8 + i * 32;
            cpa16(su32(&As[r * GLD + sg * 8]),
                  &A[(size_t)sidx[r] * DD + kofs + sg * 8]);
        }
#pragma unroll
        for (int i = 0; i < 8; i++) {
            int r = r8 + i * 32;
            cpa16(su32(&Bs[r * GLD + sg * 8]),
                  &W[(size_t)(n0 + r) * DD + kofs + sg * 8]);
        }
        CPCOMMIT();
    };

    load_stage(0);
    load_stage(1);

    for (int kt = 0; kt < nk; kt++) {
        CPWAIT(1);
        __syncthreads();

        if (kt + 2 < nk) load_stage(kt + 2); else CPCOMMIT();

        const bf16* As = smem + (kt % 3) * STAGE_ELEMS;
        const bf16* Bs = As + A_SZ;

#pragma unroll
        for (int ks = 0; ks < 4; ks++) {
            uint32_t af[4][4], bfr[8][2];
#pragma unroll
            for (int mf = 0; mf < 4; mf++) {
                uint32_t ad = su32(&As[(wm + mf * 16 + (lane & 15)) * GLD +
                                       ks * 16 + (lane >> 4) * 8]);
                ldm4(af[mf][0], af[mf][1], af[mf][2], af[mf][3], ad);
            }
#pragma unroll
            for (int p = 0; p < 4; p++) {
                uint32_t bd = su32(&Bs[(wn + p * 16 + (lane & 7) + ((lane >> 4) << 3)) * GLD +
                                       ks * 16 + ((lane >> 3) & 1) * 8]);
                ldm4(bfr[2 * p][0], bfr[2 * p][1], bfr[2 * p + 1][0], bfr[2 * p + 1][1], bd);
            }
#pragma unroll
            for (int mf = 0; mf < 4; mf++)
#pragma unroll
                for (int nf = 0; nf < 8; nf++)
                    mmabf(acc[mf][nf], af[mf], bfr[nf][0], bfr[nf][1]);
        }
    }

    if (isQ) {
#pragma unroll
        for (int mf = 0; mf < 4; mf++) {
            const int r = m0 + wm + mf * 16 + (lane >> 2);
#pragma unroll
            for (int nf = 0; nf < 8; nf++) {
                const int c = n0 + wn + nf * 8 + (lane & 3) * 2;
                float b0v = bias[c], b1v = bias[c + 1];
                *(bf162*)&qb[(size_t)r * DD + c] =
                    __floats2bfloat162_rn(acc[mf][nf][0] + b0v, acc[mf][nf][1] + b1v);
                *(bf162*)&qb[(size_t)(r + 8) * DD + c] =
                    __floats2bfloat162_rn(acc[mf][nf][2] + b0v, acc[mf][nf][3] + b1v);
            }
        }
    } else {
#pragma unroll
        for (int mf = 0; mf < 4; mf++) {
            const int j = m0 + wm + mf * 16 + (lane >> 2);
#pragma unroll
            for (int nf = 0; nf < 8; nf++) {
                const int c = n0 + wn + nf * 8 + (lane & 3) * 2;   // 0..2047
                float b0v = bias[c], b1v = bias[c + 1];
                float v0 = acc[mf][nf][0] + b0v, v1 = acc[mf][nf][1] + b1v;
                float v2 = acc[mf][nf][2] + b0v, v3 = acc[mf][nf][3] + b1v;
                if (j >= c_)     { v0 = 0.0f; v1 = 0.0f; }
                if (j + 8 >= c_) { v2 = 0.0f; v3 = 0.0f; }
                bf16* dst = (c < DD) ? kc : vc;
                const int cc = (c < DD) ? c : c - DD;
                *(bf162*)&dst[(size_t)(b * SS + j) * DD + cc]     = __floats2bfloat162_rn(v0, v1);
                *(bf162*)&dst[(size_t)(b * SS + j + 8) * DD + cc] = __floats2bfloat162_rn(v2, v3);
            }
        }
    }
}

// ---------------------------------------------------------------------------
// bf16 HGEMM (NT) for out-proj: y = attn @ Wo^T + inp (fp32 out)
// ---------------------------------------------------------------------------
__global__ __launch_bounds__(256, 1)
void hgemm_proj(const bf16* __restrict__ A, const bf16* __restrict__ W,
                const float* __restrict__ res, float* __restrict__ C,
                int M, int N, int K)
{
    extern __shared__ __align__(16) bf16 smem[];

    const int tid  = threadIdx.x;
    const int wid  = tid >> 5, lane = tid & 31;
    const int m0   = blockIdx.y << 7;
    const int n0   = blockIdx.x << 8;
    const int wm   = (wid >> 2) << 6;
    const int wn   = (wid & 3) << 6;
    const int r8 = tid >> 3, sg = tid & 7;

    float acc[4][8][4];
#pragma unroll
    for (int i = 0; i < 4; i++)
#pragma unroll
        for (int j = 0; j < 8; j++)
#pragma unroll
            for (int e = 0; e < 4; e++) acc[i][j][e] = 0.0f;

    const int nk = K >> 6;

    auto load_stage = [&](int kt) {
        bf16* As = smem + (kt % 3) * STAGE_ELEMS;
        bf16* Bs = As + A_SZ;
        const int kofs = kt << 6;
#pragma unroll
        for (int i = 0; i < 4; i++) {
            int r = r8 + i * 32;
            cpa16(su32(&As[r * GLD + sg * 8]),
                  &A[(size_t)(m0 + r) * K + kofs + sg * 8]);
        }
#pragma unroll
        for (int i = 0; i < 8; i++) {
            int r = r8 + i * 32;
            cpa16(su32(&Bs[r * GLD + sg * 8]),
                  &W[(size_t)(n0 + r) * K + kofs + sg * 8]);
        }
        CPCOMMIT();
    };

    load_stage(0);
    load_stage(1);

    for (int kt = 0; kt < nk; kt++) {
        CPWAIT(1);
        __syncthreads();

        if (kt + 2 < nk) load_stage(kt + 2); else CPCOMMIT();

        const bf16* As = smem + (kt % 3) * STAGE_ELEMS;
        const bf16* Bs = As + A_SZ;

#pragma unroll
        for (int ks = 0; ks < 4; ks++) {
            uint32_t af[4][4], bfr[8][2];
#pragma unroll
            for (int mf = 0; mf < 4; mf++) {
                uint32_t ad = su32(&As[(wm + mf * 16 + (lane & 15)) * GLD +
                                       ks * 16 + (lane >> 4) * 8]);
                ldm4(af[mf][0], af[mf][1], af[mf][2], af[mf][3], ad);
            }
#pragma unroll
            for (int p = 0; p < 4; p++) {
                uint32_t bd = su32(&Bs[(wn + p * 16 + (lane & 7) + ((lane >> 4) << 3)) * GLD +
                                       ks * 16 + ((lane >> 3) & 1) * 8]);
                ldm4(bfr[2 * p][0], bfr[2 * p][1], bfr[2 * p + 1][0], bfr[2 * p + 1][1], bd);
            }
#pragma unroll
            for (int mf = 0; mf < 4; mf++)
#pragma unroll
                for (int nf = 0; nf < 8; nf++)
                    mmabf(acc[mf][nf], af[mf], bfr[nf][0], bfr[nf][1]);
        }
    }

#pragma unroll
    for (int mf = 0; mf < 4; mf++) {
        const int r = m0 + wm + mf * 16 + (lane >> 2);
#pragma unroll
        for (int nf = 0; nf < 8; nf++) {
            const int c = n0 + wn + nf * 8 + (lane & 3) * 2;
            float2 q0 = *(const float2*)&res[(size_t)r * N + c];
            float2 q1 = *(const float2*)&res[(size_t)(r + 8) * N + c];
            *(float2*)&C[(size_t)r * N + c] =
                make_float2(acc[mf][nf][0] + q0.x, acc[mf][nf][1] + q0.y);
            *(float2*)&C[(size_t)(r + 8) * N + c] =
                make_float2(acc[mf][nf][2] + q1.x, acc[mf][nf][3] + q1.y);
        }
    }
}

// ---------------------------------------------------------------------------
// bf16 flash attention over COMPACTED keys. Block = (b,h) x 128-query tile,
// 8 warps. 3-stage cp.async ring for K/V, one __syncthreads per key tile.
// ---------------------------------------------------------------------------
#define LQT 72
#define FQ_ELEMS  (128 * LQT)
#define FKV_STAGE (2 * 64 * LQT)
#define FSMEM_BYTES ((FQ_ELEMS + 3 * FKV_STAGE) * 2)   // 73728

__global__ __launch_bounds__(256)
void flash_bf16(const bf16* __restrict__ qp, const bf16* __restrict__ kc,
                const bf16* __restrict__ vc, const int* __restrict__ cnt,
                bf16* __restrict__ attn)
{
    extern __shared__ __align__(16) bf16 fsm[];
    bf16* Qs = fsm;

    const int tid = threadIdx.x, wid = tid >> 5, lane = tid & 31;
    const int b = blockIdx.x >> 4, h = blockIdx.x & 15;
    const int q0 = blockIdx.y << 7;

    const int c_ = cnt[b];
    const int T = ((c_ + 63) & ~63) >> 6;

    const bf16* qb  = qp + (size_t)(b * SS + q0) * DD + h * DHH;
    const bf16* kcb = kc + (size_t)b * SS * DD + h * DHH;
    const bf16* vcb = vc + (size_t)b * SS * DD + h * DHH;

    auto load_kv = [&](int t) {
        bf16* Ks = fsm + FQ_ELEMS + (t % 3) * FKV_STAGE;
        bf16* Vs = Ks + 64 * LQT;
        const int kb0 = t << 6;
#pragma unroll
        for (int i = 0; i < 2; i++) {
            int e = i * 256 + tid, r = e >> 3, sgq = e & 7;
            cpa16(su32(&Ks[r * LQT + sgq * 8]), &kcb[(size_t)(kb0 + r) * DD + sgq * 8]);
            cpa16(su32(&Vs[r * LQT + sgq * 8]), &vcb[(size_t)(kb0 + r) * DD + sgq * 8]);
        }
        CPCOMMIT();
    };

    load_kv(0);
    if (T > 1) load_kv(1); else CPCOMMIT();

#pragma unroll
    for (int i = 0; i < 4; i++) {
        int e = i * 256 + tid, r = e >> 3, sgq = e & 7;
        *(uint4*)&Qs[r * LQT + sgq * 8] = *(const uint4*)&qb[(size_t)r * DD + sgq * 8];
    }
    __syncthreads();

    uint32_t qf[4][4];
#pragma unroll
    for (int ks = 0; ks < 4; ks++) {
        uint32_t ad = su32(&Qs[(wid * 16 + (lane & 15)) * LQT + ks * 16 + (lane >> 4) * 8]);
        ldm4(qf[ks][0], qf[ks][1], qf[ks][2], qf[ks][3], ad);
    }

    float m0v = -1e30f, m1v = -1e30f, l0 = 0.0f, l1 = 0.0f;
    float o[8][4];
#pragma unroll
    for (int nf = 0; nf < 8; nf++)
#pragma unroll
        for (int e = 0; e < 4; e++) o[nf][e] = 0.0f;

    for (int t = 0; t < T; t++) {
        CPWAIT(1);
        __syncthreads();
        if (t + 2 < T) load_kv(t + 2); else CPCOMMIT();

        const bf16* Ks = fsm + FQ_ELEMS + (t % 3) * FKV_STAGE;
        const bf16* Vs = Ks + 64 * LQT;
        const int kb0 = t << 6;

        float sv[8][4];
#pragma unroll
        for (int nf = 0; nf < 8; nf++)
#pragma unroll
            for (int e = 0; e < 4; e++) sv[nf][e] = 0.0f;

#pragma unroll
        for (int ks = 0; ks < 4; ks++) {
            uint32_t kf[8][2];
#pragma unroll
            for (int p = 0; p < 4; p++) {
                uint32_t bd = su32(&Ks[(p * 16 + (lane & 7) + ((lane >> 4) << 3)) * LQT +
                                       ks * 16 + ((lane >> 3) & 1) * 8]);
                ldm4(kf[2 * p][0], kf[2 * p][1], kf[2 * p + 1][0], kf[2 * p + 1][1], bd);
            }
#pragma unroll
            for (int nf = 0; nf < 8; nf++)
                mmabf(sv[nf], qf[ks], kf[nf][0], kf[nf][1]);
        }

        const int c2 = (lane & 3) * 2;
#pragma unroll
        for (int nf = 0; nf < 8; nf++) {
            int kidx = kb0 + nf * 8 + c2;
            bool v0 = kidx < c_, v1 = (kidx + 1) < c_;
            sv[nf][0] = v0 ? sv[nf][0] * 0.125f : -1e30f;
            sv[nf][1] = v1 ? sv[nf][1] * 0.125f : -1e30f;
            sv[nf][2] = v0 ? sv[nf][2] * 0.125f : -1e30f;
            sv[nf][3] = v1 ? sv[nf][3] * 0.125f : -1e30f;
        }

        float mx0 = -1e30f, mx1 = -1e30f;
#pragma unroll
        for (int nf = 0; nf < 8; nf++) {
            mx0 = fmaxf(mx0, fmaxf(sv[nf][0], sv[nf][1]));
            mx1 = fmaxf(mx1, fmaxf(sv[nf][2], sv[nf][3]));
        }
        mx0 = fmaxf(mx0, __shfl_xor_sync(0xffffffffu, mx0, 1));
        mx0 = fmaxf(mx0, __shfl_xor_sync(0xffffffffu, mx0, 2));
        mx1 = fmaxf(mx1, __shfl_xor_sync(0xffffffffu, mx1, 1));
        mx1 = fmaxf(mx1, __shfl_xor_sync(0xffffffffu, mx1, 2));

        float mn0 = fmaxf(m0v, mx0), mn1 = fmaxf(m1v, mx1);
        float al0 = __expf(m0v - mn0), al1 = __expf(m1v - mn1);
        m0v = mn0; m1v = mn1;

        float sum0 = 0.0f, sum1 = 0.0f;
#pragma unroll
        for (int nf = 0; nf < 8; nf++) {
            sv[nf][0] = __expf(sv[nf][0] - mn0);
            sv[nf][1] = __expf(sv[nf][1] - mn0);
            sv[nf][2] = __expf(sv[nf][2] - mn1);
            sv[nf][3] = __expf(sv[nf][3] - mn1);
            sum0 += sv[nf][0] + sv[nf][1];
            sum1 += sv[nf][2] + sv[nf][3];
        }
        sum0 += __shfl_xor_sync(0xffffffffu, sum0, 1);
        sum0 += __shfl_xor_sync(0xffffffffu, sum0, 2);
        sum1 += __shfl_xor_sync(0xffffffffu, sum1, 1);
        sum1 += __shfl_xor_sync(0xffffffffu, sum1, 2);
        l0 = l0 * al0 + sum0;
        l1 = l1 * al1 + sum1;
#pragma unroll
        for (int nf = 0; nf < 8; nf++) {
            o[nf][0] *= al0; o[nf][1] *= al0;
            o[nf][2] *= al1; o[nf][3] *= al1;
        }

#pragma unroll
        for (int ks = 0; ks < 4; ks++) {
            uint32_t pa[4];
            pa[0] = packbf(sv[2 * ks][0],     sv[2 * ks][1]);
            pa[1] = packbf(sv[2 * ks][2],     sv[2 * ks][3]);
            pa[2] = packbf(sv[2 * ks + 1][0], sv[2 * ks + 1][1]);
            pa[3] = packbf(sv[2 * ks + 1][2], sv[2 * ks + 1][3]);
#pragma unroll
            for (int p = 0; p < 4; p++) {
                uint32_t v0, v1, v2, v3;
                uint32_t vd = su32(&Vs[(ks * 16 + (lane & 7) + (((lane >> 3) & 1) << 3)) * LQT +
                                       p * 16 + ((lane >> 4) << 3)]);
                ldm4t(v0, v1, v2, v3, vd);
                mmabf(o[2 * p],     pa, v0, v1);
                mmabf(o[2 * p + 1], pa, v2, v3);
            }
        }
    }

    const float i0 = 1.0f / l0, i1 = 1.0f / l1;
    const int r0 = q0 + wid * 16 + (lane >> 2);
    bf16* ob = attn + (size_t)b * SS * DD + h * DHH;
#pragma unroll
    for (int nf = 0; nf < 8; nf++) {
        int c = nf * 8 + (lane & 3) * 2;
        *(bf162*)&ob[(size_t)r0 * DD + c] =
            __floats2bfloat162_rn(o[nf][0] * i0, o[nf][1] * i0);
        *(bf162*)&ob[(size_t)(r0 + 8) * DD + c] =
            __floats2bfloat162_rn(o[nf][2] * i1, o[nf][3] * i1);
    }
}

// ---------------------------------------------------------------------------
// LayerNorm: one WARP per row (8 rows/block, no smem, no block sync).
// ---------------------------------------------------------------------------
__global__ __launch_bounds__(256)
void ln_kernel(const float* __restrict__ y, const float* __restrict__ gamma,
               const float* __restrict__ beta, float* __restrict__ out)
{
    const int wid = threadIdx.x >> 5, lane = threadIdx.x & 31;
    const int row = blockIdx.x * 8 + wid;
    const float* yr = y + (size_t)row * DD;

    float4 v[8];
    float s = 0.0f, s2 = 0.0f;
#pragma unroll
    for (int i = 0; i < 8; i++) {
        v[i] = *(const float4*)&yr[lane * 4 + i * 128];
        s  += v[i].x + v[i].y + v[i].z + v[i].w;
        s2 += v[i].x * v[i].x + v[i].y * v[i].y + v[i].z * v[i].z + v[i].w * v[i].w;
    }
#pragma unroll
    for (int off = 16; off; off >>= 1) {
        s  += __shfl_xor_sync(0xffffffffu, s,  off);
        s2 += __shfl_xor_sync(0xffffffffu, s2, off);
    }

    const float mean = s * (1.0f / DD);
    const float var  = s2 * (1.0f / DD) - mean * mean;
    const float inv  = rsqrtf(var + 1e-5f);

#pragma unroll
    for (int i = 0; i < 8; i++) {
        const int c = lane * 4 + i * 128;
        float4 g  = *(const float4*)&gamma[c];
        float4 bt = *(const float4*)&beta[c];
        float4 r;
        r.x = (v[i].x - mean) * inv * g.x + bt.x;
        r.y = (v[i].y - mean) * inv * g.y + bt.y;
        r.z = (v[i].z - mean) * inv * g.z + bt.z;
        r.w = (v[i].w - mean) * inv * g.w + bt.w;
        *(float4*)&out[(size_t)row * DD + c] = r;
    }
}

// ---------------------------------------------------------------------------
extern "C" void kernel_launch(void* const* d_in, const int* in_sizes, int n_in,
                              void* d_out, int out_size)
{
    (void)in_sizes; (void)n_in; (void)out_size;
    const float* inp   = (const float*)d_in[0];
    const int*   mask  = (const int*)d_in[1];
    const float* Wqkv  = (const float*)d_in[2];
    const float* bqkv  = (const float*)d_in[3];
    const float* Wo    = (const float*)d_in[4];
    const float* gamma = (const float*)d_in[5];
    const float* beta  = (const float*)d_in[6];
    float* out = (float*)d_out;

    bf16 *inpb, *wqkvb, *wob, *qb, *kc, *vc, *attnb;
    float* y;
    int *idx, *cnt;
    cudaGetSymbolAddress((void**)&inpb,  g_inpb);
    cudaGetSymbolAddress((void**)&wqkvb, g_wqkvb);
    cudaGetSymbolAddress((void**)&wob,   g_wob);
    cudaGetSymbolAddress((void**)&qb,    g_qb);
    cudaGetSymbolAddress((void**)&kc,    g_kc);
    cudaGetSymbolAddress((void**)&vc,    g_vc);
    cudaGetSymbolAddress((void**)&attnb, g_attnb);
    cudaGetSymbolAddress((void**)&y,     g_y);
    cudaGetSymbolAddress((void**)&idx,   g_idx);
    cudaGetSymbolAddress((void**)&cnt,   g_cnt);

    cudaFuncSetAttribute(qkv_gemm,
                         cudaFuncAttributeMaxDynamicSharedMemorySize, GSMEM_BYTES);
    cudaFuncSetAttribute(hgemm_proj,
                         cudaFuncAttributeMaxDynamicSharedMemorySize, GSMEM_BYTES);
    cudaFuncSetAttribute(flash_bf16,
                         cudaFuncAttributeMaxDynamicSharedMemorySize, FSMEM_BYTES);

    // 0) fused conversions + key compaction (one launch)
    preproc<<<PRE_TOTAL, 256>>>(inp, Wqkv, Wo, mask, inpb, wqkvb, wob, idx, cnt);

    // 1) unified Q + gathered-KV GEMM (one launch, tail back-fill)
    qkv_gemm<<<768, 256, GSMEM_BYTES>>>(inpb, wqkvb, bqkv, idx, cnt, qb, kc, vc);

    // 2) attention over ~cnt keys -> bf16 [8192, 1024]
    flash_bf16<<<dim3(BB * HH, SS / 128), 256, FSMEM_BYTES>>>(qb, kc, vc, cnt, attnb);

    // 3) y = inp + attn @ Wo^T  -> fp32 [8192, 1024]
    hgemm_proj<<<dim3(DD / 256, MTOK / 128), 256, GSMEM_BYTES>>>(
        attnb, wob, inp, y, MTOK, DD, DD);

    // 4) out = LayerNorm(y)
    ln_kernel<<<MTOK / 8, 256>>>(y, gamma, beta, out);
}

// round 14
// speedup vs baseline: 10.0578x; 1.0064x over previous
#include <cuda_runtime.h>
#include <cuda_bf16.h>
#include <cstdint>

#define BB   4
#define SS   2048
#define DD   1024
#define HH   16
#define DHH  64
#define MTOK (BB * SS)          // 8192
#define NQKV (3 * HH * DHH)     // 3072

typedef __nv_bfloat16  bf16;
typedef __nv_bfloat162 bf162;

// ---------------------------------------------------------------------------
// Scratch (static __device__ arrays; no allocation allowed)
// ---------------------------------------------------------------------------
__device__ bf16  g_inpb [(size_t)MTOK * DD];     // 16 MB
__device__ bf16  g_wqkvb[(size_t)NQKV * DD];     // 6 MB
__device__ bf16  g_wob  [(size_t)DD * DD];       // 2 MB
__device__ bf16  g_qb   [(size_t)MTOK * DD];     // 16 MB  Q projections
__device__ bf16  g_kc   [(size_t)MTOK * DD];     // 16 MB  compact K
__device__ bf16  g_vc   [(size_t)MTOK * DD];     // 16 MB  compact V
__device__ bf16  g_attnb[(size_t)MTOK * DD];     // 16 MB
__device__ float g_y    [(size_t)MTOK * DD];     // 32 MB
__device__ int   g_idx  [BB * SS];
__device__ int   g_cnt  [BB];

// ---------------------------------------------------------------------------
// Helpers: ldmatrix / mma.sync (sm_80 PTX) + cp.async + griddepcontrol (sm_90+)
// ---------------------------------------------------------------------------
__device__ __forceinline__ uint32_t su32(const void* p) {
    return (uint32_t)__cvta_generic_to_shared(p);
}
__device__ __forceinline__ void ldm4(uint32_t& r0, uint32_t& r1, uint32_t& r2,
                                     uint32_t& r3, uint32_t a) {
    asm volatile("ldmatrix.sync.aligned.m8n8.x4.shared.b16 {%0,%1,%2,%3},[%4];\n"
                 : "=r"(r0), "=r"(r1), "=r"(r2), "=r"(r3) : "r"(a));
}
__device__ __forceinline__ void ldm4t(uint32_t& r0, uint32_t& r1, uint32_t& r2,
                                      uint32_t& r3, uint32_t a) {
    asm volatile("ldmatrix.sync.aligned.m8n8.x4.trans.shared.b16 {%0,%1,%2,%3},[%4];\n"
                 : "=r"(r0), "=r"(r1), "=r"(r2), "=r"(r3) : "r"(a));
}
__device__ __forceinline__ void mmabf(float* c, const uint32_t* a,
                                      uint32_t b0, uint32_t b1) {
    asm volatile(
        "mma.sync.aligned.m16n8k16.row.col.f32.bf16.bf16.f32 "
        "{%0,%1,%2,%3},{%4,%5,%6,%7},{%8,%9},{%0,%1,%2,%3};\n"
        : "+f"(c[0]), "+f"(c[1]), "+f"(c[2]), "+f"(c[3])
        : "r"(a[0]), "r"(a[1]), "r"(a[2]), "r"(a[3]), "r"(b0), "r"(b1));
}
__device__ __forceinline__ uint32_t packbf(float x, float y) {
    bf162 t = __floats2bfloat162_rn(x, y);
    return *reinterpret_cast<uint32_t*>(&t);
}
__device__ __forceinline__ void cpa16(uint32_t dst, const void* src) {
    asm volatile("cp.async.cg.shared.global [%0], [%1], 16;\n" :: "r"(dst), "l"(src));
}
#define CPCOMMIT() asm volatile("cp.async.commit_group;\n" ::: "memory")
#define CPWAIT(n)  asm volatile("cp.async.wait_group %0;\n" :: "n"(n) : "memory")
// PDL: wait for upstream completion / allow dependents to launch early.
#define GDWAIT()   asm volatile("griddepcontrol.wait;" ::: "memory")
#define GDTRIG()   asm volatile("griddepcontrol.launch_dependents;" ::: "memory")

// ---------------------------------------------------------------------------
// Fused preprocessing: 3x f2bf + key compaction, one launch.
// ---------------------------------------------------------------------------
#define PRE_INP  (MTOK * DD / 1024)            // 8192
#define PRE_WQKV (NQKV * DD / 1024)            // 3072
#define PRE_WO   (DD * DD / 1024)              // 1024
#define PRE_TOTAL (PRE_INP + PRE_WQKV + PRE_WO + BB)

__global__ __launch_bounds__(256)
void preproc(const float* __restrict__ inp, const float* __restrict__ Wqkv,
             const float* __restrict__ Wo, const int* __restrict__ mask,
             bf16* __restrict__ inpb, bf16* __restrict__ wqkvb,
             bf16* __restrict__ wob, int* __restrict__ idx, int* __restrict__ cnt)
{
    const int bid = blockIdx.x, tid = threadIdx.x;
    if (bid < PRE_INP + PRE_WQKV + PRE_WO) {
        const float* src; bf16* dst; int blk;
        if (bid < PRE_INP)                 { src = inp;  dst = inpb;  blk = bid; }
        else if (bid < PRE_INP + PRE_WQKV) { src = Wqkv; dst = wqkvb; blk = bid - PRE_INP; }
        else                               { src = Wo;   dst = wob;   blk = bid - PRE_INP - PRE_WO - PRE_WQKV + PRE_WO; }
        int i = blk * 1024 + tid * 4;
        float4 v = *(const float4*)(src + i);
        bf162* o = (bf162*)(dst + i);
        o[0] = __floats2bfloat162_rn(v.x, v.y);
        o[1] = __floats2bfloat162_rn(v.z, v.w);
        GDTRIG();
        return;
    }
    // --- key compaction for batch b ---
    const int b = bid - (PRE_INP + PRE_WQKV + PRE_WO);
    const int lane = tid & 31, wid = tid >> 5;
    const int* mrow = mask + b * SS;
    __shared__ int ws[8];

    int lm[8], local = 0;
#pragma unroll
    for (int i = 0; i < 8; i++) { lm[i] = (mrow[tid * 8 + i] == 0); local += lm[i]; }

    int inc = local;
#pragma unroll
    for (int off = 1; off < 32; off <<= 1) {
        int n = __shfl_up_sync(0xffffffffu, inc, off);
        if (lane >= off) inc += n;
    }
    if (lane == 31) ws[wid] = inc;
    __syncthreads();
    if (tid == 0) {
        int run = 0;
#pragma unroll
        for (int w = 0; w < 8; w++) { int t = ws[w]; ws[w] = run; run += t; }
        cnt[b] = run;
    }
    __syncthreads();

    int pos = ws[wid] + inc - local;
#pragma unroll
    for (int i = 0; i < 8; i++)
        if (lm[i]) { idx[b * SS + pos] = tid * 8 + i; pos++; }
    GDTRIG();
}

// ---------------------------------------------------------------------------
// GEMM tiling constants: CTA 128x256, 8 warps (2Mx4N), warp tile 64x64,
// K-chunk 64, 3-stage cp.async ring in dynamic smem.
// ---------------------------------------------------------------------------
#define GLD    72
#define A_SZ   (128 * GLD)
#define B_SZ   (256 * GLD)
#define STAGE_ELEMS (A_SZ + B_SZ)
#define GSMEM_BYTES (3 * STAGE_ELEMS * 2)   // 165888

// ---------------------------------------------------------------------------
// Unified QKV GEMM (blocks [0,256): Q ; [256,768): gathered KV).
// ---------------------------------------------------------------------------
__global__ __launch_bounds__(256, 1)
void qkv_gemm(const bf16* __restrict__ inpb, const bf16* __restrict__ wqkvb,
              const float* __restrict__ bqkv, const int* __restrict__ idx,
              const int* __restrict__ cnt, bf16* __restrict__ qb,
              bf16* __restrict__ kc, bf16* __restrict__ vc)
{
    extern __shared__ __align__(16) bf16 smem[];
    __shared__ int sidx[128];

    GDWAIT();   // upstream (preproc) complete; inputs visible

    const int bid = blockIdx.x;
    const bool isQ = bid < 256;
    const int tid  = threadIdx.x;
    const int wid  = tid >> 5, lane = tid & 31;
    const int wm   = (wid >> 2) << 6;
    const int wn   = (wid & 3) << 6;
    const int r8 = tid >> 3, sg = tid & 7;

    int m0, n0, b = 0, c_ = 0;
    if (isQ) {
        n0 = (bid & 3) << 8;
        m0 = (bid >> 2) << 7;
    } else {
        const int t = bid - 256;
        b  = t >> 7;
        const int r = t & 127;
        n0 = (r & 7) << 8;
        m0 = (r >> 3) << 7;
        c_ = cnt[b];
        if (m0 >= ((c_ + 127) & ~127)) { GDTRIG(); return; }
    }

    if (tid < 128) {
        int j = m0 + tid;
        sidx[tid] = isQ ? j : ((j < c_) ? idx[b * SS + j] : 0);
    }
    __syncthreads();

    const bf16* A = inpb + (isQ ? 0 : (size_t)b * SS * DD);
    const bf16* W = wqkvb + (isQ ? 0 : (size_t)DD * DD);
    const float* bias = bqkv + (isQ ? 0 : DD);

    float acc[4][8][4];
#pragma unroll
    for (int i = 0; i < 4; i++)
#pragma unroll
        for (int j = 0; j < 8; j++)
#pragma unroll
            for (int e = 0; e < 4; e++) acc[i][j][e] = 0.0f;

    const int nk = DD >> 6;

    auto load_stage = [&](int kt) {
        bf16* As = smem + (kt % 3) * STAGE_ELEMS;
        bf16* Bs = As + A_SZ;
        const int kofs = kt << 6;
#pragma unroll
        for (int i = 0; i < 4; i++) {
            int r = r8 + i * 32;
            cpa16(su32(&As[r * GLD + sg * 8]),
                  &A[(size_t)sidx[r] * DD + kofs + sg * 8]);
        }
#pragma unroll
        for (int i = 0; i < 8; i++) {
            int r = r8 + i * 32;
            cpa16(su32(&Bs[r * GLD + sg * 8]),
                  &W[(size_t)(n0 + r) * DD + kofs + sg * 8]);
        }
        CPCOMMIT();
    };

    load_stage(0);
    load_stage(1);

    for (int kt = 0; kt < nk; kt++) {
        CPWAIT(1);
        __syncthreads();

        if (kt + 2 < nk) load_stage(kt + 2); else CPCOMMIT();

        const bf16* As = smem + (kt % 3) * STAGE_ELEMS;
        const bf16* Bs = As + A_SZ;

#pragma unroll
        for (int ks = 0; ks < 4; ks++) {
            uint32_t af[4][4], bfr[8][2];
#pragma unroll
            for (int mf = 0; mf < 4; mf++) {
                uint32_t ad = su32(&As[(wm + mf * 16 + (lane & 15)) * GLD +
                                       ks * 16 + (lane >> 4) * 8]);
                ldm4(af[mf][0], af[mf][1], af[mf][2], af[mf][3], ad);
            }
#pragma unroll
            for (int p = 0; p < 4; p++) {
                uint32_t bd = su32(&Bs[(wn + p * 16 + (lane & 7) + ((lane >> 4) << 3)) * GLD +
                                       ks * 16 + ((lane >> 3) & 1) * 8]);
                ldm4(bfr[2 * p][0], bfr[2 * p][1], bfr[2 * p + 1][0], bfr[2 * p + 1][1], bd);
            }
#pragma unroll
            for (int mf = 0; mf < 4; mf++)
#pragma unroll
                for (int nf = 0; nf < 8; nf++)
                    mmabf(acc[mf][nf], af[mf], bfr[nf][0], bfr[nf][1]);
        }
    }

    GDTRIG();   // dependents may get resident while we run the epilogue

    if (isQ) {
#pragma unroll
        for (int mf = 0; mf < 4; mf++) {
            const int r = m0 + wm + mf * 16 + (lane >> 2);
#pragma unroll
            for (int nf = 0; nf < 8; nf++) {
                const int c = n0 + wn + nf * 8 + (lane & 3) * 2;
                float b0v = bias[c], b1v = bias[c + 1];
                *(bf162*)&qb[(size_t)r * DD + c] =
                    __floats2bfloat162_rn(acc[mf][nf][0] + b0v, acc[mf][nf][1] + b1v);
                *(bf162*)&qb[(size_t)(r + 8) * DD + c] =
                    __floats2bfloat162_rn(acc[mf][nf][2] + b0v, acc[mf][nf][3] + b1v);
            }
        }
    } else {
#pragma unroll
        for (int mf = 0; mf < 4; mf++) {
            const int j = m0 + wm + mf * 16 + (lane >> 2);
#pragma unroll
            for (int nf = 0; nf < 8; nf++) {
                const int c = n0 + wn + nf * 8 + (lane & 3) * 2;
                float b0v = bias[c], b1v = bias[c + 1];
                float v0 = acc[mf][nf][0] + b0v, v1 = acc[mf][nf][1] + b1v;
                float v2 = acc[mf][nf][2] + b0v, v3 = acc[mf][nf][3] + b1v;
                if (j >= c_)     { v0 = 0.0f; v1 = 0.0f; }
                if (j + 8 >= c_) { v2 = 0.0f; v3 = 0.0f; }
                bf16* dst = (c < DD) ? kc : vc;
                const int cc = (c < DD) ? c : c - DD;
                *(bf162*)&dst[(size_t)(b * SS + j) * DD + cc]     = __floats2bfloat162_rn(v0, v1);
                *(bf162*)&dst[(size_t)(b * SS + j + 8) * DD + cc] = __floats2bfloat162_rn(v2, v3);
            }
        }
    }
}

// ---------------------------------------------------------------------------
// bf16 HGEMM (NT) for out-proj: y = attn @ Wo^T + inp (fp32 out)
// ---------------------------------------------------------------------------
__global__ __launch_bounds__(256, 1)
void hgemm_proj(const bf16* __restrict__ A, const bf16* __restrict__ W,
                const float* __restrict__ res, float* __restrict__ C,
                int M, int N, int K)
{
    extern __shared__ __align__(16) bf16 smem[];

    GDWAIT();

    const int tid  = threadIdx.x;
    const int wid  = tid >> 5, lane = tid & 31;
    const int m0   = blockIdx.y << 7;
    const int n0   = blockIdx.x << 8;
    const int wm   = (wid >> 2) << 6;
    const int wn   = (wid & 3) << 6;
    const int r8 = tid >> 3, sg = tid & 7;

    float acc[4][8][4];
#pragma unroll
    for (int i = 0; i < 4; i++)
#pragma unroll
        for (int j = 0; j < 8; j++)
#pragma unroll
            for (int e = 0; e < 4; e++) acc[i][j][e] = 0.0f;

    const int nk = K >> 6;

    auto load_stage = [&](int kt) {
        bf16* As = smem + (kt % 3) * STAGE_ELEMS;
        bf16* Bs = As + A_SZ;
        const int kofs = kt << 6;
#pragma unroll
        for (int i = 0; i < 4; i++) {
            int r = r8 + i * 32;
            cpa16(su32(&As[r * GLD + sg * 8]),
                  &A[(size_t)(m0 + r) * K + kofs + sg * 8]);
        }
#pragma unroll
        for (int i = 0; i < 8; i++) {
            int r = r8 + i * 32;
            cpa16(su32(&Bs[r * GLD + sg * 8]),
                  &W[(size_t)(n0 + r) * K + kofs + sg * 8]);
        }
        CPCOMMIT();
    };

    load_stage(0);
    load_stage(1);

    for (int kt = 0; kt < nk; kt++) {
        CPWAIT(1);
        __syncthreads();

        if (kt + 2 < nk) load_stage(kt + 2); else CPCOMMIT();

        const bf16* As = smem + (kt % 3) * STAGE_ELEMS;
        const bf16* Bs = As + A_SZ;

#pragma unroll
        for (int ks = 0; ks < 4; ks++) {
            uint32_t af[4][4], bfr[8][2];
#pragma unroll
            for (int mf = 0; mf < 4; mf++) {
                uint32_t ad = su32(&As[(wm + mf * 16 + (lane & 15)) * GLD +
                                       ks * 16 + (lane >> 4) * 8]);
                ldm4(af[mf][0], af[mf][1], af[mf][2], af[mf][3], ad);
            }
#pragma unroll
            for (int p = 0; p < 4; p++) {
                uint32_t bd = su32(&Bs[(wn + p * 16 + (lane & 7) + ((lane >> 4) << 3)) * GLD +
                                       ks * 16 + ((lane >> 3) & 1) * 8]);
                ldm4(bfr[2 * p][0], bfr[2 * p][1], bfr[2 * p + 1][0], bfr[2 * p + 1][1], bd);
            }
#pragma unroll
            for (int mf = 0; mf < 4; mf++)
#pragma unroll
                for (int nf = 0; nf < 8; nf++)
                    mmabf(acc[mf][nf], af[mf], bfr[nf][0], bfr[nf][1]);
        }
    }

    GDTRIG();

#pragma unroll
    for (int mf = 0; mf < 4; mf++) {
        const int r = m0 + wm + mf * 16 + (lane >> 2);
#pragma unroll
        for (int nf = 0; nf < 8; nf++) {
            const int c = n0 + wn + nf * 8 + (lane & 3) * 2;
            float2 q0 = *(const float2*)&res[(size_t)r * N + c];
            float2 q1 = *(const float2*)&res[(size_t)(r + 8) * N + c];
            *(float2*)&C[(size_t)r * N + c] =
                make_float2(acc[mf][nf][0] + q0.x, acc[mf][nf][1] + q0.y);
            *(float2*)&C[(size_t)(r + 8) * N + c] =
                make_float2(acc[mf][nf][2] + q1.x, acc[mf][nf][3] + q1.y);
        }
    }
}

// ---------------------------------------------------------------------------
// bf16 flash attention over COMPACTED keys (3-stage cp.async K/V ring).
// ---------------------------------------------------------------------------
#define LQT 72
#define FQ_ELEMS  (128 * LQT)
#define FKV_STAGE (2 * 64 * LQT)
#define FSMEM_BYTES ((FQ_ELEMS + 3 * FKV_STAGE) * 2)   // 73728

__global__ __launch_bounds__(256)
void flash_bf16(const bf16* __restrict__ qp, const bf16* __restrict__ kc,
                const bf16* __restrict__ vc, const int* __restrict__ cnt,
                bf16* __restrict__ attn)
{
    extern __shared__ __align__(16) bf16 fsm[];
    bf16* Qs = fsm;

    GDWAIT();

    const int tid = threadIdx.x, wid = tid >> 5, lane = tid & 31;
    const int b = blockIdx.x >> 4, h = blockIdx.x & 15;
    const int q0 = blockIdx.y << 7;

    const int c_ = cnt[b];
    const int T = ((c_ + 63) & ~63) >> 6;

    const bf16* qb  = qp + (size_t)(b * SS + q0) * DD + h * DHH;
    const bf16* kcb = kc + (size_t)b * SS * DD + h * DHH;
    const bf16* vcb = vc + (size_t)b * SS * DD + h * DHH;

    auto load_kv = [&](int t) {
        bf16* Ks = fsm + FQ_ELEMS + (t % 3) * FKV_STAGE;
        bf16* Vs = Ks + 64 * LQT;
        const int kb0 = t << 6;
#pragma unroll
        for (int i = 0; i < 2; i++) {
            int e = i * 256 + tid, r = e >> 3, sgq = e & 7;
            cpa16(su32(&Ks[r * LQT + sgq * 8]), &kcb[(size_t)(kb0 + r) * DD + sgq * 8]);
            cpa16(su32(&Vs[r * LQT + sgq * 8]), &vcb[(size_t)(kb0 + r) * DD + sgq * 8]);
        }
        CPCOMMIT();
    };

    load_kv(0);
    if (T > 1) load_kv(1); else CPCOMMIT();

#pragma unroll
    for (int i = 0; i < 4; i++) {
        int e = i * 256 + tid, r = e >> 3, sgq = e & 7;
        *(uint4*)&Qs[r * LQT + sgq * 8] = *(const uint4*)&qb[(size_t)r * DD + sgq * 8];
    }
    __syncthreads();

    uint32_t qf[4][4];
#pragma unroll
    for (int ks = 0; ks < 4; ks++) {
        uint32_t ad = su32(&Qs[(wid * 16 + (lane & 15)) * LQT + ks * 16 + (lane >> 4) * 8]);
        ldm4(qf[ks][0], qf[ks][1], qf[ks][2], qf[ks][3], ad);
    }

    float m0v = -1e30f, m1v = -1e30f, l0 = 0.0f, l1 = 0.0f;
    float o[8][4];
#pragma unroll
    for (int nf = 0; nf < 8; nf++)
#pragma unroll
        for (int e = 0; e < 4; e++) o[nf][e] = 0.0f;

    for (int t = 0; t < T; t++) {
        CPWAIT(1);
        __syncthreads();
        if (t + 2 < T) load_kv(t + 2); else CPCOMMIT();

        const bf16* Ks = fsm + FQ_ELEMS + (t % 3) * FKV_STAGE;
        const bf16* Vs = Ks + 64 * LQT;
        const int kb0 = t << 6;

        float sv[8][4];
#pragma unroll
        for (int nf = 0; nf < 8; nf++)
#pragma unroll
            for (int e = 0; e < 4; e++) sv[nf][e] = 0.0f;

#pragma unroll
        for (int ks = 0; ks < 4; ks++) {
            uint32_t kf[8][2];
#pragma unroll
            for (int p = 0; p < 4; p++) {
                uint32_t bd = su32(&Ks[(p * 16 + (lane & 7) + ((lane >> 4) << 3)) * LQT +
                                       ks * 16 + ((lane >> 3) & 1) * 8]);
                ldm4(kf[2 * p][0], kf[2 * p][1], kf[2 * p + 1][0], kf[2 * p + 1][1], bd);
            }
#pragma unroll
            for (int nf = 0; nf < 8; nf++)
                mmabf(sv[nf], qf[ks], kf[nf][0], kf[nf][1]);
        }

        const int c2 = (lane & 3) * 2;
#pragma unroll
        for (int nf = 0; nf < 8; nf++) {
            int kidx = kb0 + nf * 8 + c2;
            bool v0 = kidx < c_, v1 = (kidx + 1) < c_;
            sv[nf][0] = v0 ? sv[nf][0] * 0.125f : -1e30f;
            sv[nf][1] = v1 ? sv[nf][1] * 0.125f : -1e30f;
            sv[nf][2] = v0 ? sv[nf][2] * 0.125f : -1e30f;
            sv[nf][3] = v1 ? sv[nf][3] * 0.125f : -1e30f;
        }

        float mx0 = -1e30f, mx1 = -1e30f;
#pragma unroll
        for (int nf = 0; nf < 8; nf++) {
            mx0 = fmaxf(mx0, fmaxf(sv[nf][0], sv[nf][1]));
            mx1 = fmaxf(mx1, fmaxf(sv[nf][2], sv[nf][3]));
        }
        mx0 = fmaxf(mx0, __shfl_xor_sync(0xffffffffu, mx0, 1));
        mx0 = fmaxf(mx0, __shfl_xor_sync(0xffffffffu, mx0, 2));
        mx1 = fmaxf(mx1, __shfl_xor_sync(0xffffffffu, mx1, 1));
        mx1 = fmaxf(mx1, __shfl_xor_sync(0xffffffffu, mx1, 2));

        float mn0 = fmaxf(m0v, mx0), mn1 = fmaxf(m1v, mx1);
        float al0 = __expf(m0v - mn0), al1 = __expf(m1v - mn1);
        m0v = mn0; m1v = mn1;

        float sum0 = 0.0f, sum1 = 0.0f;
#pragma unroll
        for (int nf = 0; nf < 8; nf++) {
            sv[nf][0] = __expf(sv[nf][0] - mn0);
            sv[nf][1] = __expf(sv[nf][1] - mn0);
            sv[nf][2] = __expf(sv[nf][2] - mn1);
            sv[nf][3] = __expf(sv[nf][3] - mn1);
            sum0 += sv[nf][0] + sv[nf][1];
            sum1 += sv[nf][2] + sv[nf][3];
        }
        sum0 += __shfl_xor_sync(0xffffffffu, sum0, 1);
        sum0 += __shfl_xor_sync(0xffffffffu, sum0, 2);
        sum1 += __shfl_xor_sync(0xffffffffu, sum1, 1);
        sum1 += __shfl_xor_sync(0xffffffffu, sum1, 2);
        l0 = l0 * al0 + sum0;
        l1 = l1 * al1 + sum1;
#pragma unroll
        for (int nf = 0; nf < 8; nf++) {
            o[nf][0] *= al0; o[nf][1] *= al0;
            o[nf][2] *= al1; o[nf][3] *= al1;
        }

#pragma unroll
        for (int ks = 0; ks < 4; ks++) {
            uint32_t pa[4];
            pa[0] = packbf(sv[2 * ks][0],     sv[2 * ks][1]);
            pa[1] = packbf(sv[2 * ks][2],     sv[2 * ks][3]);
            pa[2] = packbf(sv[2 * ks + 1][0], sv[2 * ks + 1][1]);
            pa[3] = packbf(sv[2 * ks + 1][2], sv[2 * ks + 1][3]);
#pragma unroll
            for (int p = 0; p < 4; p++) {
                uint32_t v0, v1, v2, v3;
                uint32_t vd = su32(&Vs[(ks * 16 + (lane & 7) + (((lane >> 3) & 1) << 3)) * LQT +
                                       p * 16 + ((lane >> 4) << 3)]);
                ldm4t(v0, v1, v2, v3, vd);
                mmabf(o[2 * p],     pa, v0, v1);
                mmabf(o[2 * p + 1], pa, v2, v3);
            }
        }
    }

    GDTRIG();

    const float i0 = 1.0f / l0, i1 = 1.0f / l1;
    const int r0 = q0 + wid * 16 + (lane >> 2);
    bf16* ob = attn + (size_t)b * SS * DD + h * DHH;
#pragma unroll
    for (int nf = 0; nf < 8; nf++) {
        int c = nf * 8 + (lane & 3) * 2;
        *(bf162*)&ob[(size_t)r0 * DD + c] =
            __floats2bfloat162_rn(o[nf][0] * i0, o[nf][1] * i0);
        *(bf162*)&ob[(size_t)(r0 + 8) * DD + c] =
            __floats2bfloat162_rn(o[nf][2] * i1, o[nf][3] * i1);
    }
}

// ---------------------------------------------------------------------------
// LayerNorm: one WARP per row (8 rows/block).
// ---------------------------------------------------------------------------
__global__ __launch_bounds__(256)
void ln_kernel(const float* __restrict__ y, const float* __restrict__ gamma,
               const float* __restrict__ beta, float* __restrict__ out)
{
    GDWAIT();

    const int wid = threadIdx.x >> 5, lane = threadIdx.x & 31;
    const int row = blockIdx.x * 8 + wid;
    const float* yr = y + (size_t)row * DD;

    float4 v[8];
    float s = 0.0f, s2 = 0.0f;
#pragma unroll
    for (int i = 0; i < 8; i++) {
        v[i] = *(const float4*)&yr[lane * 4 + i * 128];
        s  += v[i].x + v[i].y + v[i].z + v[i].w;
        s2 += v[i].x * v[i].x + v[i].y * v[i].y + v[i].z * v[i].z + v[i].w * v[i].w;
    }
#pragma unroll
    for (int off = 16; off; off >>= 1) {
        s  += __shfl_xor_sync(0xffffffffu, s,  off);
        s2 += __shfl_xor_sync(0xffffffffu, s2, off);
    }

    const float mean = s * (1.0f / DD);
    const float var  = s2 * (1.0f / DD) - mean * mean;
    const float inv  = rsqrtf(var + 1e-5f);

#pragma unroll
    for (int i = 0; i < 8; i++) {
        const int c = lane * 4 + i * 128;
        float4 g  = *(const float4*)&gamma[c];
        float4 bt = *(const float4*)&beta[c];
        float4 r;
        r.x = (v[i].x - mean) * inv * g.x + bt.x;
        r.y = (v[i].y - mean) * inv * g.y + bt.y;
        r.z = (v[i].z - mean) * inv * g.z + bt.z;
        r.w = (v[i].w - mean) * inv * g.w + bt.w;
        *(float4*)&out[(size_t)row * DD + c] = r;
    }
}

// ---------------------------------------------------------------------------
extern "C" void kernel_launch(void* const* d_in, const int* in_sizes, int n_in,
                              void* d_out, int out_size)
{
    (void)in_sizes; (void)n_in; (void)out_size;
    const float* inp   = (const float*)d_in[0];
    const int*   mask  = (const int*)d_in[1];
    const float* Wqkv  = (const float*)d_in[2];
    const float* bqkv  = (const float*)d_in[3];
    const float* Wo    = (const float*)d_in[4];
    const float* gamma = (const float*)d_in[5];
    const float* beta  = (const float*)d_in[6];
    float* out = (float*)d_out;

    bf16 *inpb, *wqkvb, *wob, *qb, *kc, *vc, *attnb;
    float* y;
    int *idx, *cnt;
    cudaGetSymbolAddress((void**)&inpb,  g_inpb);
    cudaGetSymbolAddress((void**)&wqkvb, g_wqkvb);
    cudaGetSymbolAddress((void**)&wob,   g_wob);
    cudaGetSymbolAddress((void**)&qb,    g_qb);
    cudaGetSymbolAddress((void**)&kc,    g_kc);
    cudaGetSymbolAddress((void**)&vc,    g_vc);
    cudaGetSymbolAddress((void**)&attnb, g_attnb);
    cudaGetSymbolAddress((void**)&y,     g_y);
    cudaGetSymbolAddress((void**)&idx,   g_idx);
    cudaGetSymbolAddress((void**)&cnt,   g_cnt);

    cudaFuncSetAttribute(qkv_gemm,
                         cudaFuncAttributeMaxDynamicSharedMemorySize, GSMEM_BYTES);
    cudaFuncSetAttribute(hgemm_proj,
                         cudaFuncAttributeMaxDynamicSharedMemorySize, GSMEM_BYTES);
    cudaFuncSetAttribute(flash_bf16,
                         cudaFuncAttributeMaxDynamicSharedMemorySize, FSMEM_BYTES);

    // PDL launch attribute (dependent may start during predecessor's epilogue)
    cudaLaunchAttribute pdl[1];
    pdl[0].id = cudaLaunchAttributeProgrammaticStreamSerialization;
    pdl[0].val.programmaticStreamSerializationAllowed = 1;

    // 0) fused conversions + key compaction
    preproc<<<PRE_TOTAL, 256>>>(inp, Wqkv, Wo, mask, inpb, wqkvb, wob, idx, cnt);

    // 1) unified Q + gathered-KV GEMM
    {
        cudaLaunchConfig_t cfg = {};
        cfg.gridDim = dim3(768, 1, 1); cfg.blockDim = dim3(256, 1, 1);
        cfg.dynamicSmemBytes = GSMEM_BYTES; cfg.stream = 0;
        cfg.attrs = pdl; cfg.numAttrs = 1;
        cudaLaunchKernelEx(&cfg, qkv_gemm, inpb, wqkvb, bqkv,
                           (const int*)idx, (const int*)cnt, qb, kc, vc);
    }

    // 2) attention over ~cnt keys
    {
        cudaLaunchConfig_t cfg = {};
        cfg.gridDim = dim3(BB * HH, SS / 128, 1); cfg.blockDim = dim3(256, 1, 1);
        cfg.dynamicSmemBytes = FSMEM_BYTES; cfg.stream = 0;
        cfg.attrs = pdl; cfg.numAttrs = 1;
        cudaLaunchKernelEx(&cfg, flash_bf16, (const bf16*)qb, (const bf16*)kc,
                           (const bf16*)vc, (const int*)cnt, attnb);
    }

    // 3) y = inp + attn @ Wo^T
    {
        cudaLaunchConfig_t cfg = {};
        cfg.gridDim = dim3(DD / 256, MTOK / 128, 1); cfg.blockDim = dim3(256, 1, 1);
        cfg.dynamicSmemBytes = GSMEM_BYTES; cfg.stream = 0;
        cfg.attrs = pdl; cfg.numAttrs = 1;
        cudaLaunchKernelEx(&cfg, hgemm_proj, (const bf16*)attnb, (const bf16*)wob,
                           inp, y, MTOK, DD, DD);
    }

    // 4) out = LayerNorm(y)
    {
        cudaLaunchConfig_t cfg = {};
        cfg.gridDim = dim3(MTOK / 8, 1, 1); cfg.blockDim = dim3(256, 1, 1);
        cfg.dynamicSmemBytes = 0; cfg.stream = 0;
        cfg.attrs = pdl; cfg.numAttrs = 1;
        cudaLaunchKernelEx(&cfg, ln_kernel, (const float*)y, gamma, beta, out);
    }
}